// round 10
// baseline (speedup 1.0000x reference)
#include <cuda_runtime.h>
#include <cuda_bf16.h>
#include <math.h>
#include <stdint.h>

// ---------------- problem constants ----------------
#define NN   30000
#define EE   480000
#define DIN  768
#define DH   256    // HID
#define DOUT 128    // OUT
#define NHEAD 4
#define NCLS 3

// ---------------- scratch (static device memory; no allocations) ----------------
__device__ float    g_Wh   [(size_t)NN * (NHEAD * DH)];
__device__ float    g_s1   [NHEAD * NN];
__device__ float    g_s2   [NHEAD * NN];
__device__ float    g_w    [(size_t)NHEAD * EE];
__device__ float    g_w2e  [EE];
__device__ float    g_hbuf [(size_t)NN * 512];
__device__ float    g_evsum[NN * NCLS];
__device__ float    g_h1   [(size_t)NN * DH];     // agg GEMM out (pre-LN)
__device__ float    g_Wh2  [(size_t)NN * DOUT];
__device__ float    g_s1b  [NN];
__device__ float    g_s2b  [NN];
__device__ float    g_xnew2[(size_t)NN * DOUT];
__device__ float    g_x2   [(size_t)NN * DOUT];
__device__ unsigned g_maxenc[12];
__device__ float    g_M    [8];
__device__ double   g_sumexp[8];
__device__ float    g_invS  [8];

// CSR (edges grouped by tgt)
__device__ int g_rowptr[NN + 1];
__device__ int g_cursor[NN];
__device__ int g_eidx  [EE];

// pre-split bf16 A operands
__device__ __align__(256) __nv_bfloat16 g_xhi [(size_t)NN * DIN],  g_xlo [(size_t)NN * DIN];
__device__ __align__(256) __nv_bfloat16 g_xnhi[(size_t)NN * 1024], g_xnlo[(size_t)NN * 1024];
__device__ __align__(256) __nv_bfloat16 g_h1hi[(size_t)NN * DH],   g_h1lo[(size_t)NN * DH];

// transposed + bf16-split weights (Bt[n][k], K-major)
__device__ __align__(256) __nv_bfloat16 g_bt1hi [1024 * 768], g_bt1lo [1024 * 768];
__device__ __align__(256) __nv_bfloat16 g_btahi [256 * 1024], g_btalo [256 * 1024];
__device__ __align__(256) __nv_bfloat16 g_btehi [512 * 256],  g_btelo [512 * 256];
__device__ __align__(256) __nv_bfloat16 g_btw2hi[128 * 256],  g_btw2lo[128 * 256];
__device__ __align__(256) __nv_bfloat16 g_btrhi [128 * 256],  g_btrlo [128 * 256];

// ---------------- helpers ----------------
__device__ __forceinline__ unsigned fenc(float f) {
    unsigned u = __float_as_uint(f);
    return (u & 0x80000000u) ? ~u : (u | 0x80000000u);
}
__device__ __forceinline__ float fdec(unsigned u) {
    return (u & 0x80000000u) ? __uint_as_float(u & 0x7fffffffu) : __uint_as_float(~u);
}
__device__ __forceinline__ float wsumf(float v) {
#pragma unroll
    for (int o = 16; o > 0; o >>= 1) v += __shfl_xor_sync(0xffffffffu, v, o);
    return v;
}
__device__ __forceinline__ float softplusf(float x) {
    return fmaxf(x, 0.f) + log1pf(expf(-fabsf(x)));
}
__device__ __forceinline__ float eluf(float x) {
    return x > 0.f ? x : expm1f(x);
}
__device__ __forceinline__ void bf16split(float x, __nv_bfloat16& hi, __nv_bfloat16& lo) {
    hi = __float2bfloat16(x);
    lo = __float2bfloat16(x - __bfloat162float(hi));
}
__device__ __forceinline__ uint32_t smem_u32(const void* p) {
    uint32_t a;
    asm("{ .reg .u64 t; cvta.to.shared.u64 t, %1; cvt.u32.u64 %0, t; }" : "=r"(a) : "l"(p));
    return a;
}
__device__ __forceinline__ void cp16(uint32_t dst, const void* src, bool valid) {
    asm volatile("cp.async.cg.shared.global [%0], [%1], 16, %2;"
                 :: "r"(dst), "l"(src), "r"(valid ? 16u : 0u) : "memory");
}
__device__ __forceinline__ void cp_commit() {
    asm volatile("cp.async.commit_group;" ::: "memory");
}
__device__ __forceinline__ void cp_wait1() {
    asm volatile("cp.async.wait_group 1;" ::: "memory");
}

// mma.sync m16n8k16 bf16 (row.col), fp32 accumulate — compiles on plain sm_103.
__device__ __forceinline__ void mma_bf16(float* c, const uint32_t* a, const uint32_t* b) {
    asm volatile(
        "mma.sync.aligned.m16n8k16.row.col.f32.bf16.bf16.f32 "
        "{%0,%1,%2,%3}, {%4,%5,%6,%7}, {%8,%9}, {%0,%1,%2,%3};"
        : "+f"(c[0]), "+f"(c[1]), "+f"(c[2]), "+f"(c[3])
        : "r"(a[0]), "r"(a[1]), "r"(a[2]), "r"(a[3]), "r"(b[0]), "r"(b[1]));
}

// ---------------- init ----------------
__global__ void k_init() {
    int i = blockIdx.x * blockDim.x + threadIdx.x;
    int stride = gridDim.x * blockDim.x;
    for (int j = i; j <= NN; j += stride) g_rowptr[j] = 0;
    if (i < 12) g_maxenc[i] = 0u;
    if (i < 8)  { g_sumexp[i] = 0.0; g_invS[i] = 0.f; g_M[i] = 0.f; }
}

// ---------------- CSR build ----------------
__global__ void k_hist(const int* __restrict__ tgt) {
    int e = blockIdx.x * blockDim.x + threadIdx.x;
    if (e < EE) atomicAdd(&g_rowptr[tgt[e] + 1], 1);
}

__global__ void k_scan() {
    __shared__ int part[1024];
    int tid = threadIdx.x;
    const int CH = (NN + 1023) / 1024;
    int beg = tid * CH;
    int end = beg + CH; if (end > NN) end = NN;
    int s = 0;
    for (int i = beg; i < end; i++) s += g_rowptr[i + 1];
    part[tid] = s;
    __syncthreads();
    for (int off = 1; off < 1024; off <<= 1) {
        int v = (tid >= off) ? part[tid - off] : 0;
        __syncthreads();
        part[tid] += v;
        __syncthreads();
    }
    int run = (tid > 0) ? part[tid - 1] : 0;
    for (int i = beg; i < end; i++) {
        int c = g_rowptr[i + 1];
        g_cursor[i] = run;
        run += c;
        g_rowptr[i + 1] = run;
    }
    if (tid == 0) g_rowptr[0] = 0;
}

__global__ void k_fill(const int* __restrict__ tgt) {
    int e = blockIdx.x * blockDim.x + threadIdx.x;
    if (e < EE) {
        int p = atomicAdd(&g_cursor[tgt[e]], 1);
        g_eidx[p] = e;
    }
}

// ---------------- A split: fp32 -> bf16 hi/lo ----------------
__global__ void k_split(const float* __restrict__ src, __nv_bfloat16* __restrict__ hi,
                        __nv_bfloat16* __restrict__ lo, int n4)
{
    int i = blockIdx.x * blockDim.x + threadIdx.x;
    if (i >= n4) return;
    float4 v = ((const float4*)src)[i];
    __nv_bfloat16 hx, lx, hy, ly, hz, lz, hw, lw;
    bf16split(v.x, hx, lx); bf16split(v.y, hy, ly);
    bf16split(v.z, hz, lz); bf16split(v.w, hw, lw);
    ((__nv_bfloat162*)hi)[2 * i]     = __nv_bfloat162(hx, hy);
    ((__nv_bfloat162*)hi)[2 * i + 1] = __nv_bfloat162(hz, hw);
    ((__nv_bfloat162*)lo)[2 * i]     = __nv_bfloat162(lx, ly);
    ((__nv_bfloat162*)lo)[2 * i + 1] = __nv_bfloat162(lz, lw);
}

// ---------------- B transpose + bf16 split ----------------
__global__ void k_bt(const float* __restrict__ src, __nv_bfloat16* __restrict__ bthi,
                     __nv_bfloat16* __restrict__ btlo, int K, int nTotal, int headN, int headStride)
{
    int idx = blockIdx.x * blockDim.x + threadIdx.x;
    if (idx >= nTotal * K) return;
    int n = idx / K, k = idx - n * K;
    int head = n / headN, nloc = n - head * headN;
    float v = src[(size_t)head * headStride + (size_t)k * headN + nloc];
    __nv_bfloat16 hi, lo;
    bf16split(v, hi, lo);
    bthi[idx] = hi;
    btlo[idx] = lo;
}

// ---------------- bf16-split tensor-core GEMM, cp.async 3-stage ----------------
// C[M, 128*gx] = A @ Bt^T ; A pre-split bf16 hi/lo [M,lda]; Bt pre-split bf16 [N,K] K-major.
// EPI: 0 = (+bias); 1 = relu(+bias); 2 = +bias +addend.
#define ASTR 40
#define TILE_B (128 * ASTR * 2)      // 10240 B
#define BUF_B  (4 * TILE_B)          // 40960 B (Ahi/Alo/Bhi/Blo)
#define NSTAGE 3
#define MMA_SMEM (NSTAGE * BUF_B)    // 122880 B

template <int EPI>
__global__ __launch_bounds__(256, 1)
void k_mma(const __nv_bfloat16* __restrict__ Ahi, const __nv_bfloat16* __restrict__ Alo,
           int lda, int aHeadStep, int headN,
           const __nv_bfloat16* __restrict__ Bthi, const __nv_bfloat16* __restrict__ Btlo,
           float* __restrict__ C, int ldc,
           const float* __restrict__ bias,
           const float* __restrict__ addend, int ldadd,
           int M, int K)
{
    extern __shared__ __align__(16) char smraw[];
    const uint32_t sbase = smem_u32(smraw);

    const int tid = threadIdx.x;
    const int lane = tid & 31;
    const int wid = tid >> 5;
    const int warp_m = wid & 1;
    const int warp_n = wid >> 1;
    const int g  = lane >> 2;
    const int tg = lane & 3;

    const int m0 = blockIdx.y * 128;
    const int n0 = blockIdx.x * 128;
    const size_t aOff = (size_t)(n0 / headN) * aHeadStep;

    // per-thread load coords: 2 chunk-ids x 4 buffers, 16B each
    const int row0 = tid >> 2,          ch0 = tid & 3;          // rows 0..63
    const int row1 = (tid + 256) >> 2,  ch1 = tid & 3;          // rows 64..127
    const bool vm0 = (m0 + row0) < M;
    const bool vm1 = (m0 + row1) < M;
    const int gm0 = vm0 ? (m0 + row0) : 0;
    const int gm1 = vm1 ? (m0 + row1) : 0;

    const char* pAh0 = (const char*)&Ahi[aOff + (size_t)gm0 * lda] + ch0 * 16;
    const char* pAl0 = (const char*)&Alo[aOff + (size_t)gm0 * lda] + ch0 * 16;
    const char* pAh1 = (const char*)&Ahi[aOff + (size_t)gm1 * lda] + ch1 * 16;
    const char* pAl1 = (const char*)&Alo[aOff + (size_t)gm1 * lda] + ch1 * 16;
    const char* pBh0 = (const char*)&Bthi[(size_t)(n0 + row0) * K] + ch0 * 16;
    const char* pBl0 = (const char*)&Btlo[(size_t)(n0 + row0) * K] + ch0 * 16;
    const char* pBh1 = (const char*)&Bthi[(size_t)(n0 + row1) * K] + ch1 * 16;
    const char* pBl1 = (const char*)&Btlo[(size_t)(n0 + row1) * K] + ch1 * 16;
    const uint32_t so0 = row0 * (ASTR * 2) + ch0 * 16;
    const uint32_t so1 = row1 * (ASTR * 2) + ch1 * 16;

    auto issue = [&](int t, int s) {
        size_t go = (size_t)t * 64;   // 32 bf16 = 64 B per K-tile
        uint32_t sb = sbase + s * BUF_B;
        cp16(sb + so0,              pAh0 + go, vm0);
        cp16(sb + TILE_B + so0,     pAl0 + go, vm0);
        cp16(sb + 2 * TILE_B + so0, pBh0 + go, true);
        cp16(sb + 3 * TILE_B + so0, pBl0 + go, true);
        cp16(sb + so1,              pAh1 + go, vm1);
        cp16(sb + TILE_B + so1,     pAl1 + go, vm1);
        cp16(sb + 2 * TILE_B + so1, pBh1 + go, true);
        cp16(sb + 3 * TILE_B + so1, pBl1 + go, true);
        cp_commit();
    };

    float acc[4][4][4];
#pragma unroll
    for (int i = 0; i < 4; i++)
#pragma unroll
        for (int j = 0; j < 4; j++)
#pragma unroll
            for (int k = 0; k < 4; k++) acc[i][j][k] = 0.f;

    auto compute = [&](int s) {
        const __nv_bfloat16* sAhi = (const __nv_bfloat16*)(smraw + s * BUF_B);
        const __nv_bfloat16* sAlo = (const __nv_bfloat16*)(smraw + s * BUF_B + TILE_B);
        const __nv_bfloat16* sBhi = (const __nv_bfloat16*)(smraw + s * BUF_B + 2 * TILE_B);
        const __nv_bfloat16* sBlo = (const __nv_bfloat16*)(smraw + s * BUF_B + 3 * TILE_B);
#pragma unroll
        for (int kc = 0; kc < 32; kc += 16) {
            uint32_t ah[4][4], al[4][4];
#pragma unroll
            for (int mt = 0; mt < 4; mt++) {
                int base = (warp_m * 64 + mt * 16 + g) * ASTR + kc + tg * 2;
                ah[mt][0] = *(const uint32_t*)&sAhi[base];
                ah[mt][1] = *(const uint32_t*)&sAhi[base + 8 * ASTR];
                ah[mt][2] = *(const uint32_t*)&sAhi[base + 8];
                ah[mt][3] = *(const uint32_t*)&sAhi[base + 8 * ASTR + 8];
                al[mt][0] = *(const uint32_t*)&sAlo[base];
                al[mt][1] = *(const uint32_t*)&sAlo[base + 8 * ASTR];
                al[mt][2] = *(const uint32_t*)&sAlo[base + 8];
                al[mt][3] = *(const uint32_t*)&sAlo[base + 8 * ASTR + 8];
            }
            uint32_t bh[4][2], bl[4][2];
#pragma unroll
            for (int nt = 0; nt < 4; nt++) {
                int base = (warp_n * 32 + nt * 8 + g) * ASTR + kc + tg * 2;
                bh[nt][0] = *(const uint32_t*)&sBhi[base];
                bh[nt][1] = *(const uint32_t*)&sBhi[base + 8];
                bl[nt][0] = *(const uint32_t*)&sBlo[base];
                bl[nt][1] = *(const uint32_t*)&sBlo[base + 8];
            }
#pragma unroll
            for (int mt = 0; mt < 4; mt++)
#pragma unroll
                for (int nt = 0; nt < 4; nt++) {
                    mma_bf16(acc[mt][nt], ah[mt], bh[nt]);
                    mma_bf16(acc[mt][nt], ah[mt], bl[nt]);
                    mma_bf16(acc[mt][nt], al[mt], bh[nt]);
                }
        }
    };

    const int T = K / 32;   // all K here are >= 256 -> T >= 8
    issue(0, 0);
    issue(1, 1);
    for (int t = 0; t < T; t++) {
        cp_wait1();
        __syncthreads();
        if (t + 2 < T) issue(t + 2, (t + 2) % NSTAGE);
        compute(t % NSTAGE);
    }

    // epilogue
#pragma unroll
    for (int mt = 0; mt < 4; mt++) {
        int r0 = m0 + warp_m * 64 + mt * 16 + g;
#pragma unroll
        for (int nt = 0; nt < 4; nt++) {
            int gc = n0 + warp_n * 32 + nt * 8 + tg * 2;
            float2 v01 = make_float2(acc[mt][nt][0], acc[mt][nt][1]);
            float2 v23 = make_float2(acc[mt][nt][2], acc[mt][nt][3]);
            if (bias) {
                float2 b = *(const float2*)&bias[gc];
                v01.x += b.x; v01.y += b.y;
                v23.x += b.x; v23.y += b.y;
            }
            if (EPI == 1) {
                v01.x = fmaxf(v01.x, 0.f); v01.y = fmaxf(v01.y, 0.f);
                v23.x = fmaxf(v23.x, 0.f); v23.y = fmaxf(v23.y, 0.f);
            }
            if (r0 < M) {
                if (EPI == 2) {
                    float2 adx = *(const float2*)&addend[(size_t)r0 * ldadd + gc];
                    v01.x += adx.x; v01.y += adx.y;
                }
                *(float2*)&C[(size_t)r0 * ldc + gc] = v01;
            }
            if (r0 + 8 < M) {
                if (EPI == 2) {
                    float2 adx = *(const float2*)&addend[(size_t)(r0 + 8) * ldadd + gc];
                    v23.x += adx.x; v23.y += adx.y;
                }
                *(float2*)&C[(size_t)(r0 + 8) * ldc + gc] = v23;
            }
        }
    }
}

// ---------------- fp32 SGEMM (small evidence-2 GEMM only) ----------------
#define BM 128
#define BN 128
#define BKK 16
template <int EPI>
__global__ __launch_bounds__(256, 2)
void k_sgemm(const float* __restrict__ A, int lda,
             const float* __restrict__ B, int ldb,
             float* __restrict__ C, int ldc,
             const float* __restrict__ bias,
             int M, int N, int K)
{
    __shared__ float As[BKK][BM + 4];
    __shared__ float Bs[BKK][BN];
    const int tid = threadIdx.x;
    const int m0 = blockIdx.y * BM;
    const int n0 = blockIdx.x * BN;
    const int tm = tid >> 4, tn = tid & 15;
    const int a_kk = tid & 15, a_m0 = tid >> 4;
    const int b_kk0 = tid >> 5, b_nb = (tid & 31) << 2;

    float acc[8][8];
#pragma unroll
    for (int i = 0; i < 8; i++)
#pragma unroll
        for (int j = 0; j < 8; j++) acc[i][j] = 0.f;

    float ra[8]; float4 rb[2];
    auto load_tiles = [&](int k0) {
#pragma unroll
        for (int i = 0; i < 8; i++) {
            int gm = m0 + a_m0 + 16 * i;
            ra[i] = (gm < M) ? A[(size_t)gm * lda + (k0 + a_kk)] : 0.f;
        }
#pragma unroll
        for (int i = 0; i < 2; i++) {
            int kk = b_kk0 + 8 * i;
            int gn = n0 + b_nb;
            float4 v = make_float4(0.f, 0.f, 0.f, 0.f);
            const float* bp = &B[(size_t)(k0 + kk) * ldb + b_nb];
            if (gn + 3 < N) v = *(const float4*)bp;
            else {
                if (gn     < N) v.x = bp[0];
                if (gn + 1 < N) v.y = bp[1];
                if (gn + 2 < N) v.z = bp[2];
            }
            rb[i] = v;
        }
    };
    auto store_tiles = [&]() {
#pragma unroll
        for (int i = 0; i < 8; i++) As[a_kk][a_m0 + 16 * i] = ra[i];
#pragma unroll
        for (int i = 0; i < 2; i++) *(float4*)&Bs[b_kk0 + 8 * i][b_nb] = rb[i];
    };
    auto compute = [&]() {
#pragma unroll
        for (int kk = 0; kk < BKK; kk++) {
            float a[8], b[8];
#pragma unroll
            for (int i = 0; i < 8; i++) a[i] = As[kk][tm * 8 + i];
#pragma unroll
            for (int j = 0; j < 8; j++) b[j] = Bs[kk][tn * 8 + j];
#pragma unroll
            for (int i = 0; i < 8; i++)
#pragma unroll
                for (int j = 0; j < 8; j++) acc[i][j] = fmaf(a[i], b[j], acc[i][j]);
        }
    };
    load_tiles(0); store_tiles(); __syncthreads();
    for (int k0 = BKK; k0 < K; k0 += BKK) {
        load_tiles(k0); compute(); __syncthreads(); store_tiles(); __syncthreads();
    }
    compute();
#pragma unroll
    for (int i = 0; i < 8; i++) {
        int gm = m0 + tm * 8 + i;
        if (gm < M) {
#pragma unroll
            for (int j = 0; j < 8; j++) {
                int gn = n0 + tn * 8 + j;
                if (gn < N) {
                    float v = acc[i][j];
                    if (bias) v += bias[gn];
                    if (EPI == 1) v = fmaxf(v, 0.f);
                    C[(size_t)gm * ldc + gn] = v;
                }
            }
        }
    }
}

// ---------------- attention projections + node maxima ----------------
__global__ void k_s1s2(const float* __restrict__ Wh, int ld, int F, int nh,
                       const float* __restrict__ a, int aStride,
                       float* __restrict__ s1, float* __restrict__ s2, int N,
                       int slot1, int slot2)
{
    int gw = (blockIdx.x * blockDim.x + threadIdx.x) >> 5;
    int lane = threadIdx.x & 31;
    if (gw >= N * nh) return;
    int node = gw / nh;
    int h = gw - node * nh;
    const float* wr = &Wh[(size_t)node * ld + h * F];
    const float* ah = &a[(size_t)h * aStride];
    float p1 = 0.f, p2 = 0.f;
    for (int j = lane; j < F; j += 32) {
        float x = wr[j];
        p1 = fmaf(x, ah[j], p1);
        p2 = fmaf(x, ah[F + j], p2);
    }
    p1 = wsumf(p1); p2 = wsumf(p2);
    if (lane == 0) {
        s1[(size_t)h * N + node] = p1;
        s2[(size_t)h * N + node] = p2;
        atomicMax(&g_maxenc[slot1 + h], fenc(p1));
        atomicMax(&g_maxenc[slot2 + h], fenc(p2));
    }
}

__global__ void k_prepM(int slot, int slot1, int slot2, int n)
{
    int i = threadIdx.x;
    if (i < n) {
        float l = fdec(g_maxenc[slot1 + i]) + fdec(g_maxenc[slot2 + i]);
        g_M[slot + i] = (l > 0.f) ? l : 0.2f * l;
    }
}

template <int NH>
__global__ void k_expsum(const int* __restrict__ src, const int* __restrict__ tgt,
                         const float* __restrict__ s1, const float* __restrict__ s2,
                         float* __restrict__ w, int E, int N, int slot)
{
    int e = blockIdx.x * blockDim.x + threadIdx.x;
    bool ok = (e < E);
    int s = 0, t = 0;
    if (ok) { s = src[e]; t = tgt[e]; }
    float sv[NH];
#pragma unroll
    for (int h = 0; h < NH; h++) {
        float v = 0.f;
        if (ok) {
            float l = s1[(size_t)h * N + s] + s2[(size_t)h * N + t];
            l = (l > 0.f) ? l : 0.2f * l;
            v = expf(l - g_M[slot + h]);
            w[(size_t)h * E + e] = v;
        }
        sv[h] = v;
    }
    __shared__ float red[256];
#pragma unroll
    for (int h = 0; h < NH; h++) {
        red[threadIdx.x] = sv[h];
        __syncthreads();
        for (int sft = 128; sft > 0; sft >>= 1) {
            if (threadIdx.x < sft) red[threadIdx.x] += red[threadIdx.x + sft];
            __syncthreads();
        }
        if (threadIdx.x == 0) atomicAdd(&g_sumexp[slot + h], (double)red[0]);
        __syncthreads();
    }
}

__global__ void k_finalize(int slot0, int n)
{
    int i = threadIdx.x;
    if (i < n) g_invS[slot0 + i] = (float)(1.0 / g_sumexp[slot0 + i]);
}

// ---------------- CSR gather (layer 1, F=1024): emit bf16-split xnew ----------------
__global__ __launch_bounds__(256, 8)
void k_gather1024(const int* __restrict__ src, const float* __restrict__ w,
                  const float* __restrict__ Wh,
                  __nv_bfloat16* __restrict__ xhi, __nv_bfloat16* __restrict__ xlo, int slot0)
{
    int node = blockIdx.x;
    int tid = threadIdx.x;
    int head = tid >> 6;
    int col = tid * 4;
    const float* wh = &w[(size_t)head * EE];

    int p = g_rowptr[node];
    const int end = g_rowptr[node + 1];

    int s_cur = 0; float c_cur = 0.f;
    if (p < end) { int e = g_eidx[p]; s_cur = src[e]; c_cur = wh[e]; }

    float4 acc = make_float4(0.f, 0.f, 0.f, 0.f);
    while (p < end) {
        int s_nxt = 0; float c_nxt = 0.f;
        if (p + 1 < end) { int e = g_eidx[p + 1]; s_nxt = src[e]; c_nxt = wh[e]; }
        float4 v = *(const float4*)&Wh[(size_t)s_cur * 1024 + col];
        acc.x = fmaf(c_cur, v.x, acc.x);
        acc.y = fmaf(c_cur, v.y, acc.y);
        acc.z = fmaf(c_cur, v.z, acc.z);
        acc.w = fmaf(c_cur, v.w, acc.w);
        s_cur = s_nxt; c_cur = c_nxt; p++;
    }
    float inv = g_invS[slot0 + head];
    acc.x *= inv; acc.y *= inv; acc.z *= inv; acc.w *= inv;
    __nv_bfloat16 hx, lx, hy, ly, hz, lz, hw, lw;
    bf16split(acc.x, hx, lx); bf16split(acc.y, hy, ly);
    bf16split(acc.z, hz, lz); bf16split(acc.w, hw, lw);
    size_t o = (size_t)node * 1024 + col;
    *(__nv_bfloat162*)&xhi[o]     = __nv_bfloat162(hx, hy);
    *(__nv_bfloat162*)&xhi[o + 2] = __nv_bfloat162(hz, hw);
    *(__nv_bfloat162*)&xlo[o]     = __nv_bfloat162(lx, ly);
    *(__nv_bfloat162*)&xlo[o + 2] = __nv_bfloat162(lz, lw);
}

// F=128 (layer 2): one warp per node, fp32 out.
__global__ __launch_bounds__(256, 8)
void k_gather128(const int* __restrict__ src, const float* __restrict__ w,
                 const float* __restrict__ Wh, float* __restrict__ xnew, int slot)
{
    int node = (blockIdx.x * blockDim.x + threadIdx.x) >> 5;
    int lane = threadIdx.x & 31;
    if (node >= NN) return;
    int col = lane * 4;

    int p = g_rowptr[node];
    const int end = g_rowptr[node + 1];

    int s_cur = 0; float c_cur = 0.f;
    if (p < end) { int e = g_eidx[p]; s_cur = src[e]; c_cur = w[e]; }

    float4 acc = make_float4(0.f, 0.f, 0.f, 0.f);
    while (p < end) {
        int s_nxt = 0; float c_nxt = 0.f;
        if (p + 1 < end) { int e = g_eidx[p + 1]; s_nxt = src[e]; c_nxt = w[e]; }
        float4 v = *(const float4*)&Wh[(size_t)s_cur * 128 + col];
        acc.x = fmaf(c_cur, v.x, acc.x);
        acc.y = fmaf(c_cur, v.y, acc.y);
        acc.z = fmaf(c_cur, v.z, acc.z);
        acc.w = fmaf(c_cur, v.w, acc.w);
        s_cur = s_nxt; c_cur = c_nxt; p++;
    }
    float inv = g_invS[slot];
    acc.x *= inv; acc.y *= inv; acc.z *= inv; acc.w *= inv;
    *(float4*)&xnew[(size_t)node * 128 + col] = acc;
}

// ---------------- evidence heads ----------------
__global__ void k_evid1(const float* __restrict__ hbuf, const float* __restrict__ w2,
                        const float* __restrict__ b2, float* __restrict__ evsum, int N)
{
    int gw = (blockIdx.x * blockDim.x + threadIdx.x) >> 5;
    int lane = threadIdx.x & 31;
    if (gw >= N) return;
    float e0 = 0.f, e1 = 0.f, e2 = 0.f;
#pragma unroll
    for (int h = 0; h < NHEAD; h++) {
        float4 v = *(const float4*)&hbuf[(size_t)gw * 512 + h * 128 + lane * 4];
        const float* wc = &w2[h * 384 + lane * 12];
        float a0 = v.x * wc[0] + v.y * wc[3] + v.z * wc[6] + v.w * wc[9];
        float a1 = v.x * wc[1] + v.y * wc[4] + v.z * wc[7] + v.w * wc[10];
        float a2 = v.x * wc[2] + v.y * wc[5] + v.z * wc[8] + v.w * wc[11];
        a0 = wsumf(a0); a1 = wsumf(a1); a2 = wsumf(a2);
        e0 += softplusf(a0 + b2[h * 3 + 0]) + 1.f;
        e1 += softplusf(a1 + b2[h * 3 + 1]) + 1.f;
        e2 += softplusf(a2 + b2[h * 3 + 2]) + 1.f;
    }
    if (lane == 0) {
        evsum[gw * 3 + 0] = e0; evsum[gw * 3 + 1] = e1; evsum[gw * 3 + 2] = e2;
    }
}

__global__ void k_evid2(const float* __restrict__ hbuf, const float* __restrict__ w2,
                        const float* __restrict__ b2, const float* __restrict__ evsum,
                        float* __restrict__ out, int N)
{
    int gw = (blockIdx.x * blockDim.x + threadIdx.x) >> 5;
    int lane = threadIdx.x & 31;
    if (gw >= N) return;
    float2 v = *(const float2*)&hbuf[(size_t)gw * 64 + lane * 2];
    const float* wc = &w2[lane * 6];
    float a0 = v.x * wc[0] + v.y * wc[3];
    float a1 = v.x * wc[1] + v.y * wc[4];
    float a2 = v.x * wc[2] + v.y * wc[5];
    a0 = wsumf(a0); a1 = wsumf(a1); a2 = wsumf(a2);
    if (lane == 0) {
        float e0 = softplusf(a0 + b2[0]) + 1.f;
        float e1 = softplusf(a1 + b2[1]) + 1.f;
        float e2 = softplusf(a2 + b2[2]) + 1.f;
        out[(size_t)gw * 3 + 0] = (evsum[gw * 3 + 0] * 0.25f + e0) * 0.5f;
        out[(size_t)gw * 3 + 1] = (evsum[gw * 3 + 1] * 0.25f + e1) * 0.5f;
        out[(size_t)gw * 3 + 2] = (evsum[gw * 3 + 2] * 0.25f + e2) * 0.5f;
    }
}

// ---------------- LayerNorm + ELU ----------------
// SPLIT=true: write bf16 hi/lo only (for h1). SPLIT=false: write fp32 out.
template <int F, bool SPLIT>
__global__ void k_ln_elu(const float* __restrict__ in, float* __restrict__ out,
                         __nv_bfloat16* __restrict__ ohi, __nv_bfloat16* __restrict__ olo,
                         const float* __restrict__ gam, const float* __restrict__ bet, int N)
{
    int gw = (blockIdx.x * blockDim.x + threadIdx.x) >> 5;
    int lane = threadIdx.x & 31;
    if (gw >= N) return;
    constexpr int R = F / 32;
    float v[R];
    const float* ir = &in[(size_t)gw * F];
#pragma unroll
    for (int r = 0; r < R; r++) v[r] = ir[lane + 32 * r];
    float s = 0.f;
#pragma unroll
    for (int r = 0; r < R; r++) s += v[r];
    s = wsumf(s);
    float mean = s * (1.f / F);
    float q = 0.f;
#pragma unroll
    for (int r = 0; r < R; r++) { float d = v[r] - mean; q = fmaf(d, d, q); }
    q = wsumf(q);
    float rstd = rsqrtf(q * (1.f / F) + 1e-5f);
#pragma unroll
    for (int r = 0; r < R; r++) {
        int j = lane + 32 * r;
        float y = (v[r] - mean) * rstd * gam[j] + bet[j];
        y = eluf(y);
        if (SPLIT) {
            __nv_bfloat16 hi, lo;
            bf16split(y, hi, lo);
            ohi[(size_t)gw * F + j] = hi;
            olo[(size_t)gw * F + j] = lo;
        } else {
            out[(size_t)gw * F + j] = y;
        }
    }
}

// ---------------- launch ----------------
extern "C" void kernel_launch(void* const* d_in, const int* in_sizes, int n_in,
                              void* d_out, int out_size)
{
    (void)in_sizes; (void)n_in; (void)out_size;

    const float* x        = (const float*)d_in[0];
    const int*   ei       = (const int*)  d_in[1];
    const float* W_heads  = (const float*)d_in[2];
    const float* a_heads  = (const float*)d_in[3];
    const float* ev1w_h   = (const float*)d_in[4];
    const float* ev1b_h   = (const float*)d_in[5];
    const float* ev2w_h   = (const float*)d_in[6];
    const float* ev2b_h   = (const float*)d_in[7];
    const float* agg_w    = (const float*)d_in[8];
    const float* agg_b    = (const float*)d_in[9];
    const float* ln1_g    = (const float*)d_in[10];
    const float* ln1_b    = (const float*)d_in[11];
    const float* W2       = (const float*)d_in[12];
    const float* a2       = (const float*)d_in[13];
    const float* ev1w2    = (const float*)d_in[14];
    const float* ev1b2    = (const float*)d_in[15];
    const float* ev2w2    = (const float*)d_in[16];
    const float* ev2b2    = (const float*)d_in[17];
    const float* ln2_g    = (const float*)d_in[18];
    const float* ln2_b    = (const float*)d_in[19];
    const float* res_w    = (const float*)d_in[20];
    const float* res_b    = (const float*)d_in[21];

    const int* src = ei;
    const int* tgt = ei + EE;

    float* out_x  = (float*)d_out;
    float* out_ev = (float*)d_out + (size_t)NN * DOUT;

    float *Wh, *s1, *s2, *wbuf, *w2e, *hbuf, *evsum, *h1, *Wh2, *s1b, *s2b, *xnew2, *x2;
    __nv_bfloat16 *xhi, *xlo, *xnhi, *xnlo, *h1hi, *h1lo;
    __nv_bfloat16 *bt1hi, *bt1lo, *btahi, *btalo, *btehi, *btelo, *btw2hi, *btw2lo, *btrhi, *btrlo;
    cudaGetSymbolAddress((void**)&Wh,    g_Wh);
    cudaGetSymbolAddress((void**)&s1,    g_s1);
    cudaGetSymbolAddress((void**)&s2,    g_s2);
    cudaGetSymbolAddress((void**)&wbuf,  g_w);
    cudaGetSymbolAddress((void**)&w2e,   g_w2e);
    cudaGetSymbolAddress((void**)&hbuf,  g_hbuf);
    cudaGetSymbolAddress((void**)&evsum, g_evsum);
    cudaGetSymbolAddress((void**)&h1,    g_h1);
    cudaGetSymbolAddress((void**)&Wh2,   g_Wh2);
    cudaGetSymbolAddress((void**)&s1b,   g_s1b);
    cudaGetSymbolAddress((void**)&s2b,   g_s2b);
    cudaGetSymbolAddress((void**)&xnew2, g_xnew2);
    cudaGetSymbolAddress((void**)&x2,    g_x2);
    cudaGetSymbolAddress((void**)&xhi,   g_xhi);
    cudaGetSymbolAddress((void**)&xlo,   g_xlo);
    cudaGetSymbolAddress((void**)&xnhi,  g_xnhi);
    cudaGetSymbolAddress((void**)&xnlo,  g_xnlo);
    cudaGetSymbolAddress((void**)&h1hi,  g_h1hi);
    cudaGetSymbolAddress((void**)&h1lo,  g_h1lo);
    cudaGetSymbolAddress((void**)&bt1hi, g_bt1hi);
    cudaGetSymbolAddress((void**)&bt1lo, g_bt1lo);
    cudaGetSymbolAddress((void**)&btahi, g_btahi);
    cudaGetSymbolAddress((void**)&btalo, g_btalo);
    cudaGetSymbolAddress((void**)&btehi, g_btehi);
    cudaGetSymbolAddress((void**)&btelo, g_btelo);
    cudaGetSymbolAddress((void**)&btw2hi, g_btw2hi);
    cudaGetSymbolAddress((void**)&btw2lo, g_btw2lo);
    cudaGetSymbolAddress((void**)&btrhi, g_btrhi);
    cudaGetSymbolAddress((void**)&btrlo, g_btrlo);

    cudaFuncSetAttribute(k_mma<0>, cudaFuncAttributeMaxDynamicSharedMemorySize, MMA_SMEM);
    cudaFuncSetAttribute(k_mma<1>, cudaFuncAttributeMaxDynamicSharedMemorySize, MMA_SMEM);
    cudaFuncSetAttribute(k_mma<2>, cudaFuncAttributeMaxDynamicSharedMemorySize, MMA_SMEM);

    const int MB = (NN + 127) / 128;   // 235

    // 0) init; weight transposes; A split; CSR build
    k_init<<<128, 256>>>();
    k_bt<<<(1024 * 768 + 255) / 256, 256>>>(W_heads, bt1hi, bt1lo, 768, 1024, 256, 768 * 256);
    k_bt<<<(256 * 1024 + 255) / 256, 256>>>(agg_w,  btahi, btalo, 1024, 256, 256, 0);
    k_bt<<<(512 * 256 + 255) / 256, 256>>>(ev1w_h, btehi, btelo, 256, 512, 128, 256 * 128);
    k_bt<<<(128 * 256 + 255) / 256, 256>>>(W2,     btw2hi, btw2lo, 256, 128, 128, 0);
    k_bt<<<(128 * 256 + 255) / 256, 256>>>(res_w,  btrhi, btrlo, 256, 128, 128, 0);
    k_split<<<(NN * DIN / 4 + 255) / 256, 256>>>(x, xhi, xlo, NN * DIN / 4);
    k_hist<<<(EE + 255) / 256, 256>>>(tgt);
    k_scan<<<1, 1024>>>();
    k_fill<<<(EE + 255) / 256, 256>>>(tgt);

    // 1) Wh = x @ W_heads
    k_mma<0><<<dim3(8, MB), 256, MMA_SMEM>>>(xhi, xlo, DIN, 0, 128, bt1hi, bt1lo,
                                             Wh, 1024, nullptr, nullptr, 0, NN, DIN);

    // 2) attention scalars + maxima, edge pass, softmax scale
    k_s1s2<<<(NN * NHEAD) / 8, 256>>>(Wh, NHEAD * DH, DH, NHEAD, a_heads, 2 * DH, s1, s2, NN, 0, 4);
    k_prepM<<<1, 8>>>(0, 0, 4, NHEAD);
    k_expsum<NHEAD><<<(EE + 255) / 256, 256>>>(src, tgt, s1, s2, wbuf, EE, NN, 0);
    k_finalize<<<1, 8>>>(0, NHEAD);

    // 3) CSR gather -> split xnew
    k_gather1024<<<NN, 256>>>(src, wbuf, Wh, xnhi, xnlo, 0);

    // 4) evidence layer 1 (block-diagonal, relu) + fused head
    k_mma<1><<<dim3(4, MB), 256, MMA_SMEM>>>(xnhi, xnlo, 1024, DH, 128, btehi, btelo,
                                             hbuf, 512, ev1b_h, nullptr, 0, NN, DH);
    k_evid1<<<NN / 8, 256>>>(hbuf, ev2w_h, ev2b_h, evsum, NN);

    // 5) h1 = elu(LN(x_cat @ agg_w + agg_b))  -> split h1
    k_mma<0><<<dim3(2, MB), 256, MMA_SMEM>>>(xnhi, xnlo, 1024, 0, 128, btahi, btalo,
                                             h1, DH, agg_b, nullptr, 0, NN, 1024);
    k_ln_elu<DH, true><<<NN / 8, 256>>>(h1, nullptr, h1hi, h1lo, ln1_g, ln1_b, NN);

    // 6) layer-2 GAT
    k_mma<0><<<dim3(1, MB), 256, MMA_SMEM>>>(h1hi, h1lo, DH, 0, 128, btw2hi, btw2lo,
                                             Wh2, DOUT, nullptr, nullptr, 0, NN, DH);
    k_s1s2<<<NN / 8, 256>>>(Wh2, DOUT, DOUT, 1, a2, 2 * DOUT, s1b, s2b, NN, 8, 9);
    k_prepM<<<1, 8>>>(4, 8, 9, 1);
    k_expsum<1><<<(EE + 255) / 256, 256>>>(src, tgt, s1b, s2b, w2e, EE, NN, 4);
    k_finalize<<<1, 8>>>(4, 1);
    k_gather128<<<(NN * 32 + 255) / 256, 256>>>(src, w2e, Wh2, xnew2, 4);

    // 7) evidence layer 2 + final combine
    k_sgemm<1><<<dim3(1, MB), 256>>>(xnew2, DOUT, ev1w2, DOUT / 2, hbuf, DOUT / 2,
                                     ev1b2, NN, DOUT / 2, DOUT);
    k_evid2<<<NN / 8, 256>>>(hbuf, ev2w2, ev2b2, evsum, out_ev, NN);

    // 8) x2 = elu(LN(x_new2)); x_out = x2 + h1 @ res_w + res_b
    k_ln_elu<DOUT, false><<<NN / 8, 256>>>(xnew2, x2, nullptr, nullptr, ln2_g, ln2_b, NN);
    k_mma<2><<<dim3(1, MB), 256, MMA_SMEM>>>(h1hi, h1lo, DH, 0, 128, btrhi, btrlo,
                                             out_x, DOUT, res_b, x2, DOUT, NN, DH);
}

// round 13
// speedup vs baseline: 1.0384x; 1.0384x over previous
#include <cuda_runtime.h>
#include <cuda_bf16.h>
#include <math.h>
#include <stdint.h>

// ---------------- problem constants ----------------
#define NN   30000
#define EE   480000
#define DIN  768
#define DH   256    // HID
#define DOUT 128    // OUT
#define NHEAD 4
#define NCLS 3

// ---------------- scratch (static device memory; no allocations) ----------------
__device__ float    g_Wh   [(size_t)NN * (NHEAD * DH)];
__device__ float    g_xnew [(size_t)NN * (NHEAD * DH)];
__device__ __align__(16) float g_s1 [NHEAD * NN];   // interleaved [node][head]
__device__ __align__(16) float g_s2 [NHEAD * NN];
__device__ float    g_w    [(size_t)NHEAD * EE];
__device__ float    g_w2e  [EE];
__device__ float    g_hbuf [(size_t)NN * 512];
__device__ float    g_evsum[NN * NCLS];
__device__ float    g_h1   [(size_t)NN * DH];
__device__ float    g_Wh2  [(size_t)NN * DOUT];
__device__ float    g_s1b  [NN];
__device__ float    g_s2b  [NN];
__device__ float    g_xnew2[(size_t)NN * DOUT];
__device__ float    g_x2   [(size_t)NN * DOUT];
__device__ unsigned g_maxenc[12];
__device__ float    g_M    [8];
__device__ double   g_sumexp[8];
__device__ float    g_invS  [8];

// CSR (edges grouped by tgt)
__device__ int g_rowptr[NN + 1];
__device__ int g_cursor[NN];
__device__ int g_eidx  [EE];

// transposed + bf16-split weights (Bt[n][k], K-major)
__device__ __align__(256) __nv_bfloat16 g_bt1hi [1024 * 768], g_bt1lo [1024 * 768];
__device__ __align__(256) __nv_bfloat16 g_btahi [256 * 1024], g_btalo [256 * 1024];
__device__ __align__(256) __nv_bfloat16 g_btehi [512 * 256],  g_btelo [512 * 256];
__device__ __align__(256) __nv_bfloat16 g_btw2hi[128 * 256],  g_btw2lo[128 * 256];
__device__ __align__(256) __nv_bfloat16 g_btrhi [128 * 256],  g_btrlo [128 * 256];

// ---------------- helpers ----------------
__device__ __forceinline__ unsigned fenc(float f) {
    unsigned u = __float_as_uint(f);
    return (u & 0x80000000u) ? ~u : (u | 0x80000000u);
}
__device__ __forceinline__ float fdec(unsigned u) {
    return (u & 0x80000000u) ? __uint_as_float(u & 0x7fffffffu) : __uint_as_float(~u);
}
__device__ __forceinline__ float wsumf(float v) {
#pragma unroll
    for (int o = 16; o > 0; o >>= 1) v += __shfl_xor_sync(0xffffffffu, v, o);
    return v;
}
__device__ __forceinline__ float softplusf(float x) {
    return fmaxf(x, 0.f) + log1pf(expf(-fabsf(x)));
}
__device__ __forceinline__ float eluf(float x) {
    return x > 0.f ? x : expm1f(x);
}
__device__ __forceinline__ void bf16split(float x, __nv_bfloat16& hi, __nv_bfloat16& lo) {
    hi = __float2bfloat16(x);
    lo = __float2bfloat16(x - __bfloat162float(hi));
}

// mma.sync m16n8k16 bf16 (row.col), fp32 accumulate — compiles on plain sm_103.
__device__ __forceinline__ void mma_bf16(float* c, const uint32_t* a, const uint32_t* b) {
    asm volatile(
        "mma.sync.aligned.m16n8k16.row.col.f32.bf16.bf16.f32 "
        "{%0,%1,%2,%3}, {%4,%5,%6,%7}, {%8,%9}, {%0,%1,%2,%3};"
        : "+f"(c[0]), "+f"(c[1]), "+f"(c[2]), "+f"(c[3])
        : "r"(a[0]), "r"(a[1]), "r"(a[2]), "r"(a[3]), "r"(b[0]), "r"(b[1]));
}

// ---------------- init ----------------
__global__ void k_init() {
    int i = blockIdx.x * blockDim.x + threadIdx.x;
    int stride = gridDim.x * blockDim.x;
    for (int j = i; j <= NN; j += stride) g_rowptr[j] = 0;
    if (i < 12) g_maxenc[i] = 0u;
    if (i < 8)  { g_sumexp[i] = 0.0; g_invS[i] = 0.f; g_M[i] = 0.f; }
}

// ---------------- fused B transpose + bf16 split (all 5 weight tensors) ----------------
__global__ void k_btall(const float* w1, const float* wa, const float* we,
                        const float* w2, const float* wr)
{
    // block ranges (256 elems per block):
    // 0:    W_heads  1024x768  (3072 blocks)
    // 3072: agg      256x1024  (1024)
    // 4096: ev1      512x256   (512)
    // 4608: W2       128x256   (128)
    // 4736: res      128x256   (128)  -> total 4864
    const float* src; __nv_bfloat16 *hi, *lo;
    int K, headN, headStride, base;
    int b = blockIdx.x;
    if (b < 3072)      { src = w1; hi = g_bt1hi;  lo = g_bt1lo;  K = 768;  headN = 256; headStride = 768 * 256; base = 0; }
    else if (b < 4096) { src = wa; hi = g_btahi;  lo = g_btalo;  K = 1024; headN = 256; headStride = 0;         base = 3072; }
    else if (b < 4608) { src = we; hi = g_btehi;  lo = g_btelo;  K = 256;  headN = 128; headStride = 256 * 128; base = 4096; }
    else if (b < 4736) { src = w2; hi = g_btw2hi; lo = g_btw2lo; K = 256;  headN = 128; headStride = 0;         base = 4608; }
    else               { src = wr; hi = g_btrhi;  lo = g_btrlo;  K = 256;  headN = 128; headStride = 0;         base = 4736; }
    int idx = (b - base) * 256 + threadIdx.x;
    int n = idx / K, k = idx - n * K;
    int head = n / headN, nloc = n - head * headN;
    float v = src[(size_t)head * headStride + (size_t)k * headN + nloc];
    __nv_bfloat16 h, l;
    bf16split(v, h, l);
    hi[idx] = h;
    lo[idx] = l;
}

// ---------------- CSR build ----------------
__global__ void k_hist(const int* __restrict__ tgt) {
    int e = blockIdx.x * blockDim.x + threadIdx.x;
    if (e < EE) atomicAdd(&g_rowptr[tgt[e] + 1], 1);
}

__global__ void k_scan() {
    __shared__ int part[1024];
    int tid = threadIdx.x;
    const int CH = (NN + 1023) / 1024;
    int beg = tid * CH;
    int end = beg + CH; if (end > NN) end = NN;
    int s = 0;
    for (int i = beg; i < end; i++) s += g_rowptr[i + 1];
    part[tid] = s;
    __syncthreads();
    for (int off = 1; off < 1024; off <<= 1) {
        int v = (tid >= off) ? part[tid - off] : 0;
        __syncthreads();
        part[tid] += v;
        __syncthreads();
    }
    int run = (tid > 0) ? part[tid - 1] : 0;
    for (int i = beg; i < end; i++) {
        int c = g_rowptr[i + 1];
        g_cursor[i] = run;
        run += c;
        g_rowptr[i + 1] = run;
    }
    if (tid == 0) g_rowptr[0] = 0;
}

__global__ void k_fill(const int* __restrict__ tgt) {
    int e = blockIdx.x * blockDim.x + threadIdx.x;
    if (e < EE) {
        int p = atomicAdd(&g_cursor[tgt[e]], 1);
        g_eidx[p] = e;
    }
}

// ---------------- bf16-split tensor-core GEMM, double-buffered (R8 proven) ----------------
#define ASTR 40
#define TILE_B 10240
#define BUF_B  (4 * TILE_B)
#define MMA_SMEM (2 * BUF_B)

template <int EPI>
__global__ __launch_bounds__(256, 1)
void k_mma(const float* __restrict__ A, int lda, int aHeadStep, int headN,
           const __nv_bfloat16* __restrict__ Bthi, const __nv_bfloat16* __restrict__ Btlo,
           float* __restrict__ C, int ldc,
           const float* __restrict__ bias,
           const float* __restrict__ addend, int ldadd,
           int M, int K)
{
    extern __shared__ __align__(16) char smraw[];

    const int tid = threadIdx.x;
    const int lane = tid & 31;
    const int wid = tid >> 5;
    const int warp_m = wid & 1;
    const int warp_n = wid >> 1;
    const int g  = lane >> 2;
    const int tg = lane & 3;

    const int m0 = blockIdx.y * 128;
    const int n0 = blockIdx.x * 128;
    const float* __restrict__ Ap = A + (size_t)(n0 / headN) * aHeadStep;

    float acc[4][4][4];
#pragma unroll
    for (int i = 0; i < 4; i++)
#pragma unroll
        for (int j = 0; j < 4; j++)
#pragma unroll
            for (int k = 0; k < 4; k++) acc[i][j][k] = 0.f;

    float4 ra[4];
    uint4  rbh[2], rbl[2];

    auto load_tiles = [&](int k0) {
#pragma unroll
        for (int i = 0; i < 4; i++) {
            int idx = tid + 256 * i;
            int row = idx >> 3, c4 = (idx & 7) << 2;
            int gm = m0 + row;
            ra[i] = (gm < M) ? *(const float4*)&Ap[(size_t)gm * lda + k0 + c4]
                             : make_float4(0.f, 0.f, 0.f, 0.f);
        }
#pragma unroll
        for (int i = 0; i < 2; i++) {
            int idx = tid + 256 * i;
            int row = idx >> 2, c8 = (idx & 3) << 3;
            size_t gi = (size_t)(n0 + row) * K + k0 + c8;
            rbh[i] = *(const uint4*)&Bthi[gi];
            rbl[i] = *(const uint4*)&Btlo[gi];
        }
    };
    auto store_tiles = [&](int s) {
        __nv_bfloat16* sAhi = (__nv_bfloat16*)(smraw + s * BUF_B);
        __nv_bfloat16* sAlo = (__nv_bfloat16*)(smraw + s * BUF_B + TILE_B);
        __nv_bfloat16* sBhi = (__nv_bfloat16*)(smraw + s * BUF_B + 2 * TILE_B);
        __nv_bfloat16* sBlo = (__nv_bfloat16*)(smraw + s * BUF_B + 3 * TILE_B);
#pragma unroll
        for (int i = 0; i < 4; i++) {
            int idx = tid + 256 * i;
            int row = idx >> 3, c4 = (idx & 7) << 2;
            __nv_bfloat16 hx, lx, hy, ly, hz, lz, hw, lw;
            bf16split(ra[i].x, hx, lx); bf16split(ra[i].y, hy, ly);
            bf16split(ra[i].z, hz, lz); bf16split(ra[i].w, hw, lw);
            int o = row * ASTR + c4;
            *(__nv_bfloat162*)&sAhi[o]     = __nv_bfloat162(hx, hy);
            *(__nv_bfloat162*)&sAhi[o + 2] = __nv_bfloat162(hz, hw);
            *(__nv_bfloat162*)&sAlo[o]     = __nv_bfloat162(lx, ly);
            *(__nv_bfloat162*)&sAlo[o + 2] = __nv_bfloat162(lz, lw);
        }
#pragma unroll
        for (int i = 0; i < 2; i++) {
            int idx = tid + 256 * i;
            int row = idx >> 2, c8 = (idx & 3) << 3;
            *(uint4*)&sBhi[row * ASTR + c8] = rbh[i];
            *(uint4*)&sBlo[row * ASTR + c8] = rbl[i];
        }
    };
    auto compute = [&](int s) {
        const __nv_bfloat16* sAhi = (const __nv_bfloat16*)(smraw + s * BUF_B);
        const __nv_bfloat16* sAlo = (const __nv_bfloat16*)(smraw + s * BUF_B + TILE_B);
        const __nv_bfloat16* sBhi = (const __nv_bfloat16*)(smraw + s * BUF_B + 2 * TILE_B);
        const __nv_bfloat16* sBlo = (const __nv_bfloat16*)(smraw + s * BUF_B + 3 * TILE_B);
#pragma unroll
        for (int kc = 0; kc < 32; kc += 16) {
            uint32_t ah[4][4], al[4][4];
#pragma unroll
            for (int mt = 0; mt < 4; mt++) {
                int base = (warp_m * 64 + mt * 16 + g) * ASTR + kc + tg * 2;
                ah[mt][0] = *(const uint32_t*)&sAhi[base];
                ah[mt][1] = *(const uint32_t*)&sAhi[base + 8 * ASTR];
                ah[mt][2] = *(const uint32_t*)&sAhi[base + 8];
                ah[mt][3] = *(const uint32_t*)&sAhi[base + 8 * ASTR + 8];
                al[mt][0] = *(const uint32_t*)&sAlo[base];
                al[mt][1] = *(const uint32_t*)&sAlo[base + 8 * ASTR];
                al[mt][2] = *(const uint32_t*)&sAlo[base + 8];
                al[mt][3] = *(const uint32_t*)&sAlo[base + 8 * ASTR + 8];
            }
            uint32_t bh[4][2], bl[4][2];
#pragma unroll
            for (int nt = 0; nt < 4; nt++) {
                int base = (warp_n * 32 + nt * 8 + g) * ASTR + kc + tg * 2;
                bh[nt][0] = *(const uint32_t*)&sBhi[base];
                bh[nt][1] = *(const uint32_t*)&sBhi[base + 8];
                bl[nt][0] = *(const uint32_t*)&sBlo[base];
                bl[nt][1] = *(const uint32_t*)&sBlo[base + 8];
            }
#pragma unroll
            for (int mt = 0; mt < 4; mt++)
#pragma unroll
                for (int nt = 0; nt < 4; nt++) {
                    mma_bf16(acc[mt][nt], ah[mt], bh[nt]);
                    mma_bf16(acc[mt][nt], ah[mt], bl[nt]);
                    mma_bf16(acc[mt][nt], al[mt], bh[nt]);
                }
        }
    };

    const int T = K / 32;
    load_tiles(0);
    store_tiles(0);
    __syncthreads();
    for (int t = 1; t < T; t++) {
        load_tiles(t * 32);
        compute((t - 1) & 1);
        store_tiles(t & 1);
        __syncthreads();
    }
    compute((T - 1) & 1);

    // epilogue
#pragma unroll
    for (int mt = 0; mt < 4; mt++) {
        int r0 = m0 + warp_m * 64 + mt * 16 + g;
#pragma unroll
        for (int nt = 0; nt < 4; nt++) {
            int gc = n0 + warp_n * 32 + nt * 8 + tg * 2;
            float2 v01 = make_float2(acc[mt][nt][0], acc[mt][nt][1]);
            float2 v23 = make_float2(acc[mt][nt][2], acc[mt][nt][3]);
            if (bias) {
                float2 b = *(const float2*)&bias[gc];
                v01.x += b.x; v01.y += b.y;
                v23.x += b.x; v23.y += b.y;
            }
            if (EPI == 1) {
                v01.x = fmaxf(v01.x, 0.f); v01.y = fmaxf(v01.y, 0.f);
                v23.x = fmaxf(v23.x, 0.f); v23.y = fmaxf(v23.y, 0.f);
            }
            if (r0 < M) {
                if (EPI == 2) {
                    float2 adx = *(const float2*)&addend[(size_t)r0 * ldadd + gc];
                    v01.x += adx.x; v01.y += adx.y;
                }
                *(float2*)&C[(size_t)r0 * ldc + gc] = v01;
            }
            if (r0 + 8 < M) {
                if (EPI == 2) {
                    float2 adx = *(const float2*)&addend[(size_t)(r0 + 8) * ldadd + gc];
                    v23.x += adx.x; v23.y += adx.y;
                }
                *(float2*)&C[(size_t)(r0 + 8) * ldc + gc] = v23;
            }
        }
    }
}

// ---------------- fp32 SGEMM (small evidence-2 GEMM only) ----------------
#define BM 128
#define BN 128
#define BKK 16
template <int EPI>
__global__ __launch_bounds__(256, 2)
void k_sgemm(const float* __restrict__ A, int lda,
             const float* __restrict__ B, int ldb,
             float* __restrict__ C, int ldc,
             const float* __restrict__ bias,
             int M, int N, int K)
{
    __shared__ float As[BKK][BM + 4];
    __shared__ float Bs[BKK][BN];
    const int tid = threadIdx.x;
    const int m0 = blockIdx.y * BM;
    const int n0 = blockIdx.x * BN;
    const int tm = tid >> 4, tn = tid & 15;
    const int a_kk = tid & 15, a_m0 = tid >> 4;
    const int b_kk0 = tid >> 5, b_nb = (tid & 31) << 2;

    float acc[8][8];
#pragma unroll
    for (int i = 0; i < 8; i++)
#pragma unroll
        for (int j = 0; j < 8; j++) acc[i][j] = 0.f;

    float ra[8]; float4 rb[2];
    auto load_tiles = [&](int k0) {
#pragma unroll
        for (int i = 0; i < 8; i++) {
            int gm = m0 + a_m0 + 16 * i;
            ra[i] = (gm < M) ? A[(size_t)gm * lda + (k0 + a_kk)] : 0.f;
        }
#pragma unroll
        for (int i = 0; i < 2; i++) {
            int kk = b_kk0 + 8 * i;
            int gn = n0 + b_nb;
            float4 v = make_float4(0.f, 0.f, 0.f, 0.f);
            const float* bp = &B[(size_t)(k0 + kk) * ldb + b_nb];
            if (gn + 3 < N) v = *(const float4*)bp;
            else {
                if (gn     < N) v.x = bp[0];
                if (gn + 1 < N) v.y = bp[1];
                if (gn + 2 < N) v.z = bp[2];
            }
            rb[i] = v;
        }
    };
    auto store_tiles = [&]() {
#pragma unroll
        for (int i = 0; i < 8; i++) As[a_kk][a_m0 + 16 * i] = ra[i];
#pragma unroll
        for (int i = 0; i < 2; i++) *(float4*)&Bs[b_kk0 + 8 * i][b_nb] = rb[i];
    };
    auto compute = [&]() {
#pragma unroll
        for (int kk = 0; kk < BKK; kk++) {
            float a[8], b[8];
#pragma unroll
            for (int i = 0; i < 8; i++) a[i] = As[kk][tm * 8 + i];
#pragma unroll
            for (int j = 0; j < 8; j++) b[j] = Bs[kk][tn * 8 + j];
#pragma unroll
            for (int i = 0; i < 8; i++)
#pragma unroll
                for (int j = 0; j < 8; j++) acc[i][j] = fmaf(a[i], b[j], acc[i][j]);
        }
    };
    load_tiles(0); store_tiles(); __syncthreads();
    for (int k0 = BKK; k0 < K; k0 += BKK) {
        load_tiles(k0); compute(); __syncthreads(); store_tiles(); __syncthreads();
    }
    compute();
#pragma unroll
    for (int i = 0; i < 8; i++) {
        int gm = m0 + tm * 8 + i;
        if (gm < M) {
#pragma unroll
            for (int j = 0; j < 8; j++) {
                int gn = n0 + tn * 8 + j;
                if (gn < N) {
                    float v = acc[i][j];
                    if (bias) v += bias[gn];
                    if (EPI == 1) v = fmaxf(v, 0.f);
                    C[(size_t)gm * ldc + gn] = v;
                }
            }
        }
    }
}

// ---------------- attention projections + node maxima (interleaved [node][head]) ----------------
__global__ void k_s1s2(const float* __restrict__ Wh, int ld, int F, int nh,
                       const float* __restrict__ a, int aStride,
                       float* __restrict__ s1, float* __restrict__ s2, int N,
                       int slot1, int slot2)
{
    int gw = (blockIdx.x * blockDim.x + threadIdx.x) >> 5;
    int lane = threadIdx.x & 31;
    if (gw >= N * nh) return;
    int node = gw / nh;
    int h = gw - node * nh;
    const float* wr = &Wh[(size_t)node * ld + h * F];
    const float* ah = &a[(size_t)h * aStride];
    float p1 = 0.f, p2 = 0.f;
    for (int j = lane; j < F; j += 32) {
        float x = wr[j];
        p1 = fmaf(x, ah[j], p1);
        p2 = fmaf(x, ah[F + j], p2);
    }
    p1 = wsumf(p1); p2 = wsumf(p2);
    if (lane == 0) {
        s1[(size_t)node * nh + h] = p1;
        s2[(size_t)node * nh + h] = p2;
        atomicMax(&g_maxenc[slot1 + h], fenc(p1));
        atomicMax(&g_maxenc[slot2 + h], fenc(p2));
    }
}

__global__ void k_prepM(int slot, int slot1, int slot2, int n)
{
    int i = threadIdx.x;
    if (i < n) {
        float l = fdec(g_maxenc[slot1 + i]) + fdec(g_maxenc[slot2 + i]);
        g_M[slot + i] = (l > 0.f) ? l : 0.2f * l;
    }
}

// ---------------- edge pass: w = exp(lrelu(s1[src]+s2[tgt]) - M); block-sum ----------------
template <int NH>
__global__ void k_expsum(const int* __restrict__ src, const int* __restrict__ tgt,
                         const float* __restrict__ s1, const float* __restrict__ s2,
                         float* __restrict__ w, int E, int slot)
{
    int e = blockIdx.x * blockDim.x + threadIdx.x;
    int tid = threadIdx.x;
    bool ok = (e < E);
    float sv[NH];
    if (NH == 4) {
        float4 a = make_float4(0.f, 0.f, 0.f, 0.f), b = a;
        if (ok) {
            int s = src[e], t = tgt[e];
            a = *(const float4*)&s1[(size_t)s * 4];
            b = *(const float4*)&s2[(size_t)t * 4];
        }
        float lv[4] = { a.x + b.x, a.y + b.y, a.z + b.z, a.w + b.w };
#pragma unroll
        for (int h = 0; h < 4; h++) {
            float l = lv[h];
            l = (l > 0.f) ? l : 0.2f * l;
            float v = ok ? expf(l - g_M[slot + h]) : 0.f;
            if (ok) w[(size_t)h * E + e] = v;
            sv[h] = v;
        }
    } else {
        float v = 0.f;
        if (ok) {
            int s = src[e], t = tgt[e];
            float l = s1[s] + s2[t];
            l = (l > 0.f) ? l : 0.2f * l;
            v = expf(l - g_M[slot]);
            w[e] = v;
        }
        sv[0] = v;
    }
    // warp reduce, one smem round, reduce in full warp 0 (shuffle mask legality)
    __shared__ float red[NH * 8];
    int wi = tid >> 5, lane = tid & 31;
#pragma unroll
    for (int h = 0; h < NH; h++) {
        float v = wsumf(sv[h]);
        if (lane == 0) red[h * 8 + wi] = v;
    }
    __syncthreads();
    if (tid < 32) {
        float v = (tid < NH * 8) ? red[tid] : 0.f;
        v += __shfl_down_sync(0xffffffffu, v, 4);
        v += __shfl_down_sync(0xffffffffu, v, 2);
        v += __shfl_down_sync(0xffffffffu, v, 1);
        if ((tid & 7) == 0 && tid < NH * 8)
            atomicAdd(&g_sumexp[slot + (tid >> 3)], (double)v);
    }
}

__global__ void k_finalize(int slot0, int n)
{
    int i = threadIdx.x;
    if (i < n) g_invS[slot0 + i] = (float)(1.0 / g_sumexp[slot0 + i]);
}

// ---------------- CSR gather ----------------
__global__ __launch_bounds__(256, 8)
void k_gather1024(const int* __restrict__ src, const float* __restrict__ w,
                  const float* __restrict__ Wh, float* __restrict__ xnew, int slot0)
{
    int node = blockIdx.x;
    int tid = threadIdx.x;
    int head = tid >> 6;
    int col = tid * 4;
    const float* wh = &w[(size_t)head * EE];

    int p = g_rowptr[node];
    const int end = g_rowptr[node + 1];

    int s_cur = 0; float c_cur = 0.f;
    if (p < end) { int e = g_eidx[p]; s_cur = src[e]; c_cur = wh[e]; }

    float4 acc = make_float4(0.f, 0.f, 0.f, 0.f);
    while (p < end) {
        int s_nxt = 0; float c_nxt = 0.f;
        if (p + 1 < end) { int e = g_eidx[p + 1]; s_nxt = src[e]; c_nxt = wh[e]; }
        float4 v = *(const float4*)&Wh[(size_t)s_cur * 1024 + col];
        acc.x = fmaf(c_cur, v.x, acc.x);
        acc.y = fmaf(c_cur, v.y, acc.y);
        acc.z = fmaf(c_cur, v.z, acc.z);
        acc.w = fmaf(c_cur, v.w, acc.w);
        s_cur = s_nxt; c_cur = c_nxt; p++;
    }
    float inv = g_invS[slot0 + head];
    acc.x *= inv; acc.y *= inv; acc.z *= inv; acc.w *= inv;
    *(float4*)&xnew[(size_t)node * 1024 + col] = acc;
}

__global__ __launch_bounds__(256, 8)
void k_gather128(const int* __restrict__ src, const float* __restrict__ w,
                 const float* __restrict__ Wh, float* __restrict__ xnew, int slot)
{
    int node = (blockIdx.x * blockDim.x + threadIdx.x) >> 5;
    int lane = threadIdx.x & 31;
    if (node >= NN) return;
    int col = lane * 4;

    int p = g_rowptr[node];
    const int end = g_rowptr[node + 1];

    int s_cur = 0; float c_cur = 0.f;
    if (p < end) { int e = g_eidx[p]; s_cur = src[e]; c_cur = w[e]; }

    float4 acc = make_float4(0.f, 0.f, 0.f, 0.f);
    while (p < end) {
        int s_nxt = 0; float c_nxt = 0.f;
        if (p + 1 < end) { int e = g_eidx[p + 1]; s_nxt = src[e]; c_nxt = w[e]; }
        float4 v = *(const float4*)&Wh[(size_t)s_cur * 128 + col];
        acc.x = fmaf(c_cur, v.x, acc.x);
        acc.y = fmaf(c_cur, v.y, acc.y);
        acc.z = fmaf(c_cur, v.z, acc.z);
        acc.w = fmaf(c_cur, v.w, acc.w);
        s_cur = s_nxt; c_cur = c_nxt; p++;
    }
    float inv = g_invS[slot];
    acc.x *= inv; acc.y *= inv; acc.z *= inv; acc.w *= inv;
    *(float4*)&xnew[(size_t)node * 128 + col] = acc;
}

// ---------------- evidence heads ----------------
__global__ void k_evid1(const float* __restrict__ hbuf, const float* __restrict__ w2,
                        const float* __restrict__ b2, float* __restrict__ evsum, int N)
{
    int gw = (blockIdx.x * blockDim.x + threadIdx.x) >> 5;
    int lane = threadIdx.x & 31;
    if (gw >= N) return;
    float e0 = 0.f, e1 = 0.f, e2 = 0.f;
#pragma unroll
    for (int h = 0; h < NHEAD; h++) {
        float4 v = *(const float4*)&hbuf[(size_t)gw * 512 + h * 128 + lane * 4];
        const float* wc = &w2[h * 384 + lane * 12];
        float a0 = v.x * wc[0] + v.y * wc[3] + v.z * wc[6] + v.w * wc[9];
        float a1 = v.x * wc[1] + v.y * wc[4] + v.z * wc[7] + v.w * wc[10];
        float a2 = v.x * wc[2] + v.y * wc[5] + v.z * wc[8] + v.w * wc[11];
        a0 = wsumf(a0); a1 = wsumf(a1); a2 = wsumf(a2);
        e0 += softplusf(a0 + b2[h * 3 + 0]) + 1.f;
        e1 += softplusf(a1 + b2[h * 3 + 1]) + 1.f;
        e2 += softplusf(a2 + b2[h * 3 + 2]) + 1.f;
    }
    if (lane == 0) {
        evsum[gw * 3 + 0] = e0; evsum[gw * 3 + 1] = e1; evsum[gw * 3 + 2] = e2;
    }
}

__global__ void k_evid2(const float* __restrict__ hbuf, const float* __restrict__ w2,
                        const float* __restrict__ b2, const float* __restrict__ evsum,
                        float* __restrict__ out, int N)
{
    int gw = (blockIdx.x * blockDim.x + threadIdx.x) >> 5;
    int lane = threadIdx.x & 31;
    if (gw >= N) return;
    float2 v = *(const float2*)&hbuf[(size_t)gw * 64 + lane * 2];
    const float* wc = &w2[lane * 6];
    float a0 = v.x * wc[0] + v.y * wc[3];
    float a1 = v.x * wc[1] + v.y * wc[4];
    float a2 = v.x * wc[2] + v.y * wc[5];
    a0 = wsumf(a0); a1 = wsumf(a1); a2 = wsumf(a2);
    if (lane == 0) {
        float e0 = softplusf(a0 + b2[0]) + 1.f;
        float e1 = softplusf(a1 + b2[1]) + 1.f;
        float e2 = softplusf(a2 + b2[2]) + 1.f;
        out[(size_t)gw * 3 + 0] = (evsum[gw * 3 + 0] * 0.25f + e0) * 0.5f;
        out[(size_t)gw * 3 + 1] = (evsum[gw * 3 + 1] * 0.25f + e1) * 0.5f;
        out[(size_t)gw * 3 + 2] = (evsum[gw * 3 + 2] * 0.25f + e2) * 0.5f;
    }
}

// ---------------- LayerNorm + ELU ----------------
template <int F>
__global__ void k_ln_elu(const float* __restrict__ in, float* __restrict__ out,
                         const float* __restrict__ gam, const float* __restrict__ bet, int N)
{
    int gw = (blockIdx.x * blockDim.x + threadIdx.x) >> 5;
    int lane = threadIdx.x & 31;
    if (gw >= N) return;
    constexpr int R = F / 32;
    float v[R];
    const float* ir = &in[(size_t)gw * F];
#pragma unroll
    for (int r = 0; r < R; r++) v[r] = ir[lane + 32 * r];
    float s = 0.f;
#pragma unroll
    for (int r = 0; r < R; r++) s += v[r];
    s = wsumf(s);
    float mean = s * (1.f / F);
    float q = 0.f;
#pragma unroll
    for (int r = 0; r < R; r++) { float d = v[r] - mean; q = fmaf(d, d, q); }
    q = wsumf(q);
    float rstd = rsqrtf(q * (1.f / F) + 1e-5f);
    float* orow = &out[(size_t)gw * F];
#pragma unroll
    for (int r = 0; r < R; r++) {
        int j = lane + 32 * r;
        float y = (v[r] - mean) * rstd * gam[j] + bet[j];
        orow[j] = eluf(y);
    }
}

// ---------------- launch ----------------
extern "C" void kernel_launch(void* const* d_in, const int* in_sizes, int n_in,
                              void* d_out, int out_size)
{
    (void)in_sizes; (void)n_in; (void)out_size;

    const float* x        = (const float*)d_in[0];
    const int*   ei       = (const int*)  d_in[1];
    const float* W_heads  = (const float*)d_in[2];
    const float* a_heads  = (const float*)d_in[3];
    const float* ev1w_h   = (const float*)d_in[4];
    const float* ev1b_h   = (const float*)d_in[5];
    const float* ev2w_h   = (const float*)d_in[6];
    const float* ev2b_h   = (const float*)d_in[7];
    const float* agg_w    = (const float*)d_in[8];
    const float* agg_b    = (const float*)d_in[9];
    const float* ln1_g    = (const float*)d_in[10];
    const float* ln1_b    = (const float*)d_in[11];
    const float* W2       = (const float*)d_in[12];
    const float* a2       = (const float*)d_in[13];
    const float* ev1w2    = (const float*)d_in[14];
    const float* ev1b2    = (const float*)d_in[15];
    const float* ev2w2    = (const float*)d_in[16];
    const float* ev2b2    = (const float*)d_in[17];
    const float* ln2_g    = (const float*)d_in[18];
    const float* ln2_b    = (const float*)d_in[19];
    const float* res_w    = (const float*)d_in[20];
    const float* res_b    = (const float*)d_in[21];

    const int* src = ei;
    const int* tgt = ei + EE;

    float* out_x  = (float*)d_out;
    float* out_ev = (float*)d_out + (size_t)NN * DOUT;

    float *Wh, *xnew, *s1, *s2, *wbuf, *w2e, *hbuf, *evsum, *h1, *Wh2, *s1b, *s2b, *xnew2, *x2;
    __nv_bfloat16 *bt1hi, *bt1lo, *btahi, *btalo, *btehi, *btelo, *btw2hi, *btw2lo, *btrhi, *btrlo;
    cudaGetSymbolAddress((void**)&Wh,    g_Wh);
    cudaGetSymbolAddress((void**)&xnew,  g_xnew);
    cudaGetSymbolAddress((void**)&s1,    g_s1);
    cudaGetSymbolAddress((void**)&s2,    g_s2);
    cudaGetSymbolAddress((void**)&wbuf,  g_w);
    cudaGetSymbolAddress((void**)&w2e,   g_w2e);
    cudaGetSymbolAddress((void**)&hbuf,  g_hbuf);
    cudaGetSymbolAddress((void**)&evsum, g_evsum);
    cudaGetSymbolAddress((void**)&h1,    g_h1);
    cudaGetSymbolAddress((void**)&Wh2,   g_Wh2);
    cudaGetSymbolAddress((void**)&s1b,   g_s1b);
    cudaGetSymbolAddress((void**)&s2b,   g_s2b);
    cudaGetSymbolAddress((void**)&xnew2, g_xnew2);
    cudaGetSymbolAddress((void**)&x2,    g_x2);
    cudaGetSymbolAddress((void**)&bt1hi, g_bt1hi);
    cudaGetSymbolAddress((void**)&bt1lo, g_bt1lo);
    cudaGetSymbolAddress((void**)&btahi, g_btahi);
    cudaGetSymbolAddress((void**)&btalo, g_btalo);
    cudaGetSymbolAddress((void**)&btehi, g_btehi);
    cudaGetSymbolAddress((void**)&btelo, g_btelo);
    cudaGetSymbolAddress((void**)&btw2hi, g_btw2hi);
    cudaGetSymbolAddress((void**)&btw2lo, g_btw2lo);
    cudaGetSymbolAddress((void**)&btrhi, g_btrhi);
    cudaGetSymbolAddress((void**)&btrlo, g_btrlo);

    cudaFuncSetAttribute(k_mma<0>, cudaFuncAttributeMaxDynamicSharedMemorySize, MMA_SMEM);
    cudaFuncSetAttribute(k_mma<1>, cudaFuncAttributeMaxDynamicSharedMemorySize, MMA_SMEM);
    cudaFuncSetAttribute(k_mma<2>, cudaFuncAttributeMaxDynamicSharedMemorySize, MMA_SMEM);

    const int MB = (NN + 127) / 128;   // 235

    // launches 1-5 (so launch #6 = big k_mma for ncu's -s 5 -c 1 window)
    k_init<<<128, 256>>>();
    k_btall<<<4864, 256>>>(W_heads, agg_w, ev1w_h, W2, res_w);
    k_hist<<<(EE + 255) / 256, 256>>>(tgt);
    k_scan<<<1, 1024>>>();
    k_fill<<<(EE + 255) / 256, 256>>>(tgt);

    // 6) Wh = x @ W_heads
    k_mma<0><<<dim3(8, MB), 256, MMA_SMEM>>>(x, DIN, 0, 128, bt1hi, bt1lo,
                                             Wh, 1024, nullptr, nullptr, 0, NN, DIN);

    // attention scalars + maxima, edge pass, softmax scale
    k_s1s2<<<(NN * NHEAD) / 8, 256>>>(Wh, NHEAD * DH, DH, NHEAD, a_heads, 2 * DH, s1, s2, NN, 0, 4);
    k_prepM<<<1, 8>>>(0, 0, 4, NHEAD);
    k_expsum<NHEAD><<<(EE + 255) / 256, 256>>>(src, tgt, s1, s2, wbuf, EE, 0);
    k_finalize<<<1, 8>>>(0, NHEAD);

    // CSR gather (all heads)
    k_gather1024<<<NN, 256>>>(src, wbuf, Wh, xnew, 0);

    // evidence layer 1 (block-diagonal, relu) + fused head
    k_mma<1><<<dim3(4, MB), 256, MMA_SMEM>>>(xnew, NHEAD * DH, DH, 128, btehi, btelo,
                                             hbuf, 512, ev1b_h, nullptr, 0, NN, DH);
    k_evid1<<<NN / 8, 256>>>(hbuf, ev2w_h, ev2b_h, evsum, NN);

    // h1 = elu(LN(x_cat @ agg_w + agg_b))
    k_mma<0><<<dim3(2, MB), 256, MMA_SMEM>>>(xnew, NHEAD * DH, 0, 128, btahi, btalo,
                                             h1, DH, agg_b, nullptr, 0, NN, NHEAD * DH);
    k_ln_elu<DH><<<NN / 8, 256>>>(h1, h1, ln1_g, ln1_b, NN);

    // layer-2 GAT
    k_mma<0><<<dim3(1, MB), 256, MMA_SMEM>>>(h1, DH, 0, 128, btw2hi, btw2lo,
                                             Wh2, DOUT, nullptr, nullptr, 0, NN, DH);
    k_s1s2<<<NN / 8, 256>>>(Wh2, DOUT, DOUT, 1, a2, 2 * DOUT, s1b, s2b, NN, 8, 9);
    k_prepM<<<1, 8>>>(4, 8, 9, 1);
    k_expsum<1><<<(EE + 255) / 256, 256>>>(src, tgt, s1b, s2b, w2e, EE, 4);
    k_finalize<<<1, 8>>>(4, 1);
    k_gather128<<<(NN * 32 + 255) / 256, 256>>>(src, w2e, Wh2, xnew2, 4);

    // evidence layer 2 + final combine
    k_sgemm<1><<<dim3(1, MB), 256>>>(xnew2, DOUT, ev1w2, DOUT / 2, hbuf, DOUT / 2,
                                     ev1b2, NN, DOUT / 2, DOUT);
    k_evid2<<<NN / 8, 256>>>(hbuf, ev2w2, ev2b2, evsum, out_ev, NN);

    // x2 = elu(LN(x_new2)); x_out = x2 + h1 @ res_w + res_b
    k_ln_elu<DOUT><<<NN / 8, 256>>>(xnew2, x2, ln2_g, ln2_b, NN);
    k_mma<2><<<dim3(1, MB), 256, MMA_SMEM>>>(h1, DH, 0, 128, btrhi, btrlo,
                                             out_x, DOUT, res_b, x2, DOUT, NN, DH);
}

// round 14
// speedup vs baseline: 1.0426x; 1.0041x over previous
#include <cuda_runtime.h>
#include <cuda_bf16.h>
#include <math.h>
#include <stdint.h>

// ---------------- problem constants ----------------
#define NN   30000
#define EE   480000
#define DIN  768
#define DH   256    // HID
#define DOUT 128    // OUT
#define NHEAD 4
#define NCLS 3

// ---------------- scratch (static device memory; no allocations) ----------------
__device__ float    g_Wh   [(size_t)NN * (NHEAD * DH)];
__device__ float    g_xnew [(size_t)NN * (NHEAD * DH)];
__device__ __align__(16) float g_s1 [NHEAD * NN];   // interleaved [node][head]
__device__ __align__(16) float g_s2 [NHEAD * NN];
__device__ float    g_w    [(size_t)NHEAD * EE];
__device__ float    g_w2e  [EE];
__device__ float    g_hbuf [(size_t)NN * 512];
__device__ float    g_evsum[NN * NCLS];
__device__ float    g_h1   [(size_t)NN * DH];
__device__ float    g_Wh2  [(size_t)NN * DOUT];
__device__ float    g_s1b  [NN];
__device__ float    g_s2b  [NN];
__device__ float    g_xnew2[(size_t)NN * DOUT];
__device__ float    g_x2   [(size_t)NN * DOUT];
__device__ unsigned g_maxenc[12];
__device__ double   g_sumexp[8];
__device__ float    g_invS  [8];

// CSR (edges grouped by tgt)
__device__ int g_rowptr[NN + 1];
__device__ int g_cursor[NN];
__device__ int g_eidx  [EE];

// transposed + bf16-split weights (Bt[n][k], K-major)
__device__ __align__(256) __nv_bfloat16 g_bt1hi [1024 * 768], g_bt1lo [1024 * 768];
__device__ __align__(256) __nv_bfloat16 g_btahi [256 * 1024], g_btalo [256 * 1024];
__device__ __align__(256) __nv_bfloat16 g_btehi [512 * 256],  g_btelo [512 * 256];
__device__ __align__(256) __nv_bfloat16 g_btw2hi[128 * 256],  g_btw2lo[128 * 256];
__device__ __align__(256) __nv_bfloat16 g_btrhi [128 * 256],  g_btrlo [128 * 256];

// ---------------- helpers ----------------
__device__ __forceinline__ unsigned fenc(float f) {
    unsigned u = __float_as_uint(f);
    return (u & 0x80000000u) ? ~u : (u | 0x80000000u);
}
__device__ __forceinline__ float fdec(unsigned u) {
    return (u & 0x80000000u) ? __uint_as_float(u & 0x7fffffffu) : __uint_as_float(~u);
}
__device__ __forceinline__ float wsumf(float v) {
#pragma unroll
    for (int o = 16; o > 0; o >>= 1) v += __shfl_xor_sync(0xffffffffu, v, o);
    return v;
}
__device__ __forceinline__ float softplusf(float x) {
    return fmaxf(x, 0.f) + log1pf(expf(-fabsf(x)));
}
__device__ __forceinline__ float eluf(float x) {
    return x > 0.f ? x : expm1f(x);
}
__device__ __forceinline__ void bf16split(float x, __nv_bfloat16& hi, __nv_bfloat16& lo) {
    hi = __float2bfloat16(x);
    lo = __float2bfloat16(x - __bfloat162float(hi));
}

// mma.sync m16n8k16 bf16 (row.col), fp32 accumulate — compiles on plain sm_103.
__device__ __forceinline__ void mma_bf16(float* c, const uint32_t* a, const uint32_t* b) {
    asm volatile(
        "mma.sync.aligned.m16n8k16.row.col.f32.bf16.bf16.f32 "
        "{%0,%1,%2,%3}, {%4,%5,%6,%7}, {%8,%9}, {%0,%1,%2,%3};"
        : "+f"(c[0]), "+f"(c[1]), "+f"(c[2]), "+f"(c[3])
        : "r"(a[0]), "r"(a[1]), "r"(a[2]), "r"(a[3]), "r"(b[0]), "r"(b[1]));
}

// ---------------- fused: B transpose/split for 5 weight tensors + init tail ----------------
// blocks [0,4864): weight transposes; blocks [4864,4982): zero rowptr + scalars
#define BT_BLOCKS 4864
#define INIT_BLOCKS 118
__global__ void k_btall(const float* w1, const float* wa, const float* we,
                        const float* w2, const float* wr)
{
    int b = blockIdx.x;
    if (b >= BT_BLOCKS) {
        int i = (b - BT_BLOCKS) * 256 + threadIdx.x;
        if (i <= NN) g_rowptr[i] = 0;
        if (b == BT_BLOCKS) {
            if (threadIdx.x < 12) g_maxenc[threadIdx.x] = 0u;
            if (threadIdx.x < 8)  { g_sumexp[threadIdx.x] = 0.0; g_invS[threadIdx.x] = 0.f; }
        }
        return;
    }
    const float* src; __nv_bfloat16 *hi, *lo;
    int K, headN, headStride, base;
    if (b < 3072)      { src = w1; hi = g_bt1hi;  lo = g_bt1lo;  K = 768;  headN = 256; headStride = 768 * 256; base = 0; }
    else if (b < 4096) { src = wa; hi = g_btahi;  lo = g_btalo;  K = 1024; headN = 256; headStride = 0;         base = 3072; }
    else if (b < 4608) { src = we; hi = g_btehi;  lo = g_btelo;  K = 256;  headN = 128; headStride = 256 * 128; base = 4096; }
    else if (b < 4736) { src = w2; hi = g_btw2hi; lo = g_btw2lo; K = 256;  headN = 128; headStride = 0;         base = 4608; }
    else               { src = wr; hi = g_btrhi;  lo = g_btrlo;  K = 256;  headN = 128; headStride = 0;         base = 4736; }
    int idx = (b - base) * 256 + threadIdx.x;
    int n = idx / K, k = idx - n * K;
    int head = n / headN, nloc = n - head * headN;
    float v = src[(size_t)head * headStride + (size_t)k * headN + nloc];
    __nv_bfloat16 h, l;
    bf16split(v, h, l);
    hi[idx] = h;
    lo[idx] = l;
}

// ---------------- CSR build ----------------
__global__ void k_hist(const int* __restrict__ tgt) {
    int e = blockIdx.x * blockDim.x + threadIdx.x;
    if (e < EE) atomicAdd(&g_rowptr[tgt[e] + 1], 1);
}

// warp-shuffle scan: 2 syncthreads total
__global__ void k_scan() {
    __shared__ int warp_tot[32];
    int tid = threadIdx.x;
    int lane = tid & 31, wi = tid >> 5;
    const int CH = (NN + 1023) / 1024;   // 30
    int beg = tid * CH;
    int end = beg + CH; if (end > NN) end = NN;
    int s = 0;
    for (int i = beg; i < end; i++) s += g_rowptr[i + 1];
    // inclusive scan across 1024 threads
    int v = s;
#pragma unroll
    for (int o = 1; o < 32; o <<= 1) {
        int u = __shfl_up_sync(0xffffffffu, v, o);
        if (lane >= o) v += u;
    }
    if (lane == 31) warp_tot[wi] = v;
    __syncthreads();
    if (wi == 0) {
        int w = warp_tot[lane];
#pragma unroll
        for (int o = 1; o < 32; o <<= 1) {
            int u = __shfl_up_sync(0xffffffffu, w, o);
            if (lane >= o) w += u;
        }
        warp_tot[lane] = w;
    }
    __syncthreads();
    int run = v - s + (wi > 0 ? warp_tot[wi - 1] : 0);   // exclusive prefix
    for (int i = beg; i < end; i++) {
        int c = g_rowptr[i + 1];
        g_cursor[i] = run;
        run += c;
        g_rowptr[i + 1] = run;
    }
    if (tid == 0) g_rowptr[0] = 0;
}

__global__ void k_fill(const int* __restrict__ tgt) {
    int e = blockIdx.x * blockDim.x + threadIdx.x;
    if (e < EE) {
        int p = atomicAdd(&g_cursor[tgt[e]], 1);
        g_eidx[p] = e;
    }
}

// ---------------- bf16-split tensor-core GEMM, double-buffered (R8 proven) ----------------
#define ASTR 40
#define TILE_B 10240
#define BUF_B  (4 * TILE_B)
#define MMA_SMEM (2 * BUF_B)

template <int EPI>
__global__ __launch_bounds__(256, 1)
void k_mma(const float* __restrict__ A, int lda, int aHeadStep, int headN,
           const __nv_bfloat16* __restrict__ Bthi, const __nv_bfloat16* __restrict__ Btlo,
           float* __restrict__ C, int ldc,
           const float* __restrict__ bias,
           const float* __restrict__ addend, int ldadd,
           int M, int K)
{
    extern __shared__ __align__(16) char smraw[];

    const int tid = threadIdx.x;
    const int lane = tid & 31;
    const int wid = tid >> 5;
    const int warp_m = wid & 1;
    const int warp_n = wid >> 1;
    const int g  = lane >> 2;
    const int tg = lane & 3;

    const int m0 = blockIdx.y * 128;
    const int n0 = blockIdx.x * 128;
    const float* __restrict__ Ap = A + (size_t)(n0 / headN) * aHeadStep;

    float acc[4][4][4];
#pragma unroll
    for (int i = 0; i < 4; i++)
#pragma unroll
        for (int j = 0; j < 4; j++)
#pragma unroll
            for (int k = 0; k < 4; k++) acc[i][j][k] = 0.f;

    float4 ra[4];
    uint4  rbh[2], rbl[2];

    auto load_tiles = [&](int k0) {
#pragma unroll
        for (int i = 0; i < 4; i++) {
            int idx = tid + 256 * i;
            int row = idx >> 3, c4 = (idx & 7) << 2;
            int gm = m0 + row;
            ra[i] = (gm < M) ? *(const float4*)&Ap[(size_t)gm * lda + k0 + c4]
                             : make_float4(0.f, 0.f, 0.f, 0.f);
        }
#pragma unroll
        for (int i = 0; i < 2; i++) {
            int idx = tid + 256 * i;
            int row = idx >> 2, c8 = (idx & 3) << 3;
            size_t gi = (size_t)(n0 + row) * K + k0 + c8;
            rbh[i] = *(const uint4*)&Bthi[gi];
            rbl[i] = *(const uint4*)&Btlo[gi];
        }
    };
    auto store_tiles = [&](int s) {
        __nv_bfloat16* sAhi = (__nv_bfloat16*)(smraw + s * BUF_B);
        __nv_bfloat16* sAlo = (__nv_bfloat16*)(smraw + s * BUF_B + TILE_B);
        __nv_bfloat16* sBhi = (__nv_bfloat16*)(smraw + s * BUF_B + 2 * TILE_B);
        __nv_bfloat16* sBlo = (__nv_bfloat16*)(smraw + s * BUF_B + 3 * TILE_B);
#pragma unroll
        for (int i = 0; i < 4; i++) {
            int idx = tid + 256 * i;
            int row = idx >> 3, c4 = (idx & 7) << 2;
            __nv_bfloat16 hx, lx, hy, ly, hz, lz, hw, lw;
            bf16split(ra[i].x, hx, lx); bf16split(ra[i].y, hy, ly);
            bf16split(ra[i].z, hz, lz); bf16split(ra[i].w, hw, lw);
            int o = row * ASTR + c4;
            *(__nv_bfloat162*)&sAhi[o]     = __nv_bfloat162(hx, hy);
            *(__nv_bfloat162*)&sAhi[o + 2] = __nv_bfloat162(hz, hw);
            *(__nv_bfloat162*)&sAlo[o]     = __nv_bfloat162(lx, ly);
            *(__nv_bfloat162*)&sAlo[o + 2] = __nv_bfloat162(lz, lw);
        }
#pragma unroll
        for (int i = 0; i < 2; i++) {
            int idx = tid + 256 * i;
            int row = idx >> 2, c8 = (idx & 3) << 3;
            *(uint4*)&sBhi[row * ASTR + c8] = rbh[i];
            *(uint4*)&sBlo[row * ASTR + c8] = rbl[i];
        }
    };
    auto compute = [&](int s) {
        const __nv_bfloat16* sAhi = (const __nv_bfloat16*)(smraw + s * BUF_B);
        const __nv_bfloat16* sAlo = (const __nv_bfloat16*)(smraw + s * BUF_B + TILE_B);
        const __nv_bfloat16* sBhi = (const __nv_bfloat16*)(smraw + s * BUF_B + 2 * TILE_B);
        const __nv_bfloat16* sBlo = (const __nv_bfloat16*)(smraw + s * BUF_B + 3 * TILE_B);
#pragma unroll
        for (int kc = 0; kc < 32; kc += 16) {
            uint32_t ah[4][4], al[4][4];
#pragma unroll
            for (int mt = 0; mt < 4; mt++) {
                int base = (warp_m * 64 + mt * 16 + g) * ASTR + kc + tg * 2;
                ah[mt][0] = *(const uint32_t*)&sAhi[base];
                ah[mt][1] = *(const uint32_t*)&sAhi[base + 8 * ASTR];
                ah[mt][2] = *(const uint32_t*)&sAhi[base + 8];
                ah[mt][3] = *(const uint32_t*)&sAhi[base + 8 * ASTR + 8];
                al[mt][0] = *(const uint32_t*)&sAlo[base];
                al[mt][1] = *(const uint32_t*)&sAlo[base + 8 * ASTR];
                al[mt][2] = *(const uint32_t*)&sAlo[base + 8];
                al[mt][3] = *(const uint32_t*)&sAlo[base + 8 * ASTR + 8];
            }
            uint32_t bh[4][2], bl[4][2];
#pragma unroll
            for (int nt = 0; nt < 4; nt++) {
                int base = (warp_n * 32 + nt * 8 + g) * ASTR + kc + tg * 2;
                bh[nt][0] = *(const uint32_t*)&sBhi[base];
                bh[nt][1] = *(const uint32_t*)&sBhi[base + 8];
                bl[nt][0] = *(const uint32_t*)&sBlo[base];
                bl[nt][1] = *(const uint32_t*)&sBlo[base + 8];
            }
#pragma unroll
            for (int mt = 0; mt < 4; mt++)
#pragma unroll
                for (int nt = 0; nt < 4; nt++) {
                    mma_bf16(acc[mt][nt], ah[mt], bh[nt]);
                    mma_bf16(acc[mt][nt], ah[mt], bl[nt]);
                    mma_bf16(acc[mt][nt], al[mt], bh[nt]);
                }
        }
    };

    const int T = K / 32;
    load_tiles(0);
    store_tiles(0);
    __syncthreads();
    for (int t = 1; t < T; t++) {
        load_tiles(t * 32);
        compute((t - 1) & 1);
        store_tiles(t & 1);
        __syncthreads();
    }
    compute((T - 1) & 1);

    // epilogue
#pragma unroll
    for (int mt = 0; mt < 4; mt++) {
        int r0 = m0 + warp_m * 64 + mt * 16 + g;
#pragma unroll
        for (int nt = 0; nt < 4; nt++) {
            int gc = n0 + warp_n * 32 + nt * 8 + tg * 2;
            float2 v01 = make_float2(acc[mt][nt][0], acc[mt][nt][1]);
            float2 v23 = make_float2(acc[mt][nt][2], acc[mt][nt][3]);
            if (bias) {
                float2 b = *(const float2*)&bias[gc];
                v01.x += b.x; v01.y += b.y;
                v23.x += b.x; v23.y += b.y;
            }
            if (EPI == 1) {
                v01.x = fmaxf(v01.x, 0.f); v01.y = fmaxf(v01.y, 0.f);
                v23.x = fmaxf(v23.x, 0.f); v23.y = fmaxf(v23.y, 0.f);
            }
            if (r0 < M) {
                if (EPI == 2) {
                    float2 adx = *(const float2*)&addend[(size_t)r0 * ldadd + gc];
                    v01.x += adx.x; v01.y += adx.y;
                }
                *(float2*)&C[(size_t)r0 * ldc + gc] = v01;
            }
            if (r0 + 8 < M) {
                if (EPI == 2) {
                    float2 adx = *(const float2*)&addend[(size_t)(r0 + 8) * ldadd + gc];
                    v23.x += adx.x; v23.y += adx.y;
                }
                *(float2*)&C[(size_t)(r0 + 8) * ldc + gc] = v23;
            }
        }
    }
}

// ---------------- fp32 SGEMM (small evidence-2 GEMM only) ----------------
#define BM 128
#define BN 128
#define BKK 16
template <int EPI>
__global__ __launch_bounds__(256, 2)
void k_sgemm(const float* __restrict__ A, int lda,
             const float* __restrict__ B, int ldb,
             float* __restrict__ C, int ldc,
             const float* __restrict__ bias,
             int M, int N, int K)
{
    __shared__ float As[BKK][BM + 4];
    __shared__ float Bs[BKK][BN];
    const int tid = threadIdx.x;
    const int m0 = blockIdx.y * BM;
    const int n0 = blockIdx.x * BN;
    const int tm = tid >> 4, tn = tid & 15;
    const int a_kk = tid & 15, a_m0 = tid >> 4;
    const int b_kk0 = tid >> 5, b_nb = (tid & 31) << 2;

    float acc[8][8];
#pragma unroll
    for (int i = 0; i < 8; i++)
#pragma unroll
        for (int j = 0; j < 8; j++) acc[i][j] = 0.f;

    float ra[8]; float4 rb[2];
    auto load_tiles = [&](int k0) {
#pragma unroll
        for (int i = 0; i < 8; i++) {
            int gm = m0 + a_m0 + 16 * i;
            ra[i] = (gm < M) ? A[(size_t)gm * lda + (k0 + a_kk)] : 0.f;
        }
#pragma unroll
        for (int i = 0; i < 2; i++) {
            int kk = b_kk0 + 8 * i;
            int gn = n0 + b_nb;
            float4 v = make_float4(0.f, 0.f, 0.f, 0.f);
            const float* bp = &B[(size_t)(k0 + kk) * ldb + b_nb];
            if (gn + 3 < N) v = *(const float4*)bp;
            else {
                if (gn     < N) v.x = bp[0];
                if (gn + 1 < N) v.y = bp[1];
                if (gn + 2 < N) v.z = bp[2];
            }
            rb[i] = v;
        }
    };
    auto store_tiles = [&]() {
#pragma unroll
        for (int i = 0; i < 8; i++) As[a_kk][a_m0 + 16 * i] = ra[i];
#pragma unroll
        for (int i = 0; i < 2; i++) *(float4*)&Bs[b_kk0 + 8 * i][b_nb] = rb[i];
    };
    auto compute = [&]() {
#pragma unroll
        for (int kk = 0; kk < BKK; kk++) {
            float a[8], b[8];
#pragma unroll
            for (int i = 0; i < 8; i++) a[i] = As[kk][tm * 8 + i];
#pragma unroll
            for (int j = 0; j < 8; j++) b[j] = Bs[kk][tn * 8 + j];
#pragma unroll
            for (int i = 0; i < 8; i++)
#pragma unroll
                for (int j = 0; j < 8; j++) acc[i][j] = fmaf(a[i], b[j], acc[i][j]);
        }
    };
    load_tiles(0); store_tiles(); __syncthreads();
    for (int k0 = BKK; k0 < K; k0 += BKK) {
        load_tiles(k0); compute(); __syncthreads(); store_tiles(); __syncthreads();
    }
    compute();
#pragma unroll
    for (int i = 0; i < 8; i++) {
        int gm = m0 + tm * 8 + i;
        if (gm < M) {
#pragma unroll
            for (int j = 0; j < 8; j++) {
                int gn = n0 + tn * 8 + j;
                if (gn < N) {
                    float v = acc[i][j];
                    if (bias) v += bias[gn];
                    if (EPI == 1) v = fmaxf(v, 0.f);
                    C[(size_t)gm * ldc + gn] = v;
                }
            }
        }
    }
}

// ---------------- attention projections + node maxima (interleaved [node][head]) ----------------
__global__ void k_s1s2(const float* __restrict__ Wh, int ld, int F, int nh,
                       const float* __restrict__ a, int aStride,
                       float* __restrict__ s1, float* __restrict__ s2, int N,
                       int slot1, int slot2)
{
    int gw = (blockIdx.x * blockDim.x + threadIdx.x) >> 5;
    int lane = threadIdx.x & 31;
    if (gw >= N * nh) return;
    int node = gw / nh;
    int h = gw - node * nh;
    const float* wr = &Wh[(size_t)node * ld + h * F];
    const float* ah = &a[(size_t)h * aStride];
    float p1 = 0.f, p2 = 0.f;
    for (int j = lane; j < F; j += 32) {
        float x = wr[j];
        p1 = fmaf(x, ah[j], p1);
        p2 = fmaf(x, ah[F + j], p2);
    }
    p1 = wsumf(p1); p2 = wsumf(p2);
    if (lane == 0) {
        s1[(size_t)node * nh + h] = p1;
        s2[(size_t)node * nh + h] = p2;
        atomicMax(&g_maxenc[slot1 + h], fenc(p1));
        atomicMax(&g_maxenc[slot2 + h], fenc(p2));
    }
}

// ---------------- edge pass: w = exp(lrelu(s1[src]+s2[tgt]) - M); M inline; block-sum ----------------
template <int NH>
__global__ void k_expsum(const int* __restrict__ src, const int* __restrict__ tgt,
                         const float* __restrict__ s1, const float* __restrict__ s2,
                         float* __restrict__ w, int E, int sumslot, int m1, int m2)
{
    int e = blockIdx.x * blockDim.x + threadIdx.x;
    int tid = threadIdx.x;
    bool ok = (e < E);
    float Mh[NH];
#pragma unroll
    for (int h = 0; h < NH; h++) {
        float l = fdec(g_maxenc[m1 + h]) + fdec(g_maxenc[m2 + h]);
        Mh[h] = (l > 0.f) ? l : 0.2f * l;
    }
    float sv[NH];
    if (NH == 4) {
        float4 a = make_float4(0.f, 0.f, 0.f, 0.f), b = a;
        if (ok) {
            int s = src[e], t = tgt[e];
            a = *(const float4*)&s1[(size_t)s * 4];
            b = *(const float4*)&s2[(size_t)t * 4];
        }
        float lv[4] = { a.x + b.x, a.y + b.y, a.z + b.z, a.w + b.w };
#pragma unroll
        for (int h = 0; h < 4; h++) {
            float l = lv[h];
            l = (l > 0.f) ? l : 0.2f * l;
            float v = ok ? expf(l - Mh[h]) : 0.f;
            if (ok) w[(size_t)h * E + e] = v;
            sv[h] = v;
        }
    } else {
        float v = 0.f;
        if (ok) {
            int s = src[e], t = tgt[e];
            float l = s1[s] + s2[t];
            l = (l > 0.f) ? l : 0.2f * l;
            v = expf(l - Mh[0]);
            w[e] = v;
        }
        sv[0] = v;
    }
    __shared__ float red[NH * 8];
    int wi = tid >> 5, lane = tid & 31;
#pragma unroll
    for (int h = 0; h < NH; h++) {
        float v = wsumf(sv[h]);
        if (lane == 0) red[h * 8 + wi] = v;
    }
    __syncthreads();
    if (tid < 32) {
        float v = (tid < NH * 8) ? red[tid] : 0.f;
        v += __shfl_down_sync(0xffffffffu, v, 4);
        v += __shfl_down_sync(0xffffffffu, v, 2);
        v += __shfl_down_sync(0xffffffffu, v, 1);
        if ((tid & 7) == 0 && tid < NH * 8)
            atomicAdd(&g_sumexp[sumslot + (tid >> 3)], (double)v);
    }
}

__global__ void k_finalize(int slot0, int n)
{
    int i = threadIdx.x;
    if (i < n) g_invS[slot0 + i] = (float)(1.0 / g_sumexp[slot0 + i]);
}

// ---------------- CSR gather ----------------
__global__ __launch_bounds__(256, 8)
void k_gather1024(const int* __restrict__ src, const float* __restrict__ w,
                  const float* __restrict__ Wh, float* __restrict__ xnew, int slot0)
{
    int node = blockIdx.x;
    int tid = threadIdx.x;
    int head = tid >> 6;
    int col = tid * 4;
    const float* wh = &w[(size_t)head * EE];

    int p = g_rowptr[node];
    const int end = g_rowptr[node + 1];

    int s_cur = 0; float c_cur = 0.f;
    if (p < end) { int e = g_eidx[p]; s_cur = src[e]; c_cur = wh[e]; }

    float4 acc = make_float4(0.f, 0.f, 0.f, 0.f);
    while (p < end) {
        int s_nxt = 0; float c_nxt = 0.f;
        if (p + 1 < end) { int e = g_eidx[p + 1]; s_nxt = src[e]; c_nxt = wh[e]; }
        float4 v = *(const float4*)&Wh[(size_t)s_cur * 1024 + col];
        acc.x = fmaf(c_cur, v.x, acc.x);
        acc.y = fmaf(c_cur, v.y, acc.y);
        acc.z = fmaf(c_cur, v.z, acc.z);
        acc.w = fmaf(c_cur, v.w, acc.w);
        s_cur = s_nxt; c_cur = c_nxt; p++;
    }
    float inv = g_invS[slot0 + head];
    acc.x *= inv; acc.y *= inv; acc.z *= inv; acc.w *= inv;
    *(float4*)&xnew[(size_t)node * 1024 + col] = acc;
}

__global__ __launch_bounds__(256, 8)
void k_gather128(const int* __restrict__ src, const float* __restrict__ w,
                 const float* __restrict__ Wh, float* __restrict__ xnew, int slot)
{
    int node = (blockIdx.x * blockDim.x + threadIdx.x) >> 5;
    int lane = threadIdx.x & 31;
    if (node >= NN) return;
    int col = lane * 4;

    int p = g_rowptr[node];
    const int end = g_rowptr[node + 1];

    int s_cur = 0; float c_cur = 0.f;
    if (p < end) { int e = g_eidx[p]; s_cur = src[e]; c_cur = w[e]; }

    float4 acc = make_float4(0.f, 0.f, 0.f, 0.f);
    while (p < end) {
        int s_nxt = 0; float c_nxt = 0.f;
        if (p + 1 < end) { int e = g_eidx[p + 1]; s_nxt = src[e]; c_nxt = w[e]; }
        float4 v = *(const float4*)&Wh[(size_t)s_cur * 128 + col];
        acc.x = fmaf(c_cur, v.x, acc.x);
        acc.y = fmaf(c_cur, v.y, acc.y);
        acc.z = fmaf(c_cur, v.z, acc.z);
        acc.w = fmaf(c_cur, v.w, acc.w);
        s_cur = s_nxt; c_cur = c_nxt; p++;
    }
    float inv = g_invS[slot];
    acc.x *= inv; acc.y *= inv; acc.z *= inv; acc.w *= inv;
    *(float4*)&xnew[(size_t)node * 128 + col] = acc;
}

// ---------------- evidence heads ----------------
__global__ void k_evid1(const float* __restrict__ hbuf, const float* __restrict__ w2,
                        const float* __restrict__ b2, float* __restrict__ evsum, int N)
{
    int gw = (blockIdx.x * blockDim.x + threadIdx.x) >> 5;
    int lane = threadIdx.x & 31;
    if (gw >= N) return;
    float e0 = 0.f, e1 = 0.f, e2 = 0.f;
#pragma unroll
    for (int h = 0; h < NHEAD; h++) {
        float4 v = *(const float4*)&hbuf[(size_t)gw * 512 + h * 128 + lane * 4];
        const float* wc = &w2[h * 384 + lane * 12];
        float a0 = v.x * wc[0] + v.y * wc[3] + v.z * wc[6] + v.w * wc[9];
        float a1 = v.x * wc[1] + v.y * wc[4] + v.z * wc[7] + v.w * wc[10];
        float a2 = v.x * wc[2] + v.y * wc[5] + v.z * wc[8] + v.w * wc[11];
        a0 = wsumf(a0); a1 = wsumf(a1); a2 = wsumf(a2);
        e0 += softplusf(a0 + b2[h * 3 + 0]) + 1.f;
        e1 += softplusf(a1 + b2[h * 3 + 1]) + 1.f;
        e2 += softplusf(a2 + b2[h * 3 + 2]) + 1.f;
    }
    if (lane == 0) {
        evsum[gw * 3 + 0] = e0; evsum[gw * 3 + 1] = e1; evsum[gw * 3 + 2] = e2;
    }
}

__global__ void k_evid2(const float* __restrict__ hbuf, const float* __restrict__ w2,
                        const float* __restrict__ b2, const float* __restrict__ evsum,
                        float* __restrict__ out, int N)
{
    int gw = (blockIdx.x * blockDim.x + threadIdx.x) >> 5;
    int lane = threadIdx.x & 31;
    if (gw >= N) return;
    float2 v = *(const float2*)&hbuf[(size_t)gw * 64 + lane * 2];
    const float* wc = &w2[lane * 6];
    float a0 = v.x * wc[0] + v.y * wc[3];
    float a1 = v.x * wc[1] + v.y * wc[4];
    float a2 = v.x * wc[2] + v.y * wc[5];
    a0 = wsumf(a0); a1 = wsumf(a1); a2 = wsumf(a2);
    if (lane == 0) {
        float e0 = softplusf(a0 + b2[0]) + 1.f;
        float e1 = softplusf(a1 + b2[1]) + 1.f;
        float e2 = softplusf(a2 + b2[2]) + 1.f;
        out[(size_t)gw * 3 + 0] = (evsum[gw * 3 + 0] * 0.25f + e0) * 0.5f;
        out[(size_t)gw * 3 + 1] = (evsum[gw * 3 + 1] * 0.25f + e1) * 0.5f;
        out[(size_t)gw * 3 + 2] = (evsum[gw * 3 + 2] * 0.25f + e2) * 0.5f;
    }
}

// ---------------- LayerNorm + ELU ----------------
template <int F>
__global__ void k_ln_elu(const float* __restrict__ in, float* __restrict__ out,
                         const float* __restrict__ gam, const float* __restrict__ bet, int N)
{
    int gw = (blockIdx.x * blockDim.x + threadIdx.x) >> 5;
    int lane = threadIdx.x & 31;
    if (gw >= N) return;
    constexpr int R = F / 32;
    float v[R];
    const float* ir = &in[(size_t)gw * F];
#pragma unroll
    for (int r = 0; r < R; r++) v[r] = ir[lane + 32 * r];
    float s = 0.f;
#pragma unroll
    for (int r = 0; r < R; r++) s += v[r];
    s = wsumf(s);
    float mean = s * (1.f / F);
    float q = 0.f;
#pragma unroll
    for (int r = 0; r < R; r++) { float d = v[r] - mean; q = fmaf(d, d, q); }
    q = wsumf(q);
    float rstd = rsqrtf(q * (1.f / F) + 1e-5f);
    float* orow = &out[(size_t)gw * F];
#pragma unroll
    for (int r = 0; r < R; r++) {
        int j = lane + 32 * r;
        float y = (v[r] - mean) * rstd * gam[j] + bet[j];
        orow[j] = eluf(y);
    }
}

// ---------------- launch ----------------
extern "C" void kernel_launch(void* const* d_in, const int* in_sizes, int n_in,
                              void* d_out, int out_size)
{
    (void)in_sizes; (void)n_in; (void)out_size;

    const float* x        = (const float*)d_in[0];
    const int*   ei       = (const int*)  d_in[1];
    const float* W_heads  = (const float*)d_in[2];
    const float* a_heads  = (const float*)d_in[3];
    const float* ev1w_h   = (const float*)d_in[4];
    const float* ev1b_h   = (const float*)d_in[5];
    const float* ev2w_h   = (const float*)d_in[6];
    const float* ev2b_h   = (const float*)d_in[7];
    const float* agg_w    = (const float*)d_in[8];
    const float* agg_b    = (const float*)d_in[9];
    const float* ln1_g    = (const float*)d_in[10];
    const float* ln1_b    = (const float*)d_in[11];
    const float* W2       = (const float*)d_in[12];
    const float* a2       = (const float*)d_in[13];
    const float* ev1w2    = (const float*)d_in[14];
    const float* ev1b2    = (const float*)d_in[15];
    const float* ev2w2    = (const float*)d_in[16];
    const float* ev2b2    = (const float*)d_in[17];
    const float* ln2_g    = (const float*)d_in[18];
    const float* ln2_b    = (const float*)d_in[19];
    const float* res_w    = (const float*)d_in[20];
    const float* res_b    = (const float*)d_in[21];

    const int* src = ei;
    const int* tgt = ei + EE;

    float* out_x  = (float*)d_out;
    float* out_ev = (float*)d_out + (size_t)NN * DOUT;

    float *Wh, *xnew, *s1, *s2, *wbuf, *w2e, *hbuf, *evsum, *h1, *Wh2, *s1b, *s2b, *xnew2, *x2;
    __nv_bfloat16 *bt1hi, *bt1lo, *btahi, *btalo, *btehi, *btelo, *btw2hi, *btw2lo, *btrhi, *btrlo;
    cudaGetSymbolAddress((void**)&Wh,    g_Wh);
    cudaGetSymbolAddress((void**)&xnew,  g_xnew);
    cudaGetSymbolAddress((void**)&s1,    g_s1);
    cudaGetSymbolAddress((void**)&s2,    g_s2);
    cudaGetSymbolAddress((void**)&wbuf,  g_w);
    cudaGetSymbolAddress((void**)&w2e,   g_w2e);
    cudaGetSymbolAddress((void**)&hbuf,  g_hbuf);
    cudaGetSymbolAddress((void**)&evsum, g_evsum);
    cudaGetSymbolAddress((void**)&h1,    g_h1);
    cudaGetSymbolAddress((void**)&Wh2,   g_Wh2);
    cudaGetSymbolAddress((void**)&s1b,   g_s1b);
    cudaGetSymbolAddress((void**)&s2b,   g_s2b);
    cudaGetSymbolAddress((void**)&xnew2, g_xnew2);
    cudaGetSymbolAddress((void**)&x2,    g_x2);
    cudaGetSymbolAddress((void**)&bt1hi, g_bt1hi);
    cudaGetSymbolAddress((void**)&bt1lo, g_bt1lo);
    cudaGetSymbolAddress((void**)&btahi, g_btahi);
    cudaGetSymbolAddress((void**)&btalo, g_btalo);
    cudaGetSymbolAddress((void**)&btehi, g_btehi);
    cudaGetSymbolAddress((void**)&btelo, g_btelo);
    cudaGetSymbolAddress((void**)&btw2hi, g_btw2hi);
    cudaGetSymbolAddress((void**)&btw2lo, g_btw2lo);
    cudaGetSymbolAddress((void**)&btrhi, g_btrhi);
    cudaGetSymbolAddress((void**)&btrlo, g_btrlo);

    cudaFuncSetAttribute(k_mma<0>, cudaFuncAttributeMaxDynamicSharedMemorySize, MMA_SMEM);
    cudaFuncSetAttribute(k_mma<1>, cudaFuncAttributeMaxDynamicSharedMemorySize, MMA_SMEM);
    cudaFuncSetAttribute(k_mma<2>, cudaFuncAttributeMaxDynamicSharedMemorySize, MMA_SMEM);

    const int MB = (NN + 127) / 128;   // 235

    // prep: fused weight transpose + init tail; CSR build
    k_btall<<<BT_BLOCKS + INIT_BLOCKS, 256>>>(W_heads, agg_w, ev1w_h, W2, res_w);
    k_hist<<<(EE + 255) / 256, 256>>>(tgt);
    k_scan<<<1, 1024>>>();
    k_fill<<<(EE + 255) / 256, 256>>>(tgt);

    // Wh = x @ W_heads
    k_mma<0><<<dim3(8, MB), 256, MMA_SMEM>>>(x, DIN, 0, 128, bt1hi, bt1lo,
                                             Wh, 1024, nullptr, nullptr, 0, NN, DIN);

    // attention scalars + maxima, edge pass (M inline), softmax scale
    k_s1s2<<<(NN * NHEAD) / 8, 256>>>(Wh, NHEAD * DH, DH, NHEAD, a_heads, 2 * DH, s1, s2, NN, 0, 4);
    k_expsum<NHEAD><<<(EE + 255) / 256, 256>>>(src, tgt, s1, s2, wbuf, EE, 0, 0, 4);
    k_finalize<<<1, 8>>>(0, NHEAD);

    // CSR gather (all heads)
    k_gather1024<<<NN, 256>>>(src, wbuf, Wh, xnew, 0);

    // evidence layer 1 (block-diagonal, relu) + fused head
    k_mma<1><<<dim3(4, MB), 256, MMA_SMEM>>>(xnew, NHEAD * DH, DH, 128, btehi, btelo,
                                             hbuf, 512, ev1b_h, nullptr, 0, NN, DH);
    k_evid1<<<NN / 8, 256>>>(hbuf, ev2w_h, ev2b_h, evsum, NN);

    // h1 = elu(LN(x_cat @ agg_w + agg_b))
    k_mma<0><<<dim3(2, MB), 256, MMA_SMEM>>>(xnew, NHEAD * DH, 0, 128, btahi, btalo,
                                             h1, DH, agg_b, nullptr, 0, NN, NHEAD * DH);
    k_ln_elu<DH><<<NN / 8, 256>>>(h1, h1, ln1_g, ln1_b, NN);

    // layer-2 GAT
    k_mma<0><<<dim3(1, MB), 256, MMA_SMEM>>>(h1, DH, 0, 128, btw2hi, btw2lo,
                                             Wh2, DOUT, nullptr, nullptr, 0, NN, DH);
    k_s1s2<<<NN / 8, 256>>>(Wh2, DOUT, DOUT, 1, a2, 2 * DOUT, s1b, s2b, NN, 8, 9);
    k_expsum<1><<<(EE + 255) / 256, 256>>>(src, tgt, s1b, s2b, w2e, EE, 4, 8, 9);
    k_finalize<<<1, 8>>>(4, 1);
    k_gather128<<<(NN * 32 + 255) / 256, 256>>>(src, w2e, Wh2, xnew2, 4);

    // evidence layer 2 + final combine
    k_sgemm<1><<<dim3(1, MB), 256>>>(xnew2, DOUT, ev1w2, DOUT / 2, hbuf, DOUT / 2,
                                     ev1b2, NN, DOUT / 2, DOUT);
    k_evid2<<<NN / 8, 256>>>(hbuf, ev2w2, ev2b2, evsum, out_ev, NN);

    // x2 = elu(LN(x_new2)); x_out = x2 + h1 @ res_w + res_b
    k_ln_elu<DOUT><<<NN / 8, 256>>>(xnew2, x2, ln2_g, ln2_b, NN);
    k_mma<2><<<dim3(1, MB), 256, MMA_SMEM>>>(h1, DH, 0, 128, btrhi, btrlo,
                                             out_x, DOUT, res_b, x2, DOUT, NN, DH);
}

// round 15
// speedup vs baseline: 1.1572x; 1.1099x over previous
#include <cuda_runtime.h>
#include <cuda_bf16.h>
#include <math.h>
#include <stdint.h>

// ---------------- problem constants ----------------
#define NN   30000
#define EE   480000
#define DIN  768
#define DH   256    // HID
#define DOUT 128    // OUT
#define NHEAD 4
#define NCLS 3

// ---------------- scratch (static device memory; no allocations) ----------------
__device__ float    g_Wh   [(size_t)NN * (NHEAD * DH)];
__device__ float    g_xnew [(size_t)NN * (NHEAD * DH)];
__device__ __align__(16) float g_s1 [NHEAD * NN];   // interleaved [node][head]
__device__ __align__(16) float g_s2 [NHEAD * NN];
__device__ float    g_w    [(size_t)NHEAD * EE];
__device__ float    g_w2e  [EE];
__device__ float    g_hbuf [(size_t)NN * 512];
__device__ float    g_evsum[NN * NCLS];
__device__ float    g_h1   [(size_t)NN * DH];
__device__ float    g_Wh2  [(size_t)NN * DOUT];
__device__ float    g_s1b  [NN];
__device__ float    g_s2b  [NN];
__device__ float    g_xnew2[(size_t)NN * DOUT];
__device__ float    g_x2   [(size_t)NN * DOUT];
__device__ unsigned g_maxenc[12];
__device__ double   g_sumexp[8];
__device__ float    g_invS  [8];

// CSR (edges grouped by tgt)
__device__ int g_rowptr[NN + 1];
__device__ int g_cursor[NN];
__device__ int g_eidx  [EE];

// transposed + bf16-split weights (Bt[n][k], K-major)
__device__ __align__(256) __nv_bfloat16 g_bt1hi [1024 * 768], g_bt1lo [1024 * 768];
__device__ __align__(256) __nv_bfloat16 g_btahi [256 * 1024], g_btalo [256 * 1024];
__device__ __align__(256) __nv_bfloat16 g_btehi [512 * 256],  g_btelo [512 * 256];
__device__ __align__(256) __nv_bfloat16 g_btw2hi[128 * 256],  g_btw2lo[128 * 256];
__device__ __align__(256) __nv_bfloat16 g_btrhi [128 * 256],  g_btrlo [128 * 256];

// ---------------- helpers ----------------
__device__ __forceinline__ unsigned fenc(float f) {
    unsigned u = __float_as_uint(f);
    return (u & 0x80000000u) ? ~u : (u | 0x80000000u);
}
__device__ __forceinline__ float fdec(unsigned u) {
    return (u & 0x80000000u) ? __uint_as_float(u & 0x7fffffffu) : __uint_as_float(~u);
}
__device__ __forceinline__ float wsumf(float v) {
#pragma unroll
    for (int o = 16; o > 0; o >>= 1) v += __shfl_xor_sync(0xffffffffu, v, o);
    return v;
}
__device__ __forceinline__ float wmaxf(float v) {
#pragma unroll
    for (int o = 16; o > 0; o >>= 1) v = fmaxf(v, __shfl_xor_sync(0xffffffffu, v, o));
    return v;
}
__device__ __forceinline__ float softplusf(float x) {
    return fmaxf(x, 0.f) + log1pf(expf(-fabsf(x)));
}
__device__ __forceinline__ float eluf(float x) {
    return x > 0.f ? x : expm1f(x);
}
__device__ __forceinline__ void bf16split(float x, __nv_bfloat16& hi, __nv_bfloat16& lo) {
    hi = __float2bfloat16(x);
    lo = __float2bfloat16(x - __bfloat162float(hi));
}

// mma.sync m16n8k16 bf16 (row.col), fp32 accumulate — compiles on plain sm_103.
__device__ __forceinline__ void mma_bf16(float* c, const uint32_t* a, const uint32_t* b) {
    asm volatile(
        "mma.sync.aligned.m16n8k16.row.col.f32.bf16.bf16.f32 "
        "{%0,%1,%2,%3}, {%4,%5,%6,%7}, {%8,%9}, {%0,%1,%2,%3};"
        : "+f"(c[0]), "+f"(c[1]), "+f"(c[2]), "+f"(c[3])
        : "r"(a[0]), "r"(a[1]), "r"(a[2]), "r"(a[3]), "r"(b[0]), "r"(b[1]));
}

// ---------------- fused: B transpose/split for 5 weight tensors + init tail ----------------
// blocks [0,4864): weight transposes
// [4864, 4982): zero rowptr; [4982, 5451): zero s1; [5451, 5920): zero s2
#define BT_BLOCKS 4864
#define INIT_BLOCKS 1056
__global__ void k_btall(const float* w1, const float* wa, const float* we,
                        const float* w2, const float* wr)
{
    int b = blockIdx.x;
    if (b >= BT_BLOCKS) {
        int ib = b - BT_BLOCKS;
        if (ib < 118) {
            int i = ib * 256 + threadIdx.x;
            if (i <= NN) g_rowptr[i] = 0;
            if (ib == 0) {
                if (threadIdx.x < 12) g_maxenc[threadIdx.x] = 0u;
                if (threadIdx.x < 8)  { g_sumexp[threadIdx.x] = 0.0; g_invS[threadIdx.x] = 0.f; }
            }
        } else if (ib < 587) {
            int i = (ib - 118) * 256 + threadIdx.x;
            if (i < NHEAD * NN) g_s1[i] = 0.f;
        } else {
            int i = (ib - 587) * 256 + threadIdx.x;
            if (i < NHEAD * NN) g_s2[i] = 0.f;
        }
        return;
    }
    const float* src; __nv_bfloat16 *hi, *lo;
    int K, headN, headStride, base;
    if (b < 3072)      { src = w1; hi = g_bt1hi;  lo = g_bt1lo;  K = 768;  headN = 256; headStride = 768 * 256; base = 0; }
    else if (b < 4096) { src = wa; hi = g_btahi;  lo = g_btalo;  K = 1024; headN = 256; headStride = 0;         base = 3072; }
    else if (b < 4608) { src = we; hi = g_btehi;  lo = g_btelo;  K = 256;  headN = 128; headStride = 256 * 128; base = 4096; }
    else if (b < 4736) { src = w2; hi = g_btw2hi; lo = g_btw2lo; K = 256;  headN = 128; headStride = 0;         base = 4608; }
    else               { src = wr; hi = g_btrhi;  lo = g_btrlo;  K = 256;  headN = 128; headStride = 0;         base = 4736; }
    int idx = (b - base) * 256 + threadIdx.x;
    int n = idx / K, k = idx - n * K;
    int head = n / headN, nloc = n - head * headN;
    float v = src[(size_t)head * headStride + (size_t)k * headN + nloc];
    __nv_bfloat16 h, l;
    bf16split(v, h, l);
    hi[idx] = h;
    lo[idx] = l;
}

// ---------------- CSR build ----------------
__global__ void k_hist(const int* __restrict__ tgt) {
    int e = blockIdx.x * blockDim.x + threadIdx.x;
    if (e < EE) atomicAdd(&g_rowptr[tgt[e] + 1], 1);
}

__global__ void k_scan() {
    __shared__ int warp_tot[32];
    int tid = threadIdx.x;
    int lane = tid & 31, wi = tid >> 5;
    const int CH = (NN + 1023) / 1024;
    int beg = tid * CH;
    int end = beg + CH; if (end > NN) end = NN;
    int s = 0;
    for (int i = beg; i < end; i++) s += g_rowptr[i + 1];
    int v = s;
#pragma unroll
    for (int o = 1; o < 32; o <<= 1) {
        int u = __shfl_up_sync(0xffffffffu, v, o);
        if (lane >= o) v += u;
    }
    if (lane == 31) warp_tot[wi] = v;
    __syncthreads();
    if (wi == 0) {
        int w = warp_tot[lane];
#pragma unroll
        for (int o = 1; o < 32; o <<= 1) {
            int u = __shfl_up_sync(0xffffffffu, w, o);
            if (lane >= o) w += u;
        }
        warp_tot[lane] = w;
    }
    __syncthreads();
    int run = v - s + (wi > 0 ? warp_tot[wi - 1] : 0);
    for (int i = beg; i < end; i++) {
        int c = g_rowptr[i + 1];
        g_cursor[i] = run;
        run += c;
        g_rowptr[i + 1] = run;
    }
    if (tid == 0) g_rowptr[0] = 0;
}

__global__ void k_fill(const int* __restrict__ tgt) {
    int e = blockIdx.x * blockDim.x + threadIdx.x;
    if (e < EE) {
        int p = atomicAdd(&g_cursor[tgt[e]], 1);
        g_eidx[p] = e;
    }
}

// ---------------- bf16-split tensor-core GEMM, double-buffered ----------------
// EPI: 0 = (+bias); 1 = relu(+bias); 2 = +bias +addend; 3 = store + fused s1/s2 projections.
#define ASTR 40
#define TILE_B 10240
#define BUF_B  (4 * TILE_B)
#define MMA_SMEM (2 * BUF_B)

template <int EPI>
__global__ __launch_bounds__(256, 1)
void k_mma(const float* __restrict__ A, int lda, int aHeadStep, int headN,
           const __nv_bfloat16* __restrict__ Bthi, const __nv_bfloat16* __restrict__ Btlo,
           float* __restrict__ C, int ldc,
           const float* __restrict__ bias,
           const float* __restrict__ addend, int ldadd,
           int M, int K,
           float* __restrict__ s1o, float* __restrict__ s2o,
           const float* __restrict__ attA)
{
    extern __shared__ __align__(16) char smraw[];

    const int tid = threadIdx.x;
    const int lane = tid & 31;
    const int wid = tid >> 5;
    const int warp_m = wid & 1;
    const int warp_n = wid >> 1;
    const int g  = lane >> 2;
    const int tg = lane & 3;

    const int m0 = blockIdx.y * 128;
    const int n0 = blockIdx.x * 128;
    const float* __restrict__ Ap = A + (size_t)(n0 / headN) * aHeadStep;

    float acc[4][4][4];
#pragma unroll
    for (int i = 0; i < 4; i++)
#pragma unroll
        for (int j = 0; j < 4; j++)
#pragma unroll
            for (int k = 0; k < 4; k++) acc[i][j][k] = 0.f;

    float4 ra[4];
    uint4  rbh[2], rbl[2];

    auto load_tiles = [&](int k0) {
#pragma unroll
        for (int i = 0; i < 4; i++) {
            int idx = tid + 256 * i;
            int row = idx >> 3, c4 = (idx & 7) << 2;
            int gm = m0 + row;
            ra[i] = (gm < M) ? *(const float4*)&Ap[(size_t)gm * lda + k0 + c4]
                             : make_float4(0.f, 0.f, 0.f, 0.f);
        }
#pragma unroll
        for (int i = 0; i < 2; i++) {
            int idx = tid + 256 * i;
            int row = idx >> 2, c8 = (idx & 3) << 3;
            size_t gi = (size_t)(n0 + row) * K + k0 + c8;
            rbh[i] = *(const uint4*)&Bthi[gi];
            rbl[i] = *(const uint4*)&Btlo[gi];
        }
    };
    auto store_tiles = [&](int s) {
        __nv_bfloat16* sAhi = (__nv_bfloat16*)(smraw + s * BUF_B);
        __nv_bfloat16* sAlo = (__nv_bfloat16*)(smraw + s * BUF_B + TILE_B);
        __nv_bfloat16* sBhi = (__nv_bfloat16*)(smraw + s * BUF_B + 2 * TILE_B);
        __nv_bfloat16* sBlo = (__nv_bfloat16*)(smraw + s * BUF_B + 3 * TILE_B);
#pragma unroll
        for (int i = 0; i < 4; i++) {
            int idx = tid + 256 * i;
            int row = idx >> 3, c4 = (idx & 7) << 2;
            __nv_bfloat16 hx, lx, hy, ly, hz, lz, hw, lw;
            bf16split(ra[i].x, hx, lx); bf16split(ra[i].y, hy, ly);
            bf16split(ra[i].z, hz, lz); bf16split(ra[i].w, hw, lw);
            int o = row * ASTR + c4;
            *(__nv_bfloat162*)&sAhi[o]     = __nv_bfloat162(hx, hy);
            *(__nv_bfloat162*)&sAhi[o + 2] = __nv_bfloat162(hz, hw);
            *(__nv_bfloat162*)&sAlo[o]     = __nv_bfloat162(lx, ly);
            *(__nv_bfloat162*)&sAlo[o + 2] = __nv_bfloat162(lz, lw);
        }
#pragma unroll
        for (int i = 0; i < 2; i++) {
            int idx = tid + 256 * i;
            int row = idx >> 2, c8 = (idx & 3) << 3;
            *(uint4*)&sBhi[row * ASTR + c8] = rbh[i];
            *(uint4*)&sBlo[row * ASTR + c8] = rbl[i];
        }
    };
    auto compute = [&](int s) {
        const __nv_bfloat16* sAhi = (const __nv_bfloat16*)(smraw + s * BUF_B);
        const __nv_bfloat16* sAlo = (const __nv_bfloat16*)(smraw + s * BUF_B + TILE_B);
        const __nv_bfloat16* sBhi = (const __nv_bfloat16*)(smraw + s * BUF_B + 2 * TILE_B);
        const __nv_bfloat16* sBlo = (const __nv_bfloat16*)(smraw + s * BUF_B + 3 * TILE_B);
#pragma unroll
        for (int kc = 0; kc < 32; kc += 16) {
            uint32_t ah[4][4], al[4][4];
#pragma unroll
            for (int mt = 0; mt < 4; mt++) {
                int base = (warp_m * 64 + mt * 16 + g) * ASTR + kc + tg * 2;
                ah[mt][0] = *(const uint32_t*)&sAhi[base];
                ah[mt][1] = *(const uint32_t*)&sAhi[base + 8 * ASTR];
                ah[mt][2] = *(const uint32_t*)&sAhi[base + 8];
                ah[mt][3] = *(const uint32_t*)&sAhi[base + 8 * ASTR + 8];
                al[mt][0] = *(const uint32_t*)&sAlo[base];
                al[mt][1] = *(const uint32_t*)&sAlo[base + 8 * ASTR];
                al[mt][2] = *(const uint32_t*)&sAlo[base + 8];
                al[mt][3] = *(const uint32_t*)&sAlo[base + 8 * ASTR + 8];
            }
            uint32_t bh[4][2], bl[4][2];
#pragma unroll
            for (int nt = 0; nt < 4; nt++) {
                int base = (warp_n * 32 + nt * 8 + g) * ASTR + kc + tg * 2;
                bh[nt][0] = *(const uint32_t*)&sBhi[base];
                bh[nt][1] = *(const uint32_t*)&sBhi[base + 8];
                bl[nt][0] = *(const uint32_t*)&sBlo[base];
                bl[nt][1] = *(const uint32_t*)&sBlo[base + 8];
            }
#pragma unroll
            for (int mt = 0; mt < 4; mt++)
#pragma unroll
                for (int nt = 0; nt < 4; nt++) {
                    mma_bf16(acc[mt][nt], ah[mt], bh[nt]);
                    mma_bf16(acc[mt][nt], ah[mt], bl[nt]);
                    mma_bf16(acc[mt][nt], al[mt], bh[nt]);
                }
        }
    };

    const int T = K / 32;
    load_tiles(0);
    store_tiles(0);
    __syncthreads();
    for (int t = 1; t < T; t++) {
        load_tiles(t * 32);
        compute((t - 1) & 1);
        store_tiles(t & 1);
        __syncthreads();
    }
    compute((T - 1) & 1);

    // epilogue: store C
#pragma unroll
    for (int mt = 0; mt < 4; mt++) {
        int r0 = m0 + warp_m * 64 + mt * 16 + g;
#pragma unroll
        for (int nt = 0; nt < 4; nt++) {
            int gc = n0 + warp_n * 32 + nt * 8 + tg * 2;
            float2 v01 = make_float2(acc[mt][nt][0], acc[mt][nt][1]);
            float2 v23 = make_float2(acc[mt][nt][2], acc[mt][nt][3]);
            if (bias) {
                float2 b = *(const float2*)&bias[gc];
                v01.x += b.x; v01.y += b.y;
                v23.x += b.x; v23.y += b.y;
            }
            if (EPI == 1) {
                v01.x = fmaxf(v01.x, 0.f); v01.y = fmaxf(v01.y, 0.f);
                v23.x = fmaxf(v23.x, 0.f); v23.y = fmaxf(v23.y, 0.f);
            }
            if (r0 < M) {
                if (EPI == 2) {
                    float2 adx = *(const float2*)&addend[(size_t)r0 * ldadd + gc];
                    v01.x += adx.x; v01.y += adx.y;
                }
                *(float2*)&C[(size_t)r0 * ldc + gc] = v01;
            }
            if (r0 + 8 < M) {
                if (EPI == 2) {
                    float2 adx = *(const float2*)&addend[(size_t)(r0 + 8) * ldadd + gc];
                    v23.x += adx.x; v23.y += adx.y;
                }
                *(float2*)&C[(size_t)(r0 + 8) * ldc + gc] = v23;
            }
        }
    }

    // fused layer-1 attention projections: s1 += Wh·a1, s2 += Wh·a2 (partial per tile)
    if (EPI == 3) {
        const int h = n0 >> 8;                                // head (DH=256 per head)
        const int cbase = (n0 & 255) + warp_n * 32 + tg * 2;  // within-head column
        float a1v[8], a2v[8];
#pragma unroll
        for (int nt = 0; nt < 4; nt++) {
            int c = cbase + nt * 8;
            a1v[nt * 2]     = attA[h * 512 + c];
            a1v[nt * 2 + 1] = attA[h * 512 + c + 1];
            a2v[nt * 2]     = attA[h * 512 + 256 + c];
            a2v[nt * 2 + 1] = attA[h * 512 + 256 + c + 1];
        }
#pragma unroll
        for (int mt = 0; mt < 4; mt++) {
            int r0 = m0 + warp_m * 64 + mt * 16 + g;
            float p1a = 0.f, p2a = 0.f, p1b = 0.f, p2b = 0.f;
#pragma unroll
            for (int nt = 0; nt < 4; nt++) {
                p1a = fmaf(acc[mt][nt][0], a1v[nt * 2], p1a);
                p1a = fmaf(acc[mt][nt][1], a1v[nt * 2 + 1], p1a);
                p2a = fmaf(acc[mt][nt][0], a2v[nt * 2], p2a);
                p2a = fmaf(acc[mt][nt][1], a2v[nt * 2 + 1], p2a);
                p1b = fmaf(acc[mt][nt][2], a1v[nt * 2], p1b);
                p1b = fmaf(acc[mt][nt][3], a1v[nt * 2 + 1], p1b);
                p2b = fmaf(acc[mt][nt][2], a2v[nt * 2], p2b);
                p2b = fmaf(acc[mt][nt][3], a2v[nt * 2 + 1], p2b);
            }
            // quad reduce (lanes sharing g; tg = lane&3)
            p1a += __shfl_xor_sync(0xffffffffu, p1a, 1);
            p1a += __shfl_xor_sync(0xffffffffu, p1a, 2);
            p2a += __shfl_xor_sync(0xffffffffu, p2a, 1);
            p2a += __shfl_xor_sync(0xffffffffu, p2a, 2);
            p1b += __shfl_xor_sync(0xffffffffu, p1b, 1);
            p1b += __shfl_xor_sync(0xffffffffu, p1b, 2);
            p2b += __shfl_xor_sync(0xffffffffu, p2b, 1);
            p2b += __shfl_xor_sync(0xffffffffu, p2b, 2);
            if (tg == 0) {
                if (r0 < M) {
                    atomicAdd(&s1o[r0 * 4 + h], p1a);
                    atomicAdd(&s2o[r0 * 4 + h], p2a);
                }
                if (r0 + 8 < M) {
                    atomicAdd(&s1o[(r0 + 8) * 4 + h], p1b);
                    atomicAdd(&s2o[(r0 + 8) * 4 + h], p2b);
                }
            }
        }
    }
}

// ---------------- node maxima from final s1/s2 (layer 1) ----------------
__global__ void k_nodemax(const float* __restrict__ s1, const float* __restrict__ s2)
{
    int node = blockIdx.x * blockDim.x + threadIdx.x;
    float4 v1 = make_float4(-3e38f, -3e38f, -3e38f, -3e38f), v2 = v1;
    if (node < NN) {
        v1 = *(const float4*)&s1[node * 4];
        v2 = *(const float4*)&s2[node * 4];
    }
    float m1[4] = { v1.x, v1.y, v1.z, v1.w };
    float m2[4] = { v2.x, v2.y, v2.z, v2.w };
#pragma unroll
    for (int h = 0; h < 4; h++) { m1[h] = wmaxf(m1[h]); m2[h] = wmaxf(m2[h]); }
    if ((threadIdx.x & 31) == 0) {
#pragma unroll
        for (int h = 0; h < 4; h++) {
            atomicMax(&g_maxenc[0 + h], fenc(m1[h]));
            atomicMax(&g_maxenc[4 + h], fenc(m2[h]));
        }
    }
}

// ---------------- fp32 SGEMM (small evidence-2 GEMM only) ----------------
#define BM 128
#define BN 128
#define BKK 16
template <int EPI>
__global__ __launch_bounds__(256, 2)
void k_sgemm(const float* __restrict__ A, int lda,
             const float* __restrict__ B, int ldb,
             float* __restrict__ C, int ldc,
             const float* __restrict__ bias,
             int M, int N, int K)
{
    __shared__ float As[BKK][BM + 4];
    __shared__ float Bs[BKK][BN];
    const int tid = threadIdx.x;
    const int m0 = blockIdx.y * BM;
    const int n0 = blockIdx.x * BN;
    const int tm = tid >> 4, tn = tid & 15;
    const int a_kk = tid & 15, a_m0 = tid >> 4;
    const int b_kk0 = tid >> 5, b_nb = (tid & 31) << 2;

    float acc[8][8];
#pragma unroll
    for (int i = 0; i < 8; i++)
#pragma unroll
        for (int j = 0; j < 8; j++) acc[i][j] = 0.f;

    float ra[8]; float4 rb[2];
    auto load_tiles = [&](int k0) {
#pragma unroll
        for (int i = 0; i < 8; i++) {
            int gm = m0 + a_m0 + 16 * i;
            ra[i] = (gm < M) ? A[(size_t)gm * lda + (k0 + a_kk)] : 0.f;
        }
#pragma unroll
        for (int i = 0; i < 2; i++) {
            int kk = b_kk0 + 8 * i;
            int gn = n0 + b_nb;
            float4 v = make_float4(0.f, 0.f, 0.f, 0.f);
            const float* bp = &B[(size_t)(k0 + kk) * ldb + b_nb];
            if (gn + 3 < N) v = *(const float4*)bp;
            else {
                if (gn     < N) v.x = bp[0];
                if (gn + 1 < N) v.y = bp[1];
                if (gn + 2 < N) v.z = bp[2];
            }
            rb[i] = v;
        }
    };
    auto store_tiles = [&]() {
#pragma unroll
        for (int i = 0; i < 8; i++) As[a_kk][a_m0 + 16 * i] = ra[i];
#pragma unroll
        for (int i = 0; i < 2; i++) *(float4*)&Bs[b_kk0 + 8 * i][b_nb] = rb[i];
    };
    auto compute = [&]() {
#pragma unroll
        for (int kk = 0; kk < BKK; kk++) {
            float a[8], b[8];
#pragma unroll
            for (int i = 0; i < 8; i++) a[i] = As[kk][tm * 8 + i];
#pragma unroll
            for (int j = 0; j < 8; j++) b[j] = Bs[kk][tn * 8 + j];
#pragma unroll
            for (int i = 0; i < 8; i++)
#pragma unroll
                for (int j = 0; j < 8; j++) acc[i][j] = fmaf(a[i], b[j], acc[i][j]);
        }
    };
    load_tiles(0); store_tiles(); __syncthreads();
    for (int k0 = BKK; k0 < K; k0 += BKK) {
        load_tiles(k0); compute(); __syncthreads(); store_tiles(); __syncthreads();
    }
    compute();
#pragma unroll
    for (int i = 0; i < 8; i++) {
        int gm = m0 + tm * 8 + i;
        if (gm < M) {
#pragma unroll
            for (int j = 0; j < 8; j++) {
                int gn = n0 + tn * 8 + j;
                if (gn < N) {
                    float v = acc[i][j];
                    if (bias) v += bias[gn];
                    if (EPI == 1) v = fmaxf(v, 0.f);
                    C[(size_t)gm * ldc + gn] = v;
                }
            }
        }
    }
}

// ---------------- attention projections + node maxima (layer 2 only) ----------------
__global__ void k_s1s2(const float* __restrict__ Wh, int ld, int F, int nh,
                       const float* __restrict__ a, int aStride,
                       float* __restrict__ s1, float* __restrict__ s2, int N,
                       int slot1, int slot2)
{
    int gw = (blockIdx.x * blockDim.x + threadIdx.x) >> 5;
    int lane = threadIdx.x & 31;
    if (gw >= N * nh) return;
    int node = gw / nh;
    int h = gw - node * nh;
    const float* wr = &Wh[(size_t)node * ld + h * F];
    const float* ah = &a[(size_t)h * aStride];
    float p1 = 0.f, p2 = 0.f;
    for (int j = lane; j < F; j += 32) {
        float x = wr[j];
        p1 = fmaf(x, ah[j], p1);
        p2 = fmaf(x, ah[F + j], p2);
    }
    p1 = wsumf(p1); p2 = wsumf(p2);
    if (lane == 0) {
        s1[(size_t)node * nh + h] = p1;
        s2[(size_t)node * nh + h] = p2;
        atomicMax(&g_maxenc[slot1 + h], fenc(p1));
        atomicMax(&g_maxenc[slot2 + h], fenc(p2));
    }
}

// ---------------- edge pass: w = exp(lrelu(s1[src]+s2[tgt]) - M); M inline; block-sum ----------------
template <int NH>
__global__ void k_expsum(const int* __restrict__ src, const int* __restrict__ tgt,
                         const float* __restrict__ s1, const float* __restrict__ s2,
                         float* __restrict__ w, int E, int sumslot, int m1, int m2)
{
    int e = blockIdx.x * blockDim.x + threadIdx.x;
    int tid = threadIdx.x;
    bool ok = (e < E);
    float Mh[NH];
#pragma unroll
    for (int h = 0; h < NH; h++) {
        float l = fdec(g_maxenc[m1 + h]) + fdec(g_maxenc[m2 + h]);
        Mh[h] = (l > 0.f) ? l : 0.2f * l;
    }
    float sv[NH];
    if (NH == 4) {
        float4 a = make_float4(0.f, 0.f, 0.f, 0.f), b = a;
        if (ok) {
            int s = src[e], t = tgt[e];
            a = *(const float4*)&s1[(size_t)s * 4];
            b = *(const float4*)&s2[(size_t)t * 4];
        }
        float lv[4] = { a.x + b.x, a.y + b.y, a.z + b.z, a.w + b.w };
#pragma unroll
        for (int h = 0; h < 4; h++) {
            float l = lv[h];
            l = (l > 0.f) ? l : 0.2f * l;
            float v = ok ? expf(l - Mh[h]) : 0.f;
            if (ok) w[(size_t)h * E + e] = v;
            sv[h] = v;
        }
    } else {
        float v = 0.f;
        if (ok) {
            int s = src[e], t = tgt[e];
            float l = s1[s] + s2[t];
            l = (l > 0.f) ? l : 0.2f * l;
            v = expf(l - Mh[0]);
            w[e] = v;
        }
        sv[0] = v;
    }
    __shared__ float red[NH * 8];
    int wi = tid >> 5, lane = tid & 31;
#pragma unroll
    for (int h = 0; h < NH; h++) {
        float v = wsumf(sv[h]);
        if (lane == 0) red[h * 8 + wi] = v;
    }
    __syncthreads();
    if (tid < 32) {
        float v = (tid < NH * 8) ? red[tid] : 0.f;
        v += __shfl_down_sync(0xffffffffu, v, 4);
        v += __shfl_down_sync(0xffffffffu, v, 2);
        v += __shfl_down_sync(0xffffffffu, v, 1);
        if ((tid & 7) == 0 && tid < NH * 8)
            atomicAdd(&g_sumexp[sumslot + (tid >> 3)], (double)v);
    }
}

__global__ void k_finalize(int slot0, int n)
{
    int i = threadIdx.x;
    if (i < n) g_invS[slot0 + i] = (float)(1.0 / g_sumexp[slot0 + i]);
}

// ---------------- CSR gather ----------------
__global__ __launch_bounds__(256, 8)
void k_gather1024(const int* __restrict__ src, const float* __restrict__ w,
                  const float* __restrict__ Wh, float* __restrict__ xnew, int slot0)
{
    int node = blockIdx.x;
    int tid = threadIdx.x;
    int head = tid >> 6;
    int col = tid * 4;
    const float* wh = &w[(size_t)head * EE];

    int p = g_rowptr[node];
    const int end = g_rowptr[node + 1];

    int s_cur = 0; float c_cur = 0.f;
    if (p < end) { int e = g_eidx[p]; s_cur = src[e]; c_cur = wh[e]; }

    float4 acc = make_float4(0.f, 0.f, 0.f, 0.f);
    while (p < end) {
        int s_nxt = 0; float c_nxt = 0.f;
        if (p + 1 < end) { int e = g_eidx[p + 1]; s_nxt = src[e]; c_nxt = wh[e]; }
        float4 v = *(const float4*)&Wh[(size_t)s_cur * 1024 + col];
        acc.x = fmaf(c_cur, v.x, acc.x);
        acc.y = fmaf(c_cur, v.y, acc.y);
        acc.z = fmaf(c_cur, v.z, acc.z);
        acc.w = fmaf(c_cur, v.w, acc.w);
        s_cur = s_nxt; c_cur = c_nxt; p++;
    }
    float inv = g_invS[slot0 + head];
    acc.x *= inv; acc.y *= inv; acc.z *= inv; acc.w *= inv;
    *(float4*)&xnew[(size_t)node * 1024 + col] = acc;
}

__global__ __launch_bounds__(256, 8)
void k_gather128(const int* __restrict__ src, const float* __restrict__ w,
                 const float* __restrict__ Wh, float* __restrict__ xnew, int slot)
{
    int node = (blockIdx.x * blockDim.x + threadIdx.x) >> 5;
    int lane = threadIdx.x & 31;
    if (node >= NN) return;
    int col = lane * 4;

    int p = g_rowptr[node];
    const int end = g_rowptr[node + 1];

    int s_cur = 0; float c_cur = 0.f;
    if (p < end) { int e = g_eidx[p]; s_cur = src[e]; c_cur = w[e]; }

    float4 acc = make_float4(0.f, 0.f, 0.f, 0.f);
    while (p < end) {
        int s_nxt = 0; float c_nxt = 0.f;
        if (p + 1 < end) { int e = g_eidx[p + 1]; s_nxt = src[e]; c_nxt = w[e]; }
        float4 v = *(const float4*)&Wh[(size_t)s_cur * 128 + col];
        acc.x = fmaf(c_cur, v.x, acc.x);
        acc.y = fmaf(c_cur, v.y, acc.y);
        acc.z = fmaf(c_cur, v.z, acc.z);
        acc.w = fmaf(c_cur, v.w, acc.w);
        s_cur = s_nxt; c_cur = c_nxt; p++;
    }
    float inv = g_invS[slot];
    acc.x *= inv; acc.y *= inv; acc.z *= inv; acc.w *= inv;
    *(float4*)&xnew[(size_t)node * 128 + col] = acc;
}

// ---------------- evidence heads ----------------
__global__ void k_evid1(const float* __restrict__ hbuf, const float* __restrict__ w2,
                        const float* __restrict__ b2, float* __restrict__ evsum, int N)
{
    int gw = (blockIdx.x * blockDim.x + threadIdx.x) >> 5;
    int lane = threadIdx.x & 31;
    if (gw >= N) return;
    float e0 = 0.f, e1 = 0.f, e2 = 0.f;
#pragma unroll
    for (int h = 0; h < NHEAD; h++) {
        float4 v = *(const float4*)&hbuf[(size_t)gw * 512 + h * 128 + lane * 4];
        const float* wc = &w2[h * 384 + lane * 12];
        float a0 = v.x * wc[0] + v.y * wc[3] + v.z * wc[6] + v.w * wc[9];
        float a1 = v.x * wc[1] + v.y * wc[4] + v.z * wc[7] + v.w * wc[10];
        float a2 = v.x * wc[2] + v.y * wc[5] + v.z * wc[8] + v.w * wc[11];
        a0 = wsumf(a0); a1 = wsumf(a1); a2 = wsumf(a2);
        e0 += softplusf(a0 + b2[h * 3 + 0]) + 1.f;
        e1 += softplusf(a1 + b2[h * 3 + 1]) + 1.f;
        e2 += softplusf(a2 + b2[h * 3 + 2]) + 1.f;
    }
    if (lane == 0) {
        evsum[gw * 3 + 0] = e0; evsum[gw * 3 + 1] = e1; evsum[gw * 3 + 2] = e2;
    }
}

__global__ void k_evid2(const float* __restrict__ hbuf, const float* __restrict__ w2,
                        const float* __restrict__ b2, const float* __restrict__ evsum,
                        float* __restrict__ out, int N)
{
    int gw = (blockIdx.x * blockDim.x + threadIdx.x) >> 5;
    int lane = threadIdx.x & 31;
    if (gw >= N) return;
    float2 v = *(const float2*)&hbuf[(size_t)gw * 64 + lane * 2];
    const float* wc = &w2[lane * 6];
    float a0 = v.x * wc[0] + v.y * wc[3];
    float a1 = v.x * wc[1] + v.y * wc[4];
    float a2 = v.x * wc[2] + v.y * wc[5];
    a0 = wsumf(a0); a1 = wsumf(a1); a2 = wsumf(a2);
    if (lane == 0) {
        float e0 = softplusf(a0 + b2[0]) + 1.f;
        float e1 = softplusf(a1 + b2[1]) + 1.f;
        float e2 = softplusf(a2 + b2[2]) + 1.f;
        out[(size_t)gw * 3 + 0] = (evsum[gw * 3 + 0] * 0.25f + e0) * 0.5f;
        out[(size_t)gw * 3 + 1] = (evsum[gw * 3 + 1] * 0.25f + e1) * 0.5f;
        out[(size_t)gw * 3 + 2] = (evsum[gw * 3 + 2] * 0.25f + e2) * 0.5f;
    }
}

// ---------------- LayerNorm + ELU ----------------
template <int F>
__global__ void k_ln_elu(const float* __restrict__ in, float* __restrict__ out,
                         const float* __restrict__ gam, const float* __restrict__ bet, int N)
{
    int gw = (blockIdx.x * blockDim.x + threadIdx.x) >> 5;
    int lane = threadIdx.x & 31;
    if (gw >= N) return;
    constexpr int R = F / 32;
    float v[R];
    const float* ir = &in[(size_t)gw * F];
#pragma unroll
    for (int r = 0; r < R; r++) v[r] = ir[lane + 32 * r];
    float s = 0.f;
#pragma unroll
    for (int r = 0; r < R; r++) s += v[r];
    s = wsumf(s);
    float mean = s * (1.f / F);
    float q = 0.f;
#pragma unroll
    for (int r = 0; r < R; r++) { float d = v[r] - mean; q = fmaf(d, d, q); }
    q = wsumf(q);
    float rstd = rsqrtf(q * (1.f / F) + 1e-5f);
    float* orow = &out[(size_t)gw * F];
#pragma unroll
    for (int r = 0; r < R; r++) {
        int j = lane + 32 * r;
        float y = (v[r] - mean) * rstd * gam[j] + bet[j];
        orow[j] = eluf(y);
    }
}

// ---------------- launch ----------------
extern "C" void kernel_launch(void* const* d_in, const int* in_sizes, int n_in,
                              void* d_out, int out_size)
{
    (void)in_sizes; (void)n_in; (void)out_size;

    const float* x        = (const float*)d_in[0];
    const int*   ei       = (const int*)  d_in[1];
    const float* W_heads  = (const float*)d_in[2];
    const float* a_heads  = (const float*)d_in[3];
    const float* ev1w_h   = (const float*)d_in[4];
    const float* ev1b_h   = (const float*)d_in[5];
    const float* ev2w_h   = (const float*)d_in[6];
    const float* ev2b_h   = (const float*)d_in[7];
    const float* agg_w    = (const float*)d_in[8];
    const float* agg_b    = (const float*)d_in[9];
    const float* ln1_g    = (const float*)d_in[10];
    const float* ln1_b    = (const float*)d_in[11];
    const float* W2       = (const float*)d_in[12];
    const float* a2       = (const float*)d_in[13];
    const float* ev1w2    = (const float*)d_in[14];
    const float* ev1b2    = (const float*)d_in[15];
    const float* ev2w2    = (const float*)d_in[16];
    const float* ev2b2    = (const float*)d_in[17];
    const float* ln2_g    = (const float*)d_in[18];
    const float* ln2_b    = (const float*)d_in[19];
    const float* res_w    = (const float*)d_in[20];
    const float* res_b    = (const float*)d_in[21];

    const int* src = ei;
    const int* tgt = ei + EE;

    float* out_x  = (float*)d_out;
    float* out_ev = (float*)d_out + (size_t)NN * DOUT;

    float *Wh, *xnew, *s1, *s2, *wbuf, *w2e, *hbuf, *evsum, *h1, *Wh2, *s1b, *s2b, *xnew2, *x2;
    __nv_bfloat16 *bt1hi, *bt1lo, *btahi, *btalo, *btehi, *btelo, *btw2hi, *btw2lo, *btrhi, *btrlo;
    cudaGetSymbolAddress((void**)&Wh,    g_Wh);
    cudaGetSymbolAddress((void**)&xnew,  g_xnew);
    cudaGetSymbolAddress((void**)&s1,    g_s1);
    cudaGetSymbolAddress((void**)&s2,    g_s2);
    cudaGetSymbolAddress((void**)&wbuf,  g_w);
    cudaGetSymbolAddress((void**)&w2e,   g_w2e);
    cudaGetSymbolAddress((void**)&hbuf,  g_hbuf);
    cudaGetSymbolAddress((void**)&evsum, g_evsum);
    cudaGetSymbolAddress((void**)&h1,    g_h1);
    cudaGetSymbolAddress((void**)&Wh2,   g_Wh2);
    cudaGetSymbolAddress((void**)&s1b,   g_s1b);
    cudaGetSymbolAddress((void**)&s2b,   g_s2b);
    cudaGetSymbolAddress((void**)&xnew2, g_xnew2);
    cudaGetSymbolAddress((void**)&x2,    g_x2);
    cudaGetSymbolAddress((void**)&bt1hi, g_bt1hi);
    cudaGetSymbolAddress((void**)&bt1lo, g_bt1lo);
    cudaGetSymbolAddress((void**)&btahi, g_btahi);
    cudaGetSymbolAddress((void**)&btalo, g_btalo);
    cudaGetSymbolAddress((void**)&btehi, g_btehi);
    cudaGetSymbolAddress((void**)&btelo, g_btelo);
    cudaGetSymbolAddress((void**)&btw2hi, g_btw2hi);
    cudaGetSymbolAddress((void**)&btw2lo, g_btw2lo);
    cudaGetSymbolAddress((void**)&btrhi, g_btrhi);
    cudaGetSymbolAddress((void**)&btrlo, g_btrlo);

    cudaFuncSetAttribute(k_mma<0>, cudaFuncAttributeMaxDynamicSharedMemorySize, MMA_SMEM);
    cudaFuncSetAttribute(k_mma<1>, cudaFuncAttributeMaxDynamicSharedMemorySize, MMA_SMEM);
    cudaFuncSetAttribute(k_mma<2>, cudaFuncAttributeMaxDynamicSharedMemorySize, MMA_SMEM);
    cudaFuncSetAttribute(k_mma<3>, cudaFuncAttributeMaxDynamicSharedMemorySize, MMA_SMEM);

    const int MB = (NN + 127) / 128;   // 235

    // launches 1-3, then #4 = big G1 k_mma (ncu captures launch #4)
    k_btall<<<BT_BLOCKS + INIT_BLOCKS, 256>>>(W_heads, agg_w, ev1w_h, W2, res_w);
    k_hist<<<(EE + 255) / 256, 256>>>(tgt);
    k_scan<<<1, 1024>>>();

    // #4: Wh = x @ W_heads, with fused s1/s2 attention projections
    k_mma<3><<<dim3(8, MB), 256, MMA_SMEM>>>(x, DIN, 0, 128, bt1hi, bt1lo,
                                             Wh, 1024, nullptr, nullptr, 0, NN, DIN,
                                             s1, s2, a_heads);

    // CSR fill (only needed before gather), node maxima, edge pass, softmax scale
    k_fill<<<(EE + 255) / 256, 256>>>(tgt);
    k_nodemax<<<(NN + 255) / 256, 256>>>(s1, s2);
    k_expsum<NHEAD><<<(EE + 255) / 256, 256>>>(src, tgt, s1, s2, wbuf, EE, 0, 0, 4);
    k_finalize<<<1, 8>>>(0, NHEAD);

    // CSR gather (all heads)
    k_gather1024<<<NN, 256>>>(src, wbuf, Wh, xnew, 0);

    // evidence layer 1 (block-diagonal, relu) + fused head
    k_mma<1><<<dim3(4, MB), 256, MMA_SMEM>>>(xnew, NHEAD * DH, DH, 128, btehi, btelo,
                                             hbuf, 512, ev1b_h, nullptr, 0, NN, DH,
                                             nullptr, nullptr, nullptr);
    k_evid1<<<NN / 8, 256>>>(hbuf, ev2w_h, ev2b_h, evsum, NN);

    // h1 = elu(LN(x_cat @ agg_w + agg_b))
    k_mma<0><<<dim3(2, MB), 256, MMA_SMEM>>>(xnew, NHEAD * DH, 0, 128, btahi, btalo,
                                             h1, DH, agg_b, nullptr, 0, NN, NHEAD * DH,
                                             nullptr, nullptr, nullptr);
    k_ln_elu<DH><<<NN / 8, 256>>>(h1, h1, ln1_g, ln1_b, NN);

    // layer-2 GAT
    k_mma<0><<<dim3(1, MB), 256, MMA_SMEM>>>(h1, DH, 0, 128, btw2hi, btw2lo,
                                             Wh2, DOUT, nullptr, nullptr, 0, NN, DH,
                                             nullptr, nullptr, nullptr);
    k_s1s2<<<NN / 8, 256>>>(Wh2, DOUT, DOUT, 1, a2, 2 * DOUT, s1b, s2b, NN, 8, 9);
    k_expsum<1><<<(EE + 255) / 256, 256>>>(src, tgt, s1b, s2b, w2e, EE, 4, 8, 9);
    k_finalize<<<1, 8>>>(4, 1);
    k_gather128<<<(NN * 32 + 255) / 256, 256>>>(src, w2e, Wh2, xnew2, 4);

    // evidence layer 2 + final combine
    k_sgemm<1><<<dim3(1, MB), 256>>>(xnew2, DOUT, ev1w2, DOUT / 2, hbuf, DOUT / 2,
                                     ev1b2, NN, DOUT / 2, DOUT);
    k_evid2<<<NN / 8, 256>>>(hbuf, ev2w2, ev2b2, evsum, out_ev, NN);

    // x2 = elu(LN(x_new2)); x_out = x2 + h1 @ res_w + res_b
    k_ln_elu<DOUT><<<NN / 8, 256>>>(xnew2, x2, ln2_g, ln2_b, NN);
    k_mma<2><<<dim3(1, MB), 256, MMA_SMEM>>>(h1, DH, 0, 128, btrhi, btrlo,
                                             out_x, DOUT, res_b, x2, DOUT, NN, DH,
                                             nullptr, nullptr, nullptr);
}

// round 16
// speedup vs baseline: 1.2239x; 1.0576x over previous
#include <cuda_runtime.h>
#include <cuda_bf16.h>
#include <math.h>
#include <stdint.h>

// ---------------- problem constants ----------------
#define NN   30000
#define EE   480000
#define DIN  768
#define DH   256    // HID
#define DOUT 128    // OUT
#define NHEAD 4
#define NCLS 3

// ---------------- scratch (static device memory; no allocations) ----------------
__device__ float    g_Wh   [(size_t)NN * (NHEAD * DH)];
__device__ __align__(16) float g_s1 [NHEAD * NN];   // interleaved [node][head]
__device__ __align__(16) float g_s2 [NHEAD * NN];
__device__ float    g_w    [(size_t)NHEAD * EE];
__device__ float    g_w2e  [EE];
__device__ float    g_hbuf [(size_t)NN * 512];
__device__ float    g_evsum[NN * NCLS];
__device__ float    g_h1   [(size_t)NN * DH];
__device__ float    g_Wh2  [(size_t)NN * DOUT];
__device__ float    g_s1b  [NN];
__device__ float    g_s2b  [NN];
__device__ float    g_xnew2[(size_t)NN * DOUT];
__device__ float    g_x2   [(size_t)NN * DOUT];
__device__ unsigned g_maxenc[12];
__device__ double   g_sumexp[8];
__device__ float    g_invS  [8];

// CSR (edges grouped by tgt)
__device__ int g_rowptr[NN + 1];
__device__ int g_cursor[NN];
__device__ int g_eidx  [EE];

// pre-split bf16 A operands (hi/lo)
__device__ __align__(256) __nv_bfloat16 g_xhi [(size_t)NN * DIN],  g_xlo [(size_t)NN * DIN];
__device__ __align__(256) __nv_bfloat16 g_xnhi[(size_t)NN * 1024], g_xnlo[(size_t)NN * 1024];
__device__ __align__(256) __nv_bfloat16 g_h1hi[(size_t)NN * DH],   g_h1lo[(size_t)NN * DH];

// transposed + bf16-split weights (Bt[n][k], K-major)
__device__ __align__(256) __nv_bfloat16 g_bt1hi [1024 * 768], g_bt1lo [1024 * 768];
__device__ __align__(256) __nv_bfloat16 g_btahi [256 * 1024], g_btalo [256 * 1024];
__device__ __align__(256) __nv_bfloat16 g_btehi [512 * 256],  g_btelo [512 * 256];
__device__ __align__(256) __nv_bfloat16 g_btw2hi[128 * 256],  g_btw2lo[128 * 256];
__device__ __align__(256) __nv_bfloat16 g_btrhi [128 * 256],  g_btrlo [128 * 256];

// ---------------- helpers ----------------
__device__ __forceinline__ unsigned fenc(float f) {
    unsigned u = __float_as_uint(f);
    return (u & 0x80000000u) ? ~u : (u | 0x80000000u);
}
__device__ __forceinline__ float fdec(unsigned u) {
    return (u & 0x80000000u) ? __uint_as_float(u & 0x7fffffffu) : __uint_as_float(~u);
}
__device__ __forceinline__ float wsumf(float v) {
#pragma unroll
    for (int o = 16; o > 0; o >>= 1) v += __shfl_xor_sync(0xffffffffu, v, o);
    return v;
}
__device__ __forceinline__ float wmaxf(float v) {
#pragma unroll
    for (int o = 16; o > 0; o >>= 1) v = fmaxf(v, __shfl_xor_sync(0xffffffffu, v, o));
    return v;
}
__device__ __forceinline__ float softplusf(float x) {
    return fmaxf(x, 0.f) + log1pf(expf(-fabsf(x)));
}
__device__ __forceinline__ float eluf(float x) {
    return x > 0.f ? x : expm1f(x);
}
__device__ __forceinline__ void bf16split(float x, __nv_bfloat16& hi, __nv_bfloat16& lo) {
    hi = __float2bfloat16(x);
    lo = __float2bfloat16(x - __bfloat162float(hi));
}
__device__ __forceinline__ uint32_t smem_u32(const void* p) {
    uint32_t a;
    asm("{ .reg .u64 t; cvta.to.shared.u64 t, %1; cvt.u32.u64 %0, t; }" : "=r"(a) : "l"(p));
    return a;
}
__device__ __forceinline__ void cp16(uint32_t dst, const void* src, bool valid) {
    asm volatile("cp.async.cg.shared.global [%0], [%1], 16, %2;"
                 :: "r"(dst), "l"(src), "r"(valid ? 16u : 0u) : "memory");
}
__device__ __forceinline__ void cp_commit() {
    asm volatile("cp.async.commit_group;" ::: "memory");
}
__device__ __forceinline__ void cp_wait0() {
    asm volatile("cp.async.wait_group 0;" ::: "memory");
}
__device__ __forceinline__ void cp_wait1() {
    asm volatile("cp.async.wait_group 1;" ::: "memory");
}

// mma.sync m16n8k16 bf16 (row.col), fp32 accumulate — compiles on plain sm_103.
__device__ __forceinline__ void mma_bf16(float* c, const uint32_t* a, const uint32_t* b) {
    asm volatile(
        "mma.sync.aligned.m16n8k16.row.col.f32.bf16.bf16.f32 "
        "{%0,%1,%2,%3}, {%4,%5,%6,%7}, {%8,%9}, {%0,%1,%2,%3};"
        : "+f"(c[0]), "+f"(c[1]), "+f"(c[2]), "+f"(c[3])
        : "r"(a[0]), "r"(a[1]), "r"(a[2]), "r"(a[3]), "r"(b[0]), "r"(b[1]));
}

// ---------------- fused: B transpose/split + init tail ----------------
#define BT_BLOCKS 4864
#define INIT_BLOCKS 1056
__global__ void k_btall(const float* w1, const float* wa, const float* we,
                        const float* w2, const float* wr)
{
    int b = blockIdx.x;
    if (b >= BT_BLOCKS) {
        int ib = b - BT_BLOCKS;
        if (ib < 118) {
            int i = ib * 256 + threadIdx.x;
            if (i <= NN) g_rowptr[i] = 0;
            if (ib == 0) {
                if (threadIdx.x < 12) g_maxenc[threadIdx.x] = 0u;
                if (threadIdx.x < 8)  { g_sumexp[threadIdx.x] = 0.0; g_invS[threadIdx.x] = 0.f; }
            }
        } else if (ib < 587) {
            int i = (ib - 118) * 256 + threadIdx.x;
            if (i < NHEAD * NN) g_s1[i] = 0.f;
        } else {
            int i = (ib - 587) * 256 + threadIdx.x;
            if (i < NHEAD * NN) g_s2[i] = 0.f;
        }
        return;
    }
    const float* src; __nv_bfloat16 *hi, *lo;
    int K, headN, headStride, base;
    if (b < 3072)      { src = w1; hi = g_bt1hi;  lo = g_bt1lo;  K = 768;  headN = 256; headStride = 768 * 256; base = 0; }
    else if (b < 4096) { src = wa; hi = g_btahi;  lo = g_btalo;  K = 1024; headN = 256; headStride = 0;         base = 3072; }
    else if (b < 4608) { src = we; hi = g_btehi;  lo = g_btelo;  K = 256;  headN = 128; headStride = 256 * 128; base = 4096; }
    else if (b < 4736) { src = w2; hi = g_btw2hi; lo = g_btw2lo; K = 256;  headN = 128; headStride = 0;         base = 4608; }
    else               { src = wr; hi = g_btrhi;  lo = g_btrlo;  K = 256;  headN = 128; headStride = 0;         base = 4736; }
    int idx = (b - base) * 256 + threadIdx.x;
    int n = idx / K, k = idx - n * K;
    int head = n / headN, nloc = n - head * headN;
    float v = src[(size_t)head * headStride + (size_t)k * headN + nloc];
    __nv_bfloat16 h, l;
    bf16split(v, h, l);
    hi[idx] = h;
    lo[idx] = l;
}

// ---------------- A split: fp32 -> bf16 hi/lo ----------------
__global__ void k_split(const float* __restrict__ src, __nv_bfloat16* __restrict__ hi,
                        __nv_bfloat16* __restrict__ lo, int n4)
{
    int i = blockIdx.x * blockDim.x + threadIdx.x;
    if (i >= n4) return;
    float4 v = ((const float4*)src)[i];
    __nv_bfloat16 hx, lx, hy, ly, hz, lz, hw, lw;
    bf16split(v.x, hx, lx); bf16split(v.y, hy, ly);
    bf16split(v.z, hz, lz); bf16split(v.w, hw, lw);
    ((__nv_bfloat162*)hi)[2 * i]     = __nv_bfloat162(hx, hy);
    ((__nv_bfloat162*)hi)[2 * i + 1] = __nv_bfloat162(hz, hw);
    ((__nv_bfloat162*)lo)[2 * i]     = __nv_bfloat162(lx, ly);
    ((__nv_bfloat162*)lo)[2 * i + 1] = __nv_bfloat162(lz, lw);
}

// ---------------- CSR build ----------------
__global__ void k_hist(const int* __restrict__ tgt) {
    int e = blockIdx.x * blockDim.x + threadIdx.x;
    if (e < EE) atomicAdd(&g_rowptr[tgt[e] + 1], 1);
}

__global__ void k_scan() {
    __shared__ int warp_tot[32];
    int tid = threadIdx.x;
    int lane = tid & 31, wi = tid >> 5;
    const int CH = (NN + 1023) / 1024;
    int beg = tid * CH;
    int end = beg + CH; if (end > NN) end = NN;
    int s = 0;
    for (int i = beg; i < end; i++) s += g_rowptr[i + 1];
    int v = s;
#pragma unroll
    for (int o = 1; o < 32; o <<= 1) {
        int u = __shfl_up_sync(0xffffffffu, v, o);
        if (lane >= o) v += u;
    }
    if (lane == 31) warp_tot[wi] = v;
    __syncthreads();
    if (wi == 0) {
        int w = warp_tot[lane];
#pragma unroll
        for (int o = 1; o < 32; o <<= 1) {
            int u = __shfl_up_sync(0xffffffffu, w, o);
            if (lane >= o) w += u;
        }
        warp_tot[lane] = w;
    }
    __syncthreads();
    int run = v - s + (wi > 0 ? warp_tot[wi - 1] : 0);
    for (int i = beg; i < end; i++) {
        int c = g_rowptr[i + 1];
        g_cursor[i] = run;
        run += c;
        g_rowptr[i + 1] = run;
    }
    if (tid == 0) g_rowptr[0] = 0;
}

__global__ void k_fill(const int* __restrict__ tgt) {
    int e = blockIdx.x * blockDim.x + threadIdx.x;
    if (e < EE) {
        int p = atomicAdd(&g_cursor[tgt[e]], 1);
        g_eidx[p] = e;
    }
}

// ---------------- bf16-split tensor-core GEMM, cp.async 2-stage, 2 CTAs/SM ----------------
// A pre-split bf16 hi/lo [M,lda]; Bt pre-split bf16 [Ntot,K] K-major.
// EPI: 0 = (+bias); 1 = relu(+bias); 2 = +bias +addend; 3 = store + fused s1/s2 projections.
#define ASTR 40
#define TILE_B (128 * ASTR * 2)    // 10240 B
#define BUF_B  (4 * TILE_B)        // 40960 B (Ahi/Alo/Bhi/Blo)
#define NSTAGE 2
#define MMA_SMEM (NSTAGE * BUF_B)  // 81920 B -> 2 CTAs/SM

template <int EPI>
__global__ __launch_bounds__(256, 2)
void k_mma(const __nv_bfloat16* __restrict__ Ahi, const __nv_bfloat16* __restrict__ Alo,
           int lda, int aHeadStep, int headN,
           const __nv_bfloat16* __restrict__ Bthi, const __nv_bfloat16* __restrict__ Btlo,
           float* __restrict__ C, int ldc,
           const float* __restrict__ bias,
           const float* __restrict__ addend, int ldadd,
           int M, int K,
           float* __restrict__ s1o, float* __restrict__ s2o,
           const float* __restrict__ attA)
{
    extern __shared__ __align__(16) char smraw[];
    const uint32_t sbase = smem_u32(smraw);

    const int tid = threadIdx.x;
    const int lane = tid & 31;
    const int wid = tid >> 5;
    const int warp_m = wid & 1;
    const int warp_n = wid >> 1;
    const int g  = lane >> 2;
    const int tg = lane & 3;

    const int m0 = blockIdx.y * 128;
    const int n0 = blockIdx.x * 128;
    const size_t aOff = (size_t)(n0 / headN) * aHeadStep;

    // per-thread cp.async coords: rows row0 (0..63) and row0+64, 16B chunk ch (0..3)
    const int row0 = tid >> 2, ch = tid & 3;
    const int row1 = row0 + 64;
    const bool vm0 = (m0 + row0) < M;
    const bool vm1 = (m0 + row1) < M;
    const int gm0 = vm0 ? (m0 + row0) : 0;
    const int gm1 = vm1 ? (m0 + row1) : 0;

    const char* pAh0 = (const char*)&Ahi[aOff + (size_t)gm0 * lda] + ch * 16;
    const char* pAl0 = (const char*)&Alo[aOff + (size_t)gm0 * lda] + ch * 16;
    const char* pAh1 = (const char*)&Ahi[aOff + (size_t)gm1 * lda] + ch * 16;
    const char* pAl1 = (const char*)&Alo[aOff + (size_t)gm1 * lda] + ch * 16;
    const char* pBh0 = (const char*)&Bthi[(size_t)(n0 + row0) * K] + ch * 16;
    const char* pBl0 = (const char*)&Btlo[(size_t)(n0 + row0) * K] + ch * 16;
    const char* pBh1 = (const char*)&Bthi[(size_t)(n0 + row1) * K] + ch * 16;
    const char* pBl1 = (const char*)&Btlo[(size_t)(n0 + row1) * K] + ch * 16;
    const uint32_t so0 = row0 * (ASTR * 2) + ch * 16;
    const uint32_t so1 = row1 * (ASTR * 2) + ch * 16;

    auto issue = [&](int t, int s) {
        size_t go = (size_t)t * 64;    // 32 bf16 = 64 B per K-tile
        uint32_t sb = sbase + s * BUF_B;
        cp16(sb + so0,              pAh0 + go, vm0);
        cp16(sb + TILE_B + so0,     pAl0 + go, vm0);
        cp16(sb + 2 * TILE_B + so0, pBh0 + go, true);
        cp16(sb + 3 * TILE_B + so0, pBl0 + go, true);
        cp16(sb + so1,              pAh1 + go, vm1);
        cp16(sb + TILE_B + so1,     pAl1 + go, vm1);
        cp16(sb + 2 * TILE_B + so1, pBh1 + go, true);
        cp16(sb + 3 * TILE_B + so1, pBl1 + go, true);
        cp_commit();
    };

    float acc[4][4][4];
#pragma unroll
    for (int i = 0; i < 4; i++)
#pragma unroll
        for (int j = 0; j < 4; j++)
#pragma unroll
            for (int k = 0; k < 4; k++) acc[i][j][k] = 0.f;

    auto compute = [&](int s) {
        const __nv_bfloat16* sAhi = (const __nv_bfloat16*)(smraw + s * BUF_B);
        const __nv_bfloat16* sAlo = (const __nv_bfloat16*)(smraw + s * BUF_B + TILE_B);
        const __nv_bfloat16* sBhi = (const __nv_bfloat16*)(smraw + s * BUF_B + 2 * TILE_B);
        const __nv_bfloat16* sBlo = (const __nv_bfloat16*)(smraw + s * BUF_B + 3 * TILE_B);
#pragma unroll
        for (int kc = 0; kc < 32; kc += 16) {
            uint32_t ah[4][4], al[4][4];
#pragma unroll
            for (int mt = 0; mt < 4; mt++) {
                int base = (warp_m * 64 + mt * 16 + g) * ASTR + kc + tg * 2;
                ah[mt][0] = *(const uint32_t*)&sAhi[base];
                ah[mt][1] = *(const uint32_t*)&sAhi[base + 8 * ASTR];
                ah[mt][2] = *(const uint32_t*)&sAhi[base + 8];
                ah[mt][3] = *(const uint32_t*)&sAhi[base + 8 * ASTR + 8];
                al[mt][0] = *(const uint32_t*)&sAlo[base];
                al[mt][1] = *(const uint32_t*)&sAlo[base + 8 * ASTR];
                al[mt][2] = *(const uint32_t*)&sAlo[base + 8];
                al[mt][3] = *(const uint32_t*)&sAlo[base + 8 * ASTR + 8];
            }
            uint32_t bh[4][2], bl[4][2];
#pragma unroll
            for (int nt = 0; nt < 4; nt++) {
                int base = (warp_n * 32 + nt * 8 + g) * ASTR + kc + tg * 2;
                bh[nt][0] = *(const uint32_t*)&sBhi[base];
                bh[nt][1] = *(const uint32_t*)&sBhi[base + 8];
                bl[nt][0] = *(const uint32_t*)&sBlo[base];
                bl[nt][1] = *(const uint32_t*)&sBlo[base + 8];
            }
#pragma unroll
            for (int mt = 0; mt < 4; mt++)
#pragma unroll
                for (int nt = 0; nt < 4; nt++) {
                    mma_bf16(acc[mt][nt], ah[mt], bh[nt]);
                    mma_bf16(acc[mt][nt], ah[mt], bl[nt]);
                    mma_bf16(acc[mt][nt], al[mt], bh[nt]);
                }
        }
    };

    const int T = K / 32;
    issue(0, 0);
    for (int t = 0; t < T; t++) {
        if (t + 1 < T) { issue(t + 1, (t + 1) & 1); cp_wait1(); }
        else           { cp_wait0(); }
        __syncthreads();
        compute(t & 1);
        __syncthreads();
    }

    // epilogue: store C
#pragma unroll
    for (int mt = 0; mt < 4; mt++) {
        int r0 = m0 + warp_m * 64 + mt * 16 + g;
#pragma unroll
        for (int nt = 0; nt < 4; nt++) {
            int gc = n0 + warp_n * 32 + nt * 8 + tg * 2;
            float2 v01 = make_float2(acc[mt][nt][0], acc[mt][nt][1]);
            float2 v23 = make_float2(acc[mt][nt][2], acc[mt][nt][3]);
            if (bias) {
                float2 b = *(const float2*)&bias[gc];
                v01.x += b.x; v01.y += b.y;
                v23.x += b.x; v23.y += b.y;
            }
            if (EPI == 1) {
                v01.x = fmaxf(v01.x, 0.f); v01.y = fmaxf(v01.y, 0.f);
                v23.x = fmaxf(v23.x, 0.f); v23.y = fmaxf(v23.y, 0.f);
            }
            if (r0 < M) {
                if (EPI == 2) {
                    float2 adx = *(const float2*)&addend[(size_t)r0 * ldadd + gc];
                    v01.x += adx.x; v01.y += adx.y;
                }
                *(float2*)&C[(size_t)r0 * ldc + gc] = v01;
            }
            if (r0 + 8 < M) {
                if (EPI == 2) {
                    float2 adx = *(const float2*)&addend[(size_t)(r0 + 8) * ldadd + gc];
                    v23.x += adx.x; v23.y += adx.y;
                }
                *(float2*)&C[(size_t)(r0 + 8) * ldc + gc] = v23;
            }
        }
    }

    // fused layer-1 attention projections
    if (EPI == 3) {
        const int h = n0 >> 8;
        const int cbase = (n0 & 255) + warp_n * 32 + tg * 2;
        float a1v[8], a2v[8];
#pragma unroll
        for (int nt = 0; nt < 4; nt++) {
            int c = cbase + nt * 8;
            a1v[nt * 2]     = attA[h * 512 + c];
            a1v[nt * 2 + 1] = attA[h * 512 + c + 1];
            a2v[nt * 2]     = attA[h * 512 + 256 + c];
            a2v[nt * 2 + 1] = attA[h * 512 + 256 + c + 1];
        }
#pragma unroll
        for (int mt = 0; mt < 4; mt++) {
            int r0 = m0 + warp_m * 64 + mt * 16 + g;
            float p1a = 0.f, p2a = 0.f, p1b = 0.f, p2b = 0.f;
#pragma unroll
            for (int nt = 0; nt < 4; nt++) {
                p1a = fmaf(acc[mt][nt][0], a1v[nt * 2], p1a);
                p1a = fmaf(acc[mt][nt][1], a1v[nt * 2 + 1], p1a);
                p2a = fmaf(acc[mt][nt][0], a2v[nt * 2], p2a);
                p2a = fmaf(acc[mt][nt][1], a2v[nt * 2 + 1], p2a);
                p1b = fmaf(acc[mt][nt][2], a1v[nt * 2], p1b);
                p1b = fmaf(acc[mt][nt][3], a1v[nt * 2 + 1], p1b);
                p2b = fmaf(acc[mt][nt][2], a2v[nt * 2], p2b);
                p2b = fmaf(acc[mt][nt][3], a2v[nt * 2 + 1], p2b);
            }
            p1a += __shfl_xor_sync(0xffffffffu, p1a, 1);
            p1a += __shfl_xor_sync(0xffffffffu, p1a, 2);
            p2a += __shfl_xor_sync(0xffffffffu, p2a, 1);
            p2a += __shfl_xor_sync(0xffffffffu, p2a, 2);
            p1b += __shfl_xor_sync(0xffffffffu, p1b, 1);
            p1b += __shfl_xor_sync(0xffffffffu, p1b, 2);
            p2b += __shfl_xor_sync(0xffffffffu, p2b, 1);
            p2b += __shfl_xor_sync(0xffffffffu, p2b, 2);
            if (tg == 0) {
                if (r0 < M) {
                    atomicAdd(&s1o[r0 * 4 + h], p1a);
                    atomicAdd(&s2o[r0 * 4 + h], p2a);
                }
                if (r0 + 8 < M) {
                    atomicAdd(&s1o[(r0 + 8) * 4 + h], p1b);
                    atomicAdd(&s2o[(r0 + 8) * 4 + h], p2b);
                }
            }
        }
    }
}

// ---------------- node maxima from final s1/s2 (layer 1) ----------------
__global__ void k_nodemax(const float* __restrict__ s1, const float* __restrict__ s2)
{
    int node = blockIdx.x * blockDim.x + threadIdx.x;
    float4 v1 = make_float4(-3e38f, -3e38f, -3e38f, -3e38f), v2 = v1;
    if (node < NN) {
        v1 = *(const float4*)&s1[node * 4];
        v2 = *(const float4*)&s2[node * 4];
    }
    float m1[4] = { v1.x, v1.y, v1.z, v1.w };
    float m2[4] = { v2.x, v2.y, v2.z, v2.w };
#pragma unroll
    for (int h = 0; h < 4; h++) { m1[h] = wmaxf(m1[h]); m2[h] = wmaxf(m2[h]); }
    if ((threadIdx.x & 31) == 0) {
#pragma unroll
        for (int h = 0; h < 4; h++) {
            atomicMax(&g_maxenc[0 + h], fenc(m1[h]));
            atomicMax(&g_maxenc[4 + h], fenc(m2[h]));
        }
    }
}

// ---------------- fp32 SGEMM (small evidence-2 GEMM only) ----------------
#define BM 128
#define BN 128
#define BKK 16
template <int EPI>
__global__ __launch_bounds__(256, 2)
void k_sgemm(const float* __restrict__ A, int lda,
             const float* __restrict__ B, int ldb,
             float* __restrict__ C, int ldc,
             const float* __restrict__ bias,
             int M, int N, int K)
{
    __shared__ float As[BKK][BM + 4];
    __shared__ float Bs[BKK][BN];
    const int tid = threadIdx.x;
    const int m0 = blockIdx.y * BM;
    const int n0 = blockIdx.x * BN;
    const int tm = tid >> 4, tn = tid & 15;
    const int a_kk = tid & 15, a_m0 = tid >> 4;
    const int b_kk0 = tid >> 5, b_nb = (tid & 31) << 2;

    float acc[8][8];
#pragma unroll
    for (int i = 0; i < 8; i++)
#pragma unroll
        for (int j = 0; j < 8; j++) acc[i][j] = 0.f;

    float ra[8]; float4 rb[2];
    auto load_tiles = [&](int k0) {
#pragma unroll
        for (int i = 0; i < 8; i++) {
            int gm = m0 + a_m0 + 16 * i;
            ra[i] = (gm < M) ? A[(size_t)gm * lda + (k0 + a_kk)] : 0.f;
        }
#pragma unroll
        for (int i = 0; i < 2; i++) {
            int kk = b_kk0 + 8 * i;
            int gn = n0 + b_nb;
            float4 v = make_float4(0.f, 0.f, 0.f, 0.f);
            const float* bp = &B[(size_t)(k0 + kk) * ldb + b_nb];
            if (gn + 3 < N) v = *(const float4*)bp;
            else {
                if (gn     < N) v.x = bp[0];
                if (gn + 1 < N) v.y = bp[1];
                if (gn + 2 < N) v.z = bp[2];
            }
            rb[i] = v;
        }
    };
    auto store_tiles = [&]() {
#pragma unroll
        for (int i = 0; i < 8; i++) As[a_kk][a_m0 + 16 * i] = ra[i];
#pragma unroll
        for (int i = 0; i < 2; i++) *(float4*)&Bs[b_kk0 + 8 * i][b_nb] = rb[i];
    };
    auto compute = [&]() {
#pragma unroll
        for (int kk = 0; kk < BKK; kk++) {
            float a[8], b[8];
#pragma unroll
            for (int i = 0; i < 8; i++) a[i] = As[kk][tm * 8 + i];
#pragma unroll
            for (int j = 0; j < 8; j++) b[j] = Bs[kk][tn * 8 + j];
#pragma unroll
            for (int i = 0; i < 8; i++)
#pragma unroll
                for (int j = 0; j < 8; j++) acc[i][j] = fmaf(a[i], b[j], acc[i][j]);
        }
    };
    load_tiles(0); store_tiles(); __syncthreads();
    for (int k0 = BKK; k0 < K; k0 += BKK) {
        load_tiles(k0); compute(); __syncthreads(); store_tiles(); __syncthreads();
    }
    compute();
#pragma unroll
    for (int i = 0; i < 8; i++) {
        int gm = m0 + tm * 8 + i;
        if (gm < M) {
#pragma unroll
            for (int j = 0; j < 8; j++) {
                int gn = n0 + tn * 8 + j;
                if (gn < N) {
                    float v = acc[i][j];
                    if (bias) v += bias[gn];
                    if (EPI == 1) v = fmaxf(v, 0.f);
                    C[(size_t)gm * ldc + gn] = v;
                }
            }
        }
    }
}

// ---------------- attention projections + node maxima (layer 2 only) ----------------
__global__ void k_s1s2(const float* __restrict__ Wh, int ld, int F, int nh,
                       const float* __restrict__ a, int aStride,
                       float* __restrict__ s1, float* __restrict__ s2, int N,
                       int slot1, int slot2)
{
    int gw = (blockIdx.x * blockDim.x + threadIdx.x) >> 5;
    int lane = threadIdx.x & 31;
    if (gw >= N * nh) return;
    int node = gw / nh;
    int h = gw - node * nh;
    const float* wr = &Wh[(size_t)node * ld + h * F];
    const float* ah = &a[(size_t)h * aStride];
    float p1 = 0.f, p2 = 0.f;
    for (int j = lane; j < F; j += 32) {
        float x = wr[j];
        p1 = fmaf(x, ah[j], p1);
        p2 = fmaf(x, ah[F + j], p2);
    }
    p1 = wsumf(p1); p2 = wsumf(p2);
    if (lane == 0) {
        s1[(size_t)node * nh + h] = p1;
        s2[(size_t)node * nh + h] = p2;
        atomicMax(&g_maxenc[slot1 + h], fenc(p1));
        atomicMax(&g_maxenc[slot2 + h], fenc(p2));
    }
}

// ---------------- edge pass ----------------
template <int NH>
__global__ void k_expsum(const int* __restrict__ src, const int* __restrict__ tgt,
                         const float* __restrict__ s1, const float* __restrict__ s2,
                         float* __restrict__ w, int E, int sumslot, int m1, int m2)
{
    int e = blockIdx.x * blockDim.x + threadIdx.x;
    int tid = threadIdx.x;
    bool ok = (e < E);
    float Mh[NH];
#pragma unroll
    for (int h = 0; h < NH; h++) {
        float l = fdec(g_maxenc[m1 + h]) + fdec(g_maxenc[m2 + h]);
        Mh[h] = (l > 0.f) ? l : 0.2f * l;
    }
    float sv[NH];
    if (NH == 4) {
        float4 a = make_float4(0.f, 0.f, 0.f, 0.f), b = a;
        if (ok) {
            int s = src[e], t = tgt[e];
            a = *(const float4*)&s1[(size_t)s * 4];
            b = *(const float4*)&s2[(size_t)t * 4];
        }
        float lv[4] = { a.x + b.x, a.y + b.y, a.z + b.z, a.w + b.w };
#pragma unroll
        for (int h = 0; h < 4; h++) {
            float l = lv[h];
            l = (l > 0.f) ? l : 0.2f * l;
            float v = ok ? expf(l - Mh[h]) : 0.f;
            if (ok) w[(size_t)h * E + e] = v;
            sv[h] = v;
        }
    } else {
        float v = 0.f;
        if (ok) {
            int s = src[e], t = tgt[e];
            float l = s1[s] + s2[t];
            l = (l > 0.f) ? l : 0.2f * l;
            v = expf(l - Mh[0]);
            w[e] = v;
        }
        sv[0] = v;
    }
    __shared__ float red[NH * 8];
    int wi = tid >> 5, lane = tid & 31;
#pragma unroll
    for (int h = 0; h < NH; h++) {
        float v = wsumf(sv[h]);
        if (lane == 0) red[h * 8 + wi] = v;
    }
    __syncthreads();
    if (tid < 32) {
        float v = (tid < NH * 8) ? red[tid] : 0.f;
        v += __shfl_down_sync(0xffffffffu, v, 4);
        v += __shfl_down_sync(0xffffffffu, v, 2);
        v += __shfl_down_sync(0xffffffffu, v, 1);
        if ((tid & 7) == 0 && tid < NH * 8)
            atomicAdd(&g_sumexp[sumslot + (tid >> 3)], (double)v);
    }
}

__global__ void k_finalize(int slot0, int n)
{
    int i = threadIdx.x;
    if (i < n) g_invS[slot0 + i] = (float)(1.0 / g_sumexp[slot0 + i]);
}

// ---------------- CSR gather (layer 1): emit bf16-split xnew ----------------
__global__ __launch_bounds__(256, 8)
void k_gather1024(const int* __restrict__ src, const float* __restrict__ w,
                  const float* __restrict__ Wh,
                  __nv_bfloat16* __restrict__ xhi, __nv_bfloat16* __restrict__ xlo, int slot0)
{
    int node = blockIdx.x;
    int tid = threadIdx.x;
    int head = tid >> 6;
    int col = tid * 4;
    const float* wh = &w[(size_t)head * EE];

    int p = g_rowptr[node];
    const int end = g_rowptr[node + 1];

    int s_cur = 0; float c_cur = 0.f;
    if (p < end) { int e = g_eidx[p]; s_cur = src[e]; c_cur = wh[e]; }

    float4 acc = make_float4(0.f, 0.f, 0.f, 0.f);
    while (p < end) {
        int s_nxt = 0; float c_nxt = 0.f;
        if (p + 1 < end) { int e = g_eidx[p + 1]; s_nxt = src[e]; c_nxt = wh[e]; }
        float4 v = *(const float4*)&Wh[(size_t)s_cur * 1024 + col];
        acc.x = fmaf(c_cur, v.x, acc.x);
        acc.y = fmaf(c_cur, v.y, acc.y);
        acc.z = fmaf(c_cur, v.z, acc.z);
        acc.w = fmaf(c_cur, v.w, acc.w);
        s_cur = s_nxt; c_cur = c_nxt; p++;
    }
    float inv = g_invS[slot0 + head];
    acc.x *= inv; acc.y *= inv; acc.z *= inv; acc.w *= inv;
    __nv_bfloat16 hx, lx, hy, ly, hz, lz, hw, lw;
    bf16split(acc.x, hx, lx); bf16split(acc.y, hy, ly);
    bf16split(acc.z, hz, lz); bf16split(acc.w, hw, lw);
    size_t o = (size_t)node * 1024 + col;
    *(__nv_bfloat162*)&xhi[o]     = __nv_bfloat162(hx, hy);
    *(__nv_bfloat162*)&xhi[o + 2] = __nv_bfloat162(hz, hw);
    *(__nv_bfloat162*)&xlo[o]     = __nv_bfloat162(lx, ly);
    *(__nv_bfloat162*)&xlo[o + 2] = __nv_bfloat162(lz, lw);
}

__global__ __launch_bounds__(256, 8)
void k_gather128(const int* __restrict__ src, const float* __restrict__ w,
                 const float* __restrict__ Wh, float* __restrict__ xnew, int slot)
{
    int node = (blockIdx.x * blockDim.x + threadIdx.x) >> 5;
    int lane = threadIdx.x & 31;
    if (node >= NN) return;
    int col = lane * 4;

    int p = g_rowptr[node];
    const int end = g_rowptr[node + 1];

    int s_cur = 0; float c_cur = 0.f;
    if (p < end) { int e = g_eidx[p]; s_cur = src[e]; c_cur = w[e]; }

    float4 acc = make_float4(0.f, 0.f, 0.f, 0.f);
    while (p < end) {
        int s_nxt = 0; float c_nxt = 0.f;
        if (p + 1 < end) { int e = g_eidx[p + 1]; s_nxt = src[e]; c_nxt = w[e]; }
        float4 v = *(const float4*)&Wh[(size_t)s_cur * 128 + col];
        acc.x = fmaf(c_cur, v.x, acc.x);
        acc.y = fmaf(c_cur, v.y, acc.y);
        acc.z = fmaf(c_cur, v.z, acc.z);
        acc.w = fmaf(c_cur, v.w, acc.w);
        s_cur = s_nxt; c_cur = c_nxt; p++;
    }
    float inv = g_invS[slot];
    acc.x *= inv; acc.y *= inv; acc.z *= inv; acc.w *= inv;
    *(float4*)&xnew[(size_t)node * 128 + col] = acc;
}

// ---------------- evidence heads ----------------
__global__ void k_evid1(const float* __restrict__ hbuf, const float* __restrict__ w2,
                        const float* __restrict__ b2, float* __restrict__ evsum, int N)
{
    int gw = (blockIdx.x * blockDim.x + threadIdx.x) >> 5;
    int lane = threadIdx.x & 31;
    if (gw >= N) return;
    float e0 = 0.f, e1 = 0.f, e2 = 0.f;
#pragma unroll
    for (int h = 0; h < NHEAD; h++) {
        float4 v = *(const float4*)&hbuf[(size_t)gw * 512 + h * 128 + lane * 4];
        const float* wc = &w2[h * 384 + lane * 12];
        float a0 = v.x * wc[0] + v.y * wc[3] + v.z * wc[6] + v.w * wc[9];
        float a1 = v.x * wc[1] + v.y * wc[4] + v.z * wc[7] + v.w * wc[10];
        float a2 = v.x * wc[2] + v.y * wc[5] + v.z * wc[8] + v.w * wc[11];
        a0 = wsumf(a0); a1 = wsumf(a1); a2 = wsumf(a2);
        e0 += softplusf(a0 + b2[h * 3 + 0]) + 1.f;
        e1 += softplusf(a1 + b2[h * 3 + 1]) + 1.f;
        e2 += softplusf(a2 + b2[h * 3 + 2]) + 1.f;
    }
    if (lane == 0) {
        evsum[gw * 3 + 0] = e0; evsum[gw * 3 + 1] = e1; evsum[gw * 3 + 2] = e2;
    }
}

__global__ void k_evid2(const float* __restrict__ hbuf, const float* __restrict__ w2,
                        const float* __restrict__ b2, const float* __restrict__ evsum,
                        float* __restrict__ out, int N)
{
    int gw = (blockIdx.x * blockDim.x + threadIdx.x) >> 5;
    int lane = threadIdx.x & 31;
    if (gw >= N) return;
    float2 v = *(const float2*)&hbuf[(size_t)gw * 64 + lane * 2];
    const float* wc = &w2[lane * 6];
    float a0 = v.x * wc[0] + v.y * wc[3];
    float a1 = v.x * wc[1] + v.y * wc[4];
    float a2 = v.x * wc[2] + v.y * wc[5];
    a0 = wsumf(a0); a1 = wsumf(a1); a2 = wsumf(a2);
    if (lane == 0) {
        float e0 = softplusf(a0 + b2[0]) + 1.f;
        float e1 = softplusf(a1 + b2[1]) + 1.f;
        float e2 = softplusf(a2 + b2[2]) + 1.f;
        out[(size_t)gw * 3 + 0] = (evsum[gw * 3 + 0] * 0.25f + e0) * 0.5f;
        out[(size_t)gw * 3 + 1] = (evsum[gw * 3 + 1] * 0.25f + e1) * 0.5f;
        out[(size_t)gw * 3 + 2] = (evsum[gw * 3 + 2] * 0.25f + e2) * 0.5f;
    }
}

// ---------------- LayerNorm + ELU ----------------
// SPLIT=true: also write bf16 hi/lo (for h1).
template <int F, bool SPLIT>
__global__ void k_ln_elu(const float* __restrict__ in, float* __restrict__ out,
                         __nv_bfloat16* __restrict__ ohi, __nv_bfloat16* __restrict__ olo,
                         const float* __restrict__ gam, const float* __restrict__ bet, int N)
{
    int gw = (blockIdx.x * blockDim.x + threadIdx.x) >> 5;
    int lane = threadIdx.x & 31;
    if (gw >= N) return;
    constexpr int R = F / 32;
    float v[R];
    const float* ir = &in[(size_t)gw * F];
#pragma unroll
    for (int r = 0; r < R; r++) v[r] = ir[lane + 32 * r];
    float s = 0.f;
#pragma unroll
    for (int r = 0; r < R; r++) s += v[r];
    s = wsumf(s);
    float mean = s * (1.f / F);
    float q = 0.f;
#pragma unroll
    for (int r = 0; r < R; r++) { float d = v[r] - mean; q = fmaf(d, d, q); }
    q = wsumf(q);
    float rstd = rsqrtf(q * (1.f / F) + 1e-5f);
#pragma unroll
    for (int r = 0; r < R; r++) {
        int j = lane + 32 * r;
        float y = (v[r] - mean) * rstd * gam[j] + bet[j];
        y = eluf(y);
        if (SPLIT) {
            __nv_bfloat16 hi, lo;
            bf16split(y, hi, lo);
            ohi[(size_t)gw * F + j] = hi;
            olo[(size_t)gw * F + j] = lo;
        } else {
            out[(size_t)gw * F + j] = y;
        }
    }
}

// ---------------- launch ----------------
extern "C" void kernel_launch(void* const* d_in, const int* in_sizes, int n_in,
                              void* d_out, int out_size)
{
    (void)in_sizes; (void)n_in; (void)out_size;

    const float* x        = (const float*)d_in[0];
    const int*   ei       = (const int*)  d_in[1];
    const float* W_heads  = (const float*)d_in[2];
    const float* a_heads  = (const float*)d_in[3];
    const float* ev1w_h   = (const float*)d_in[4];
    const float* ev1b_h   = (const float*)d_in[5];
    const float* ev2w_h   = (const float*)d_in[6];
    const float* ev2b_h   = (const float*)d_in[7];
    const float* agg_w    = (const float*)d_in[8];
    const float* agg_b    = (const float*)d_in[9];
    const float* ln1_g    = (const float*)d_in[10];
    const float* ln1_b    = (const float*)d_in[11];
    const float* W2       = (const float*)d_in[12];
    const float* a2       = (const float*)d_in[13];
    const float* ev1w2    = (const float*)d_in[14];
    const float* ev1b2    = (const float*)d_in[15];
    const float* ev2w2    = (const float*)d_in[16];
    const float* ev2b2    = (const float*)d_in[17];
    const float* ln2_g    = (const float*)d_in[18];
    const float* ln2_b    = (const float*)d_in[19];
    const float* res_w    = (const float*)d_in[20];
    const float* res_b    = (const float*)d_in[21];

    const int* src = ei;
    const int* tgt = ei + EE;

    float* out_x  = (float*)d_out;
    float* out_ev = (float*)d_out + (size_t)NN * DOUT;

    float *Wh, *s1, *s2, *wbuf, *w2e, *hbuf, *evsum, *h1, *Wh2, *s1b, *s2b, *xnew2, *x2;
    __nv_bfloat16 *xhi, *xlo, *xnhi, *xnlo, *h1hi, *h1lo;
    __nv_bfloat16 *bt1hi, *bt1lo, *btahi, *btalo, *btehi, *btelo, *btw2hi, *btw2lo, *btrhi, *btrlo;
    cudaGetSymbolAddress((void**)&Wh,    g_Wh);
    cudaGetSymbolAddress((void**)&s1,    g_s1);
    cudaGetSymbolAddress((void**)&s2,    g_s2);
    cudaGetSymbolAddress((void**)&wbuf,  g_w);
    cudaGetSymbolAddress((void**)&w2e,   g_w2e);
    cudaGetSymbolAddress((void**)&hbuf,  g_hbuf);
    cudaGetSymbolAddress((void**)&evsum, g_evsum);
    cudaGetSymbolAddress((void**)&h1,    g_h1);
    cudaGetSymbolAddress((void**)&Wh2,   g_Wh2);
    cudaGetSymbolAddress((void**)&s1b,   g_s1b);
    cudaGetSymbolAddress((void**)&s2b,   g_s2b);
    cudaGetSymbolAddress((void**)&xnew2, g_xnew2);
    cudaGetSymbolAddress((void**)&x2,    g_x2);
    cudaGetSymbolAddress((void**)&xhi,   g_xhi);
    cudaGetSymbolAddress((void**)&xlo,   g_xlo);
    cudaGetSymbolAddress((void**)&xnhi,  g_xnhi);
    cudaGetSymbolAddress((void**)&xnlo,  g_xnlo);
    cudaGetSymbolAddress((void**)&h1hi,  g_h1hi);
    cudaGetSymbolAddress((void**)&h1lo,  g_h1lo);
    cudaGetSymbolAddress((void**)&bt1hi, g_bt1hi);
    cudaGetSymbolAddress((void**)&bt1lo, g_bt1lo);
    cudaGetSymbolAddress((void**)&btahi, g_btahi);
    cudaGetSymbolAddress((void**)&btalo, g_btalo);
    cudaGetSymbolAddress((void**)&btehi, g_btehi);
    cudaGetSymbolAddress((void**)&btelo, g_btelo);
    cudaGetSymbolAddress((void**)&btw2hi, g_btw2hi);
    cudaGetSymbolAddress((void**)&btw2lo, g_btw2lo);
    cudaGetSymbolAddress((void**)&btrhi, g_btrhi);
    cudaGetSymbolAddress((void**)&btrlo, g_btrlo);

    cudaFuncSetAttribute(k_mma<0>, cudaFuncAttributeMaxDynamicSharedMemorySize, MMA_SMEM);
    cudaFuncSetAttribute(k_mma<1>, cudaFuncAttributeMaxDynamicSharedMemorySize, MMA_SMEM);
    cudaFuncSetAttribute(k_mma<2>, cudaFuncAttributeMaxDynamicSharedMemorySize, MMA_SMEM);
    cudaFuncSetAttribute(k_mma<3>, cudaFuncAttributeMaxDynamicSharedMemorySize, MMA_SMEM);

    const int MB = (NN + 127) / 128;   // 235

    // launches 1-3, then #4 = big G1 k_mma (ncu captures launch #4)
    k_btall<<<BT_BLOCKS + INIT_BLOCKS, 256>>>(W_heads, agg_w, ev1w_h, W2, res_w);
    k_hist<<<(EE + 255) / 256, 256>>>(tgt);
    k_split<<<(NN * DIN / 4 + 255) / 256, 256>>>(x, xhi, xlo, NN * DIN / 4);

    // #4: Wh = x @ W_heads, with fused s1/s2 attention projections
    k_mma<3><<<dim3(8, MB), 256, MMA_SMEM>>>(xhi, xlo, DIN, 0, 128, bt1hi, bt1lo,
                                             Wh, 1024, nullptr, nullptr, 0, NN, DIN,
                                             s1, s2, a_heads);

    // CSR scan/fill, node maxima, edge pass, softmax scale
    k_scan<<<1, 1024>>>();
    k_fill<<<(EE + 255) / 256, 256>>>(tgt);
    k_nodemax<<<(NN + 255) / 256, 256>>>(s1, s2);
    k_expsum<NHEAD><<<(EE + 255) / 256, 256>>>(src, tgt, s1, s2, wbuf, EE, 0, 0, 4);
    k_finalize<<<1, 8>>>(0, NHEAD);

    // CSR gather -> split xnew
    k_gather1024<<<NN, 256>>>(src, wbuf, Wh, xnhi, xnlo, 0);

    // evidence layer 1 (block-diagonal, relu) + fused head
    k_mma<1><<<dim3(4, MB), 256, MMA_SMEM>>>(xnhi, xnlo, 1024, DH, 128, btehi, btelo,
                                             hbuf, 512, ev1b_h, nullptr, 0, NN, DH,
                                             nullptr, nullptr, nullptr);
    k_evid1<<<NN / 8, 256>>>(hbuf, ev2w_h, ev2b_h, evsum, NN);

    // h1 = elu(LN(x_cat @ agg_w + agg_b)) -> split h1
    k_mma<0><<<dim3(2, MB), 256, MMA_SMEM>>>(xnhi, xnlo, 1024, 0, 128, btahi, btalo,
                                             h1, DH, agg_b, nullptr, 0, NN, 1024,
                                             nullptr, nullptr, nullptr);
    k_ln_elu<DH, true><<<NN / 8, 256>>>(h1, nullptr, h1hi, h1lo, ln1_g, ln1_b, NN);

    // layer-2 GAT
    k_mma<0><<<dim3(1, MB), 256, MMA_SMEM>>>(h1hi, h1lo, DH, 0, 128, btw2hi, btw2lo,
                                             Wh2, DOUT, nullptr, nullptr, 0, NN, DH,
                                             nullptr, nullptr, nullptr);
    k_s1s2<<<NN / 8, 256>>>(Wh2, DOUT, DOUT, 1, a2, 2 * DOUT, s1b, s2b, NN, 8, 9);
    k_expsum<1><<<(EE + 255) / 256, 256>>>(src, tgt, s1b, s2b, w2e, EE, 4, 8, 9);
    k_finalize<<<1, 8>>>(4, 1);
    k_gather128<<<(NN * 32 + 255) / 256, 256>>>(src, w2e, Wh2, xnew2, 4);

    // evidence layer 2 + final combine
    k_sgemm<1><<<dim3(1, MB), 256>>>(xnew2, DOUT, ev1w2, DOUT / 2, hbuf, DOUT / 2,
                                     ev1b2, NN, DOUT / 2, DOUT);
    k_evid2<<<NN / 8, 256>>>(hbuf, ev2w2, ev2b2, evsum, out_ev, NN);

    // x2 = elu(LN(x_new2)); x_out = x2 + h1 @ res_w + res_b
    k_ln_elu<DOUT, false><<<NN / 8, 256>>>(xnew2, x2, nullptr, nullptr, ln2_g, ln2_b, NN);
    k_mma<2><<<dim3(1, MB), 256, MMA_SMEM>>>(h1hi, h1lo, DH, 0, 128, btrhi, btrlo,
                                             out_x, DOUT, res_b, x2, DOUT, NN, DH,
                                             nullptr, nullptr, nullptr);
}

// round 17
// speedup vs baseline: 1.2322x; 1.0068x over previous
#include <cuda_runtime.h>
#include <cuda_bf16.h>
#include <math.h>
#include <stdint.h>

// ---------------- problem constants ----------------
#define NN   30000
#define EE   480000
#define DIN  768
#define DH   256    // HID
#define DOUT 128    // OUT
#define NHEAD 4
#define NCLS 3

// ---------------- scratch (static device memory; no allocations) ----------------
__device__ float    g_Wh   [(size_t)NN * (NHEAD * DH)];
__device__ __align__(16) float g_s1 [NHEAD * NN];   // interleaved [node][head]
__device__ __align__(16) float g_s2 [NHEAD * NN];
__device__ float    g_w    [(size_t)NHEAD * EE];
__device__ float    g_w2e  [EE];
__device__ float    g_hbuf [(size_t)NN * 512];
__device__ float    g_evsum[NN * NCLS];
__device__ float    g_h1   [(size_t)NN * DH];
__device__ float    g_Wh2  [(size_t)NN * DOUT];
__device__ float    g_s1b  [NN];
__device__ float    g_s2b  [NN];
__device__ float    g_xnew2[(size_t)NN * DOUT];
__device__ float    g_x2   [(size_t)NN * DOUT];
__device__ unsigned g_maxenc[12];
__device__ double   g_sumexp[8];
__device__ float    g_invS  [8];

// CSR (edges grouped by tgt)
__device__ int g_rowptr[NN + 1];
__device__ int g_cursor[NN];
__device__ int g_eidx  [EE];

// pre-split bf16 A operands (hi/lo)
__device__ __align__(256) __nv_bfloat16 g_xhi [(size_t)NN * DIN],  g_xlo [(size_t)NN * DIN];
__device__ __align__(256) __nv_bfloat16 g_xnhi[(size_t)NN * 1024], g_xnlo[(size_t)NN * 1024];
__device__ __align__(256) __nv_bfloat16 g_h1hi[(size_t)NN * DH],   g_h1lo[(size_t)NN * DH];

// transposed + bf16-split weights (Bt[n][k], K-major)
__device__ __align__(256) __nv_bfloat16 g_bt1hi [1024 * 768], g_bt1lo [1024 * 768];
__device__ __align__(256) __nv_bfloat16 g_btahi [256 * 1024], g_btalo [256 * 1024];
__device__ __align__(256) __nv_bfloat16 g_btehi [512 * 256],  g_btelo [512 * 256];
__device__ __align__(256) __nv_bfloat16 g_btw2hi[128 * 256],  g_btw2lo[128 * 256];
__device__ __align__(256) __nv_bfloat16 g_btrhi [128 * 256],  g_btrlo [128 * 256];

// ---------------- helpers ----------------
__device__ __forceinline__ unsigned fenc(float f) {
    unsigned u = __float_as_uint(f);
    return (u & 0x80000000u) ? ~u : (u | 0x80000000u);
}
__device__ __forceinline__ float fdec(unsigned u) {
    return (u & 0x80000000u) ? __uint_as_float(u & 0x7fffffffu) : __uint_as_float(~u);
}
__device__ __forceinline__ float wsumf(float v) {
#pragma unroll
    for (int o = 16; o > 0; o >>= 1) v += __shfl_xor_sync(0xffffffffu, v, o);
    return v;
}
__device__ __forceinline__ float wmaxf(float v) {
#pragma unroll
    for (int o = 16; o > 0; o >>= 1) v = fmaxf(v, __shfl_xor_sync(0xffffffffu, v, o));
    return v;
}
__device__ __forceinline__ float softplusf(float x) {
    return fmaxf(x, 0.f) + log1pf(expf(-fabsf(x)));
}
__device__ __forceinline__ float eluf(float x) {
    return x > 0.f ? x : expm1f(x);
}
__device__ __forceinline__ void bf16split(float x, __nv_bfloat16& hi, __nv_bfloat16& lo) {
    hi = __float2bfloat16(x);
    lo = __float2bfloat16(x - __bfloat162float(hi));
}
__device__ __forceinline__ uint32_t smem_u32(const void* p) {
    uint32_t a;
    asm("{ .reg .u64 t; cvta.to.shared.u64 t, %1; cvt.u32.u64 %0, t; }" : "=r"(a) : "l"(p));
    return a;
}
__device__ __forceinline__ void cp16(uint32_t dst, const void* src, bool valid) {
    asm volatile("cp.async.cg.shared.global [%0], [%1], 16, %2;"
                 :: "r"(dst), "l"(src), "r"(valid ? 16u : 0u) : "memory");
}
__device__ __forceinline__ void cp_commit() {
    asm volatile("cp.async.commit_group;" ::: "memory");
}
__device__ __forceinline__ void cp_wait0() {
    asm volatile("cp.async.wait_group 0;" ::: "memory");
}
__device__ __forceinline__ void cp_wait1() {
    asm volatile("cp.async.wait_group 1;" ::: "memory");
}
__device__ __forceinline__ void ldsm_x4(uint32_t* r, uint32_t addr) {
    asm volatile("ldmatrix.sync.aligned.m8n8.x4.shared.b16 {%0,%1,%2,%3}, [%4];"
                 : "=r"(r[0]), "=r"(r[1]), "=r"(r[2]), "=r"(r[3]) : "r"(addr));
}
__device__ __forceinline__ void ldsm_x2(uint32_t* r, uint32_t addr) {
    asm volatile("ldmatrix.sync.aligned.m8n8.x2.shared.b16 {%0,%1}, [%2];"
                 : "=r"(r[0]), "=r"(r[1]) : "r"(addr));
}

// mma.sync m16n8k16 bf16 (row.col), fp32 accumulate — compiles on plain sm_103.
__device__ __forceinline__ void mma_bf16(float* c, const uint32_t* a, const uint32_t* b) {
    asm volatile(
        "mma.sync.aligned.m16n8k16.row.col.f32.bf16.bf16.f32 "
        "{%0,%1,%2,%3}, {%4,%5,%6,%7}, {%8,%9}, {%0,%1,%2,%3};"
        : "+f"(c[0]), "+f"(c[1]), "+f"(c[2]), "+f"(c[3])
        : "r"(a[0]), "r"(a[1]), "r"(a[2]), "r"(a[3]), "r"(b[0]), "r"(b[1]));
}

// ---------------- fused: B transpose/split + init tail ----------------
#define BT_BLOCKS 4864
#define INIT_BLOCKS 1056
__global__ void k_btall(const float* w1, const float* wa, const float* we,
                        const float* w2, const float* wr)
{
    int b = blockIdx.x;
    if (b >= BT_BLOCKS) {
        int ib = b - BT_BLOCKS;
        if (ib < 118) {
            int i = ib * 256 + threadIdx.x;
            if (i <= NN) g_rowptr[i] = 0;
            if (ib == 0) {
                if (threadIdx.x < 12) g_maxenc[threadIdx.x] = 0u;
                if (threadIdx.x < 8)  { g_sumexp[threadIdx.x] = 0.0; g_invS[threadIdx.x] = 0.f; }
            }
        } else if (ib < 587) {
            int i = (ib - 118) * 256 + threadIdx.x;
            if (i < NHEAD * NN) g_s1[i] = 0.f;
        } else {
            int i = (ib - 587) * 256 + threadIdx.x;
            if (i < NHEAD * NN) g_s2[i] = 0.f;
        }
        return;
    }
    const float* src; __nv_bfloat16 *hi, *lo;
    int K, headN, headStride, base;
    if (b < 3072)      { src = w1; hi = g_bt1hi;  lo = g_bt1lo;  K = 768;  headN = 256; headStride = 768 * 256; base = 0; }
    else if (b < 4096) { src = wa; hi = g_btahi;  lo = g_btalo;  K = 1024; headN = 256; headStride = 0;         base = 3072; }
    else if (b < 4608) { src = we; hi = g_btehi;  lo = g_btelo;  K = 256;  headN = 128; headStride = 256 * 128; base = 4096; }
    else if (b < 4736) { src = w2; hi = g_btw2hi; lo = g_btw2lo; K = 256;  headN = 128; headStride = 0;         base = 4608; }
    else               { src = wr; hi = g_btrhi;  lo = g_btrlo;  K = 256;  headN = 128; headStride = 0;         base = 4736; }
    int idx = (b - base) * 256 + threadIdx.x;
    int n = idx / K, k = idx - n * K;
    int head = n / headN, nloc = n - head * headN;
    float v = src[(size_t)head * headStride + (size_t)k * headN + nloc];
    __nv_bfloat16 h, l;
    bf16split(v, h, l);
    hi[idx] = h;
    lo[idx] = l;
}

// ---------------- A split: fp32 -> bf16 hi/lo ----------------
__global__ void k_split(const float* __restrict__ src, __nv_bfloat16* __restrict__ hi,
                        __nv_bfloat16* __restrict__ lo, int n4)
{
    int i = blockIdx.x * blockDim.x + threadIdx.x;
    if (i >= n4) return;
    float4 v = ((const float4*)src)[i];
    __nv_bfloat16 hx, lx, hy, ly, hz, lz, hw, lw;
    bf16split(v.x, hx, lx); bf16split(v.y, hy, ly);
    bf16split(v.z, hz, lz); bf16split(v.w, hw, lw);
    ((__nv_bfloat162*)hi)[2 * i]     = __nv_bfloat162(hx, hy);
    ((__nv_bfloat162*)hi)[2 * i + 1] = __nv_bfloat162(hz, hw);
    ((__nv_bfloat162*)lo)[2 * i]     = __nv_bfloat162(lx, ly);
    ((__nv_bfloat162*)lo)[2 * i + 1] = __nv_bfloat162(lz, lw);
}

// ---------------- CSR build ----------------
__global__ void k_hist(const int* __restrict__ tgt) {
    int e = blockIdx.x * blockDim.x + threadIdx.x;
    if (e < EE) atomicAdd(&g_rowptr[tgt[e] + 1], 1);
}

__global__ void k_scan() {
    __shared__ int warp_tot[32];
    int tid = threadIdx.x;
    int lane = tid & 31, wi = tid >> 5;
    const int CH = (NN + 1023) / 1024;
    int beg = tid * CH;
    int end = beg + CH; if (end > NN) end = NN;
    int s = 0;
    for (int i = beg; i < end; i++) s += g_rowptr[i + 1];
    int v = s;
#pragma unroll
    for (int o = 1; o < 32; o <<= 1) {
        int u = __shfl_up_sync(0xffffffffu, v, o);
        if (lane >= o) v += u;
    }
    if (lane == 31) warp_tot[wi] = v;
    __syncthreads();
    if (wi == 0) {
        int w = warp_tot[lane];
#pragma unroll
        for (int o = 1; o < 32; o <<= 1) {
            int u = __shfl_up_sync(0xffffffffu, w, o);
            if (lane >= o) w += u;
        }
        warp_tot[lane] = w;
    }
    __syncthreads();
    int run = v - s + (wi > 0 ? warp_tot[wi - 1] : 0);
    for (int i = beg; i < end; i++) {
        int c = g_rowptr[i + 1];
        g_cursor[i] = run;
        run += c;
        g_rowptr[i + 1] = run;
    }
    if (tid == 0) g_rowptr[0] = 0;
}

__global__ void k_fill(const int* __restrict__ tgt) {
    int e = blockIdx.x * blockDim.x + threadIdx.x;
    if (e < EE) {
        int p = atomicAdd(&g_cursor[tgt[e]], 1);
        g_eidx[p] = e;
    }
}

// ---------------- bf16-split tensor-core GEMM, cp.async 2-stage, ldmatrix frags ----------------
// EPI: 0 = (+bias); 1 = relu(+bias); 2 = +bias +addend; 3 = store + fused s1/s2 projections.
#define ASTR 40
#define TILE_B (128 * ASTR * 2)    // 10240 B
#define BUF_B  (4 * TILE_B)        // 40960 B
#define NSTAGE 2
#define MMA_SMEM (NSTAGE * BUF_B)  // 81920 B -> 2 CTAs/SM

template <int EPI>
__global__ __launch_bounds__(256, 2)
void k_mma(const __nv_bfloat16* __restrict__ Ahi, const __nv_bfloat16* __restrict__ Alo,
           int lda, int aHeadStep, int headN,
           const __nv_bfloat16* __restrict__ Bthi, const __nv_bfloat16* __restrict__ Btlo,
           float* __restrict__ C, int ldc,
           const float* __restrict__ bias,
           const float* __restrict__ addend, int ldadd,
           int M, int K,
           float* __restrict__ s1o, float* __restrict__ s2o,
           const float* __restrict__ attA)
{
    extern __shared__ __align__(16) char smraw[];
    const uint32_t sbase = smem_u32(smraw);

    const int tid = threadIdx.x;
    const int lane = tid & 31;
    const int wid = tid >> 5;
    const int warp_m = wid & 1;
    const int warp_n = wid >> 1;
    const int g  = lane >> 2;
    const int tg = lane & 3;

    const int m0 = blockIdx.y * 128;
    const int n0 = blockIdx.x * 128;
    const size_t aOff = (size_t)(n0 / headN) * aHeadStep;

    // cp.async coords
    const int row0 = tid >> 2, ch = tid & 3;
    const int row1 = row0 + 64;
    const bool vm0 = (m0 + row0) < M;
    const bool vm1 = (m0 + row1) < M;
    const int gm0 = vm0 ? (m0 + row0) : 0;
    const int gm1 = vm1 ? (m0 + row1) : 0;

    const char* pAh0 = (const char*)&Ahi[aOff + (size_t)gm0 * lda] + ch * 16;
    const char* pAl0 = (const char*)&Alo[aOff + (size_t)gm0 * lda] + ch * 16;
    const char* pAh1 = (const char*)&Ahi[aOff + (size_t)gm1 * lda] + ch * 16;
    const char* pAl1 = (const char*)&Alo[aOff + (size_t)gm1 * lda] + ch * 16;
    const char* pBh0 = (const char*)&Bthi[(size_t)(n0 + row0) * K] + ch * 16;
    const char* pBl0 = (const char*)&Btlo[(size_t)(n0 + row0) * K] + ch * 16;
    const char* pBh1 = (const char*)&Bthi[(size_t)(n0 + row1) * K] + ch * 16;
    const char* pBl1 = (const char*)&Btlo[(size_t)(n0 + row1) * K] + ch * 16;
    const uint32_t so0 = row0 * (ASTR * 2) + ch * 16;
    const uint32_t so1 = row1 * (ASTR * 2) + ch * 16;

    auto issue = [&](int t, int s) {
        size_t go = (size_t)t * 64;
        uint32_t sb = sbase + s * BUF_B;
        cp16(sb + so0,              pAh0 + go, vm0);
        cp16(sb + TILE_B + so0,     pAl0 + go, vm0);
        cp16(sb + 2 * TILE_B + so0, pBh0 + go, true);
        cp16(sb + 3 * TILE_B + so0, pBl0 + go, true);
        cp16(sb + so1,              pAh1 + go, vm1);
        cp16(sb + TILE_B + so1,     pAl1 + go, vm1);
        cp16(sb + 2 * TILE_B + so1, pBh1 + go, true);
        cp16(sb + 3 * TILE_B + so1, pBl1 + go, true);
        cp_commit();
    };

    float acc[4][4][4];
#pragma unroll
    for (int i = 0; i < 4; i++)
#pragma unroll
        for (int j = 0; j < 4; j++)
#pragma unroll
            for (int k = 0; k < 4; k++) acc[i][j][k] = 0.f;

    // ldmatrix per-lane address components (element units, x2 for bytes)
    // A x4: lane provides row (lane&15) of [rows0-15], k-half (lane>>4)*8
    const uint32_t aLdRow = (uint32_t)(warp_m * 64 + (lane & 15));
    const uint32_t aLdCol = (uint32_t)((lane >> 4) * 8);
    // B x2: lanes 0-7 matrix0 (k0-7), 8-15 matrix1 (k8-15); clamp lane to 0-15 for valid addrs
    const uint32_t bLdRow = (uint32_t)(warp_n * 32 + (lane & 7));
    const uint32_t bLdCol = (uint32_t)(((lane >> 3) & 1) * 8);

    auto compute = [&](int s) {
        const uint32_t sb = sbase + s * BUF_B;
        const uint32_t aHiB = sb;
        const uint32_t aLoB = sb + TILE_B;
        const uint32_t bHiB = sb + 2 * TILE_B;
        const uint32_t bLoB = sb + 3 * TILE_B;
#pragma unroll
        for (int kc = 0; kc < 32; kc += 16) {
            uint32_t ah[4][4], al[4][4];
#pragma unroll
            for (int mt = 0; mt < 4; mt++) {
                uint32_t off = (((aLdRow + mt * 16) * ASTR) + kc + aLdCol) << 1;
                ldsm_x4(ah[mt], aHiB + off);
                ldsm_x4(al[mt], aLoB + off);
            }
            uint32_t bh[4][2], bl[4][2];
#pragma unroll
            for (int nt = 0; nt < 4; nt++) {
                uint32_t off = (((bLdRow + nt * 8) * ASTR) + kc + bLdCol) << 1;
                ldsm_x2(bh[nt], bHiB + off);
                ldsm_x2(bl[nt], bLoB + off);
            }
#pragma unroll
            for (int mt = 0; mt < 4; mt++)
#pragma unroll
                for (int nt = 0; nt < 4; nt++) {
                    mma_bf16(acc[mt][nt], ah[mt], bh[nt]);
                    mma_bf16(acc[mt][nt], ah[mt], bl[nt]);
                    mma_bf16(acc[mt][nt], al[mt], bh[nt]);
                }
        }
    };

    const int T = K / 32;
    issue(0, 0);
    for (int t = 0; t < T; t++) {
        if (t + 1 < T) { issue(t + 1, (t + 1) & 1); cp_wait1(); }
        else           { cp_wait0(); }
        __syncthreads();
        compute(t & 1);
        __syncthreads();
    }

    // epilogue: store C
#pragma unroll
    for (int mt = 0; mt < 4; mt++) {
        int r0 = m0 + warp_m * 64 + mt * 16 + g;
#pragma unroll
        for (int nt = 0; nt < 4; nt++) {
            int gc = n0 + warp_n * 32 + nt * 8 + tg * 2;
            float2 v01 = make_float2(acc[mt][nt][0], acc[mt][nt][1]);
            float2 v23 = make_float2(acc[mt][nt][2], acc[mt][nt][3]);
            if (bias) {
                float2 b = *(const float2*)&bias[gc];
                v01.x += b.x; v01.y += b.y;
                v23.x += b.x; v23.y += b.y;
            }
            if (EPI == 1) {
                v01.x = fmaxf(v01.x, 0.f); v01.y = fmaxf(v01.y, 0.f);
                v23.x = fmaxf(v23.x, 0.f); v23.y = fmaxf(v23.y, 0.f);
            }
            if (r0 < M) {
                if (EPI == 2) {
                    float2 adx = *(const float2*)&addend[(size_t)r0 * ldadd + gc];
                    v01.x += adx.x; v01.y += adx.y;
                }
                *(float2*)&C[(size_t)r0 * ldc + gc] = v01;
            }
            if (r0 + 8 < M) {
                if (EPI == 2) {
                    float2 adx = *(const float2*)&addend[(size_t)(r0 + 8) * ldadd + gc];
                    v23.x += adx.x; v23.y += adx.y;
                }
                *(float2*)&C[(size_t)(r0 + 8) * ldc + gc] = v23;
            }
        }
    }

    // fused layer-1 attention projections
    if (EPI == 3) {
        const int h = n0 >> 8;
        const int cbase = (n0 & 255) + warp_n * 32 + tg * 2;
        float a1v[8], a2v[8];
#pragma unroll
        for (int nt = 0; nt < 4; nt++) {
            int c = cbase + nt * 8;
            a1v[nt * 2]     = attA[h * 512 + c];
            a1v[nt * 2 + 1] = attA[h * 512 + c + 1];
            a2v[nt * 2]     = attA[h * 512 + 256 + c];
            a2v[nt * 2 + 1] = attA[h * 512 + 256 + c + 1];
        }
#pragma unroll
        for (int mt = 0; mt < 4; mt++) {
            int r0 = m0 + warp_m * 64 + mt * 16 + g;
            float p1a = 0.f, p2a = 0.f, p1b = 0.f, p2b = 0.f;
#pragma unroll
            for (int nt = 0; nt < 4; nt++) {
                p1a = fmaf(acc[mt][nt][0], a1v[nt * 2], p1a);
                p1a = fmaf(acc[mt][nt][1], a1v[nt * 2 + 1], p1a);
                p2a = fmaf(acc[mt][nt][0], a2v[nt * 2], p2a);
                p2a = fmaf(acc[mt][nt][1], a2v[nt * 2 + 1], p2a);
                p1b = fmaf(acc[mt][nt][2], a1v[nt * 2], p1b);
                p1b = fmaf(acc[mt][nt][3], a1v[nt * 2 + 1], p1b);
                p2b = fmaf(acc[mt][nt][2], a2v[nt * 2], p2b);
                p2b = fmaf(acc[mt][nt][3], a2v[nt * 2 + 1], p2b);
            }
            p1a += __shfl_xor_sync(0xffffffffu, p1a, 1);
            p1a += __shfl_xor_sync(0xffffffffu, p1a, 2);
            p2a += __shfl_xor_sync(0xffffffffu, p2a, 1);
            p2a += __shfl_xor_sync(0xffffffffu, p2a, 2);
            p1b += __shfl_xor_sync(0xffffffffu, p1b, 1);
            p1b += __shfl_xor_sync(0xffffffffu, p1b, 2);
            p2b += __shfl_xor_sync(0xffffffffu, p2b, 1);
            p2b += __shfl_xor_sync(0xffffffffu, p2b, 2);
            if (tg == 0) {
                if (r0 < M) {
                    atomicAdd(&s1o[r0 * 4 + h], p1a);
                    atomicAdd(&s2o[r0 * 4 + h], p2a);
                }
                if (r0 + 8 < M) {
                    atomicAdd(&s1o[(r0 + 8) * 4 + h], p1b);
                    atomicAdd(&s2o[(r0 + 8) * 4 + h], p2b);
                }
            }
        }
    }
}

// ---------------- node maxima from final s1/s2 (layer 1) ----------------
__global__ void k_nodemax(const float* __restrict__ s1, const float* __restrict__ s2)
{
    int node = blockIdx.x * blockDim.x + threadIdx.x;
    float4 v1 = make_float4(-3e38f, -3e38f, -3e38f, -3e38f), v2 = v1;
    if (node < NN) {
        v1 = *(const float4*)&s1[node * 4];
        v2 = *(const float4*)&s2[node * 4];
    }
    float m1[4] = { v1.x, v1.y, v1.z, v1.w };
    float m2[4] = { v2.x, v2.y, v2.z, v2.w };
#pragma unroll
    for (int h = 0; h < 4; h++) { m1[h] = wmaxf(m1[h]); m2[h] = wmaxf(m2[h]); }
    if ((threadIdx.x & 31) == 0) {
#pragma unroll
        for (int h = 0; h < 4; h++) {
            atomicMax(&g_maxenc[0 + h], fenc(m1[h]));
            atomicMax(&g_maxenc[4 + h], fenc(m2[h]));
        }
    }
}

// ---------------- fp32 SGEMM (small evidence-2 GEMM only) ----------------
#define BM 128
#define BN 128
#define BKK 16
template <int EPI>
__global__ __launch_bounds__(256, 2)
void k_sgemm(const float* __restrict__ A, int lda,
             const float* __restrict__ B, int ldb,
             float* __restrict__ C, int ldc,
             const float* __restrict__ bias,
             int M, int N, int K)
{
    __shared__ float As[BKK][BM + 4];
    __shared__ float Bs[BKK][BN];
    const int tid = threadIdx.x;
    const int m0 = blockIdx.y * BM;
    const int n0 = blockIdx.x * BN;
    const int tm = tid >> 4, tn = tid & 15;
    const int a_kk = tid & 15, a_m0 = tid >> 4;
    const int b_kk0 = tid >> 5, b_nb = (tid & 31) << 2;

    float acc[8][8];
#pragma unroll
    for (int i = 0; i < 8; i++)
#pragma unroll
        for (int j = 0; j < 8; j++) acc[i][j] = 0.f;

    float ra[8]; float4 rb[2];
    auto load_tiles = [&](int k0) {
#pragma unroll
        for (int i = 0; i < 8; i++) {
            int gm = m0 + a_m0 + 16 * i;
            ra[i] = (gm < M) ? A[(size_t)gm * lda + (k0 + a_kk)] : 0.f;
        }
#pragma unroll
        for (int i = 0; i < 2; i++) {
            int kk = b_kk0 + 8 * i;
            int gn = n0 + b_nb;
            float4 v = make_float4(0.f, 0.f, 0.f, 0.f);
            const float* bp = &B[(size_t)(k0 + kk) * ldb + b_nb];
            if (gn + 3 < N) v = *(const float4*)bp;
            else {
                if (gn     < N) v.x = bp[0];
                if (gn + 1 < N) v.y = bp[1];
                if (gn + 2 < N) v.z = bp[2];
            }
            rb[i] = v;
        }
    };
    auto store_tiles = [&]() {
#pragma unroll
        for (int i = 0; i < 8; i++) As[a_kk][a_m0 + 16 * i] = ra[i];
#pragma unroll
        for (int i = 0; i < 2; i++) *(float4*)&Bs[b_kk0 + 8 * i][b_nb] = rb[i];
    };
    auto compute = [&]() {
#pragma unroll
        for (int kk = 0; kk < BKK; kk++) {
            float a[8], b[8];
#pragma unroll
            for (int i = 0; i < 8; i++) a[i] = As[kk][tm * 8 + i];
#pragma unroll
            for (int j = 0; j < 8; j++) b[j] = Bs[kk][tn * 8 + j];
#pragma unroll
            for (int i = 0; i < 8; i++)
#pragma unroll
                for (int j = 0; j < 8; j++) acc[i][j] = fmaf(a[i], b[j], acc[i][j]);
        }
    };
    load_tiles(0); store_tiles(); __syncthreads();
    for (int k0 = BKK; k0 < K; k0 += BKK) {
        load_tiles(k0); compute(); __syncthreads(); store_tiles(); __syncthreads();
    }
    compute();
#pragma unroll
    for (int i = 0; i < 8; i++) {
        int gm = m0 + tm * 8 + i;
        if (gm < M) {
#pragma unroll
            for (int j = 0; j < 8; j++) {
                int gn = n0 + tn * 8 + j;
                if (gn < N) {
                    float v = acc[i][j];
                    if (bias) v += bias[gn];
                    if (EPI == 1) v = fmaxf(v, 0.f);
                    C[(size_t)gm * ldc + gn] = v;
                }
            }
        }
    }
}

// ---------------- attention projections + node maxima (layer 2 only) ----------------
__global__ void k_s1s2(const float* __restrict__ Wh, int ld, int F, int nh,
                       const float* __restrict__ a, int aStride,
                       float* __restrict__ s1, float* __restrict__ s2, int N,
                       int slot1, int slot2)
{
    int gw = (blockIdx.x * blockDim.x + threadIdx.x) >> 5;
    int lane = threadIdx.x & 31;
    if (gw >= N * nh) return;
    int node = gw / nh;
    int h = gw - node * nh;
    const float* wr = &Wh[(size_t)node * ld + h * F];
    const float* ah = &a[(size_t)h * aStride];
    float p1 = 0.f, p2 = 0.f;
    for (int j = lane; j < F; j += 32) {
        float x = wr[j];
        p1 = fmaf(x, ah[j], p1);
        p2 = fmaf(x, ah[F + j], p2);
    }
    p1 = wsumf(p1); p2 = wsumf(p2);
    if (lane == 0) {
        s1[(size_t)node * nh + h] = p1;
        s2[(size_t)node * nh + h] = p2;
        atomicMax(&g_maxenc[slot1 + h], fenc(p1));
        atomicMax(&g_maxenc[slot2 + h], fenc(p2));
    }
}

// ---------------- edge pass ----------------
template <int NH>
__global__ void k_expsum(const int* __restrict__ src, const int* __restrict__ tgt,
                         const float* __restrict__ s1, const float* __restrict__ s2,
                         float* __restrict__ w, int E, int sumslot, int m1, int m2)
{
    int e = blockIdx.x * blockDim.x + threadIdx.x;
    int tid = threadIdx.x;
    bool ok = (e < E);
    float Mh[NH];
#pragma unroll
    for (int h = 0; h < NH; h++) {
        float l = fdec(g_maxenc[m1 + h]) + fdec(g_maxenc[m2 + h]);
        Mh[h] = (l > 0.f) ? l : 0.2f * l;
    }
    float sv[NH];
    if (NH == 4) {
        float4 a = make_float4(0.f, 0.f, 0.f, 0.f), b = a;
        if (ok) {
            int s = src[e], t = tgt[e];
            a = *(const float4*)&s1[(size_t)s * 4];
            b = *(const float4*)&s2[(size_t)t * 4];
        }
        float lv[4] = { a.x + b.x, a.y + b.y, a.z + b.z, a.w + b.w };
#pragma unroll
        for (int h = 0; h < 4; h++) {
            float l = lv[h];
            l = (l > 0.f) ? l : 0.2f * l;
            float v = ok ? expf(l - Mh[h]) : 0.f;
            if (ok) w[(size_t)h * E + e] = v;
            sv[h] = v;
        }
    } else {
        float v = 0.f;
        if (ok) {
            int s = src[e], t = tgt[e];
            float l = s1[s] + s2[t];
            l = (l > 0.f) ? l : 0.2f * l;
            v = expf(l - Mh[0]);
            w[e] = v;
        }
        sv[0] = v;
    }
    __shared__ float red[NH * 8];
    int wi = tid >> 5, lane = tid & 31;
#pragma unroll
    for (int h = 0; h < NH; h++) {
        float v = wsumf(sv[h]);
        if (lane == 0) red[h * 8 + wi] = v;
    }
    __syncthreads();
    if (tid < 32) {
        float v = (tid < NH * 8) ? red[tid] : 0.f;
        v += __shfl_down_sync(0xffffffffu, v, 4);
        v += __shfl_down_sync(0xffffffffu, v, 2);
        v += __shfl_down_sync(0xffffffffu, v, 1);
        if ((tid & 7) == 0 && tid < NH * 8)
            atomicAdd(&g_sumexp[sumslot + (tid >> 3)], (double)v);
    }
}

__global__ void k_finalize(int slot0, int n)
{
    int i = threadIdx.x;
    if (i < n) g_invS[slot0 + i] = (float)(1.0 / g_sumexp[slot0 + i]);
}

// ---------------- CSR gather (layer 1): emit bf16-split xnew ----------------
__global__ __launch_bounds__(256, 8)
void k_gather1024(const int* __restrict__ src, const float* __restrict__ w,
                  const float* __restrict__ Wh,
                  __nv_bfloat16* __restrict__ xhi, __nv_bfloat16* __restrict__ xlo, int slot0)
{
    int node = blockIdx.x;
    int tid = threadIdx.x;
    int head = tid >> 6;
    int col = tid * 4;
    const float* wh = &w[(size_t)head * EE];

    int p = g_rowptr[node];
    const int end = g_rowptr[node + 1];

    int s_cur = 0; float c_cur = 0.f;
    if (p < end) { int e = g_eidx[p]; s_cur = src[e]; c_cur = wh[e]; }

    float4 acc = make_float4(0.f, 0.f, 0.f, 0.f);
    while (p < end) {
        int s_nxt = 0; float c_nxt = 0.f;
        if (p + 1 < end) { int e = g_eidx[p + 1]; s_nxt = src[e]; c_nxt = wh[e]; }
        float4 v = *(const float4*)&Wh[(size_t)s_cur * 1024 + col];
        acc.x = fmaf(c_cur, v.x, acc.x);
        acc.y = fmaf(c_cur, v.y, acc.y);
        acc.z = fmaf(c_cur, v.z, acc.z);
        acc.w = fmaf(c_cur, v.w, acc.w);
        s_cur = s_nxt; c_cur = c_nxt; p++;
    }
    float inv = g_invS[slot0 + head];
    acc.x *= inv; acc.y *= inv; acc.z *= inv; acc.w *= inv;
    __nv_bfloat16 hx, lx, hy, ly, hz, lz, hw, lw;
    bf16split(acc.x, hx, lx); bf16split(acc.y, hy, ly);
    bf16split(acc.z, hz, lz); bf16split(acc.w, hw, lw);
    size_t o = (size_t)node * 1024 + col;
    *(__nv_bfloat162*)&xhi[o]     = __nv_bfloat162(hx, hy);
    *(__nv_bfloat162*)&xhi[o + 2] = __nv_bfloat162(hz, hw);
    *(__nv_bfloat162*)&xlo[o]     = __nv_bfloat162(lx, ly);
    *(__nv_bfloat162*)&xlo[o + 2] = __nv_bfloat162(lz, lw);
}

__global__ __launch_bounds__(256, 8)
void k_gather128(const int* __restrict__ src, const float* __restrict__ w,
                 const float* __restrict__ Wh, float* __restrict__ xnew, int slot)
{
    int node = (blockIdx.x * blockDim.x + threadIdx.x) >> 5;
    int lane = threadIdx.x & 31;
    if (node >= NN) return;
    int col = lane * 4;

    int p = g_rowptr[node];
    const int end = g_rowptr[node + 1];

    int s_cur = 0; float c_cur = 0.f;
    if (p < end) { int e = g_eidx[p]; s_cur = src[e]; c_cur = w[e]; }

    float4 acc = make_float4(0.f, 0.f, 0.f, 0.f);
    while (p < end) {
        int s_nxt = 0; float c_nxt = 0.f;
        if (p + 1 < end) { int e = g_eidx[p + 1]; s_nxt = src[e]; c_nxt = w[e]; }
        float4 v = *(const float4*)&Wh[(size_t)s_cur * 128 + col];
        acc.x = fmaf(c_cur, v.x, acc.x);
        acc.y = fmaf(c_cur, v.y, acc.y);
        acc.z = fmaf(c_cur, v.z, acc.z);
        acc.w = fmaf(c_cur, v.w, acc.w);
        s_cur = s_nxt; c_cur = c_nxt; p++;
    }
    float inv = g_invS[slot];
    acc.x *= inv; acc.y *= inv; acc.z *= inv; acc.w *= inv;
    *(float4*)&xnew[(size_t)node * 128 + col] = acc;
}

// ---------------- evidence heads ----------------
__global__ void k_evid1(const float* __restrict__ hbuf, const float* __restrict__ w2,
                        const float* __restrict__ b2, float* __restrict__ evsum, int N)
{
    int gw = (blockIdx.x * blockDim.x + threadIdx.x) >> 5;
    int lane = threadIdx.x & 31;
    if (gw >= N) return;
    float e0 = 0.f, e1 = 0.f, e2 = 0.f;
#pragma unroll
    for (int h = 0; h < NHEAD; h++) {
        float4 v = *(const float4*)&hbuf[(size_t)gw * 512 + h * 128 + lane * 4];
        const float* wc = &w2[h * 384 + lane * 12];
        float a0 = v.x * wc[0] + v.y * wc[3] + v.z * wc[6] + v.w * wc[9];
        float a1 = v.x * wc[1] + v.y * wc[4] + v.z * wc[7] + v.w * wc[10];
        float a2 = v.x * wc[2] + v.y * wc[5] + v.z * wc[8] + v.w * wc[11];
        a0 = wsumf(a0); a1 = wsumf(a1); a2 = wsumf(a2);
        e0 += softplusf(a0 + b2[h * 3 + 0]) + 1.f;
        e1 += softplusf(a1 + b2[h * 3 + 1]) + 1.f;
        e2 += softplusf(a2 + b2[h * 3 + 2]) + 1.f;
    }
    if (lane == 0) {
        evsum[gw * 3 + 0] = e0; evsum[gw * 3 + 1] = e1; evsum[gw * 3 + 2] = e2;
    }
}

__global__ void k_evid2(const float* __restrict__ hbuf, const float* __restrict__ w2,
                        const float* __restrict__ b2, const float* __restrict__ evsum,
                        float* __restrict__ out, int N)
{
    int gw = (blockIdx.x * blockDim.x + threadIdx.x) >> 5;
    int lane = threadIdx.x & 31;
    if (gw >= N) return;
    float2 v = *(const float2*)&hbuf[(size_t)gw * 64 + lane * 2];
    const float* wc = &w2[lane * 6];
    float a0 = v.x * wc[0] + v.y * wc[3];
    float a1 = v.x * wc[1] + v.y * wc[4];
    float a2 = v.x * wc[2] + v.y * wc[5];
    a0 = wsumf(a0); a1 = wsumf(a1); a2 = wsumf(a2);
    if (lane == 0) {
        float e0 = softplusf(a0 + b2[0]) + 1.f;
        float e1 = softplusf(a1 + b2[1]) + 1.f;
        float e2 = softplusf(a2 + b2[2]) + 1.f;
        out[(size_t)gw * 3 + 0] = (evsum[gw * 3 + 0] * 0.25f + e0) * 0.5f;
        out[(size_t)gw * 3 + 1] = (evsum[gw * 3 + 1] * 0.25f + e1) * 0.5f;
        out[(size_t)gw * 3 + 2] = (evsum[gw * 3 + 2] * 0.25f + e2) * 0.5f;
    }
}

// ---------------- LayerNorm + ELU ----------------
template <int F, bool SPLIT>
__global__ void k_ln_elu(const float* __restrict__ in, float* __restrict__ out,
                         __nv_bfloat16* __restrict__ ohi, __nv_bfloat16* __restrict__ olo,
                         const float* __restrict__ gam, const float* __restrict__ bet, int N)
{
    int gw = (blockIdx.x * blockDim.x + threadIdx.x) >> 5;
    int lane = threadIdx.x & 31;
    if (gw >= N) return;
    constexpr int R = F / 32;
    float v[R];
    const float* ir = &in[(size_t)gw * F];
#pragma unroll
    for (int r = 0; r < R; r++) v[r] = ir[lane + 32 * r];
    float s = 0.f;
#pragma unroll
    for (int r = 0; r < R; r++) s += v[r];
    s = wsumf(s);
    float mean = s * (1.f / F);
    float q = 0.f;
#pragma unroll
    for (int r = 0; r < R; r++) { float d = v[r] - mean; q = fmaf(d, d, q); }
    q = wsumf(q);
    float rstd = rsqrtf(q * (1.f / F) + 1e-5f);
#pragma unroll
    for (int r = 0; r < R; r++) {
        int j = lane + 32 * r;
        float y = (v[r] - mean) * rstd * gam[j] + bet[j];
        y = eluf(y);
        if (SPLIT) {
            __nv_bfloat16 hi, lo;
            bf16split(y, hi, lo);
            ohi[(size_t)gw * F + j] = hi;
            olo[(size_t)gw * F + j] = lo;
        } else {
            out[(size_t)gw * F + j] = y;
        }
    }
}

// ---------------- launch ----------------
extern "C" void kernel_launch(void* const* d_in, const int* in_sizes, int n_in,
                              void* d_out, int out_size)
{
    (void)in_sizes; (void)n_in; (void)out_size;

    const float* x        = (const float*)d_in[0];
    const int*   ei       = (const int*)  d_in[1];
    const float* W_heads  = (const float*)d_in[2];
    const float* a_heads  = (const float*)d_in[3];
    const float* ev1w_h   = (const float*)d_in[4];
    const float* ev1b_h   = (const float*)d_in[5];
    const float* ev2w_h   = (const float*)d_in[6];
    const float* ev2b_h   = (const float*)d_in[7];
    const float* agg_w    = (const float*)d_in[8];
    const float* agg_b    = (const float*)d_in[9];
    const float* ln1_g    = (const float*)d_in[10];
    const float* ln1_b    = (const float*)d_in[11];
    const float* W2       = (const float*)d_in[12];
    const float* a2       = (const float*)d_in[13];
    const float* ev1w2    = (const float*)d_in[14];
    const float* ev1b2    = (const float*)d_in[15];
    const float* ev2w2    = (const float*)d_in[16];
    const float* ev2b2    = (const float*)d_in[17];
    const float* ln2_g    = (const float*)d_in[18];
    const float* ln2_b    = (const float*)d_in[19];
    const float* res_w    = (const float*)d_in[20];
    const float* res_b    = (const float*)d_in[21];

    const int* src = ei;
    const int* tgt = ei + EE;

    float* out_x  = (float*)d_out;
    float* out_ev = (float*)d_out + (size_t)NN * DOUT;

    float *Wh, *s1, *s2, *wbuf, *w2e, *hbuf, *evsum, *h1, *Wh2, *s1b, *s2b, *xnew2, *x2;
    __nv_bfloat16 *xhi, *xlo, *xnhi, *xnlo, *h1hi, *h1lo;
    __nv_bfloat16 *bt1hi, *bt1lo, *btahi, *btalo, *btehi, *btelo, *btw2hi, *btw2lo, *btrhi, *btrlo;
    cudaGetSymbolAddress((void**)&Wh,    g_Wh);
    cudaGetSymbolAddress((void**)&s1,    g_s1);
    cudaGetSymbolAddress((void**)&s2,    g_s2);
    cudaGetSymbolAddress((void**)&wbuf,  g_w);
    cudaGetSymbolAddress((void**)&w2e,   g_w2e);
    cudaGetSymbolAddress((void**)&hbuf,  g_hbuf);
    cudaGetSymbolAddress((void**)&evsum, g_evsum);
    cudaGetSymbolAddress((void**)&h1,    g_h1);
    cudaGetSymbolAddress((void**)&Wh2,   g_Wh2);
    cudaGetSymbolAddress((void**)&s1b,   g_s1b);
    cudaGetSymbolAddress((void**)&s2b,   g_s2b);
    cudaGetSymbolAddress((void**)&xnew2, g_xnew2);
    cudaGetSymbolAddress((void**)&x2,    g_x2);
    cudaGetSymbolAddress((void**)&xhi,   g_xhi);
    cudaGetSymbolAddress((void**)&xlo,   g_xlo);
    cudaGetSymbolAddress((void**)&xnhi,  g_xnhi);
    cudaGetSymbolAddress((void**)&xnlo,  g_xnlo);
    cudaGetSymbolAddress((void**)&h1hi,  g_h1hi);
    cudaGetSymbolAddress((void**)&h1lo,  g_h1lo);
    cudaGetSymbolAddress((void**)&bt1hi, g_bt1hi);
    cudaGetSymbolAddress((void**)&bt1lo, g_bt1lo);
    cudaGetSymbolAddress((void**)&btahi, g_btahi);
    cudaGetSymbolAddress((void**)&btalo, g_btalo);
    cudaGetSymbolAddress((void**)&btehi, g_btehi);
    cudaGetSymbolAddress((void**)&btelo, g_btelo);
    cudaGetSymbolAddress((void**)&btw2hi, g_btw2hi);
    cudaGetSymbolAddress((void**)&btw2lo, g_btw2lo);
    cudaGetSymbolAddress((void**)&btrhi, g_btrhi);
    cudaGetSymbolAddress((void**)&btrlo, g_btrlo);

    cudaFuncSetAttribute(k_mma<0>, cudaFuncAttributeMaxDynamicSharedMemorySize, MMA_SMEM);
    cudaFuncSetAttribute(k_mma<1>, cudaFuncAttributeMaxDynamicSharedMemorySize, MMA_SMEM);
    cudaFuncSetAttribute(k_mma<2>, cudaFuncAttributeMaxDynamicSharedMemorySize, MMA_SMEM);
    cudaFuncSetAttribute(k_mma<3>, cudaFuncAttributeMaxDynamicSharedMemorySize, MMA_SMEM);

    const int MB = (NN + 127) / 128;   // 235

    // launches 1-3, then #4 = big G1 k_mma (ncu captures launch #4)
    k_btall<<<BT_BLOCKS + INIT_BLOCKS, 256>>>(W_heads, agg_w, ev1w_h, W2, res_w);
    k_hist<<<(EE + 255) / 256, 256>>>(tgt);
    k_split<<<(NN * DIN / 4 + 255) / 256, 256>>>(x, xhi, xlo, NN * DIN / 4);

    // #4: Wh = x @ W_heads, with fused s1/s2 attention projections
    k_mma<3><<<dim3(8, MB), 256, MMA_SMEM>>>(xhi, xlo, DIN, 0, 128, bt1hi, bt1lo,
                                             Wh, 1024, nullptr, nullptr, 0, NN, DIN,
                                             s1, s2, a_heads);

    // CSR scan/fill, node maxima, edge pass, softmax scale
    k_scan<<<1, 1024>>>();
    k_fill<<<(EE + 255) / 256, 256>>>(tgt);
    k_nodemax<<<(NN + 255) / 256, 256>>>(s1, s2);
    k_expsum<NHEAD><<<(EE + 255) / 256, 256>>>(src, tgt, s1, s2, wbuf, EE, 0, 0, 4);
    k_finalize<<<1, 8>>>(0, NHEAD);

    // CSR gather -> split xnew
    k_gather1024<<<NN, 256>>>(src, wbuf, Wh, xnhi, xnlo, 0);

    // evidence layer 1 (block-diagonal, relu) + fused head
    k_mma<1><<<dim3(4, MB), 256, MMA_SMEM>>>(xnhi, xnlo, 1024, DH, 128, btehi, btelo,
                                             hbuf, 512, ev1b_h, nullptr, 0, NN, DH,
                                             nullptr, nullptr, nullptr);
    k_evid1<<<NN / 8, 256>>>(hbuf, ev2w_h, ev2b_h, evsum, NN);

    // h1 = elu(LN(x_cat @ agg_w + agg_b)) -> split h1
    k_mma<0><<<dim3(2, MB), 256, MMA_SMEM>>>(xnhi, xnlo, 1024, 0, 128, btahi, btalo,
                                             h1, DH, agg_b, nullptr, 0, NN, 1024,
                                             nullptr, nullptr, nullptr);
    k_ln_elu<DH, true><<<NN / 8, 256>>>(h1, nullptr, h1hi, h1lo, ln1_g, ln1_b, NN);

    // layer-2 GAT
    k_mma<0><<<dim3(1, MB), 256, MMA_SMEM>>>(h1hi, h1lo, DH, 0, 128, btw2hi, btw2lo,
                                             Wh2, DOUT, nullptr, nullptr, 0, NN, DH,
                                             nullptr, nullptr, nullptr);
    k_s1s2<<<NN / 8, 256>>>(Wh2, DOUT, DOUT, 1, a2, 2 * DOUT, s1b, s2b, NN, 8, 9);
    k_expsum<1><<<(EE + 255) / 256, 256>>>(src, tgt, s1b, s2b, w2e, EE, 4, 8, 9);
    k_finalize<<<1, 8>>>(4, 1);
    k_gather128<<<(NN * 32 + 255) / 256, 256>>>(src, w2e, Wh2, xnew2, 4);

    // evidence layer 2 + final combine
    k_sgemm<1><<<dim3(1, MB), 256>>>(xnew2, DOUT, ev1w2, DOUT / 2, hbuf, DOUT / 2,
                                     ev1b2, NN, DOUT / 2, DOUT);
    k_evid2<<<NN / 8, 256>>>(hbuf, ev2w2, ev2b2, evsum, out_ev, NN);

    // x2 = elu(LN(x_new2)); x_out = x2 + h1 @ res_w + res_b
    k_ln_elu<DOUT, false><<<NN / 8, 256>>>(xnew2, x2, nullptr, nullptr, ln2_g, ln2_b, NN);
    k_mma<2><<<dim3(1, MB), 256, MMA_SMEM>>>(h1hi, h1lo, DH, 0, 128, btrhi, btrlo,
                                             out_x, DOUT, res_b, x2, DOUT, NN, DH,
                                             nullptr, nullptr, nullptr);
}